// round 1
// baseline (speedup 1.0000x reference)
#include <cuda_runtime.h>
#include <math.h>

#define NN 50000
#define EE 850000
#define FD 256      // HEADS*HID
#define HEADS 4
#define CH 64
#define OUTD 40
#define BN_EPS 1e-5f
#define NEG_SLOPE 0.2f

// ---------------- scratch (static, allocation-free) ----------------
__device__ float g_h[NN * FD];     // GEMM output of current layer
__device__ float g_x1[NN * FD];    // activations between layers
__device__ float g_agg[NN * FD];   // aggregation output
__device__ float g_as[NN * HEADS];
__device__ float g_ad[NN * HEADS];
__device__ float g_e[EE * HEADS];  // per-edge scores -> probs
__device__ float g_m[NN * HEADS];
__device__ float g_den[NN * HEADS];

// ---------------- helpers ----------------
__device__ __forceinline__ void atomicMaxF(float* addr, float val) {
    if (val >= 0.0f)
        atomicMax((int*)addr, __float_as_int(val));
    else
        atomicMin((unsigned int*)addr, __float_as_uint(val));
}

// ---------------- GEMM: C[M,N] = A[M,K] @ B[K,N], fp32, 64x64 tile ----------------
__global__ void gemm64(const float* __restrict__ A, const float* __restrict__ B,
                       float* __restrict__ C, int M, int N, int K) {
    __shared__ float As[16][64];
    __shared__ float Bs[16][64];
    int tx = threadIdx.x & 15;
    int ty = threadIdx.x >> 4;
    int row0 = blockIdx.y * 64;
    int col0 = blockIdx.x * 64;
    float acc[4][4] = {};

    for (int kk = 0; kk < K; kk += 16) {
        #pragma unroll
        for (int i = 0; i < 4; i++) {
            int idx = threadIdx.x + i * 256;
            int r = idx >> 4, c = idx & 15;        // r: row in tile, c: k
            float v = 0.0f;
            if (row0 + r < M) v = A[(size_t)(row0 + r) * K + kk + c];
            As[c][r] = v;
        }
        #pragma unroll
        for (int i = 0; i < 4; i++) {
            int idx = threadIdx.x + i * 256;
            int r = idx >> 6, c = idx & 63;        // r: k, c: col in tile
            float v = 0.0f;
            if (col0 + c < N) v = B[(size_t)(kk + r) * N + col0 + c];
            Bs[r][c] = v;
        }
        __syncthreads();
        #pragma unroll
        for (int k = 0; k < 16; k++) {
            float a[4], b[4];
            #pragma unroll
            for (int i = 0; i < 4; i++) a[i] = As[k][ty * 4 + i];
            #pragma unroll
            for (int j = 0; j < 4; j++) b[j] = Bs[k][tx * 4 + j];
            #pragma unroll
            for (int i = 0; i < 4; i++)
                #pragma unroll
                for (int j = 0; j < 4; j++)
                    acc[i][j] += a[i] * b[j];
        }
        __syncthreads();
    }
    #pragma unroll
    for (int i = 0; i < 4; i++) {
        int r = row0 + ty * 4 + i;
        if (r >= M) continue;
        #pragma unroll
        for (int j = 0; j < 4; j++) {
            int c = col0 + tx * 4 + j;
            if (c < N) C[(size_t)r * N + c] = acc[i][j];
        }
    }
}

// ---------------- per-node attention dot products ----------------
// one warp per (node, head)
__global__ void attn_scores(const float* __restrict__ h, const float* __restrict__ asrc,
                            const float* __restrict__ adst, float* __restrict__ outs,
                            float* __restrict__ outd, int n, int heads, int ch) {
    int w = (blockIdx.x * blockDim.x + threadIdx.x) >> 5;
    int lane = threadIdx.x & 31;
    if (w >= n * heads) return;
    int node = w / heads;
    int hh = w - node * heads;
    int fd = heads * ch;
    float s = 0.0f, d = 0.0f;
    for (int c = lane; c < ch; c += 32) {
        float v = h[(size_t)node * fd + hh * ch + c];
        s += v * asrc[hh * ch + c];
        d += v * adst[hh * ch + c];
    }
    #pragma unroll
    for (int o = 16; o > 0; o >>= 1) {
        s += __shfl_xor_sync(0xFFFFFFFFu, s, o);
        d += __shfl_xor_sync(0xFFFFFFFFu, d, o);
    }
    if (lane == 0) { outs[w] = s; outd[w] = d; }
}

// ---------------- init: m=-3e38, den=0, agg=0 ----------------
__global__ void init_buffers(float* __restrict__ m, float* __restrict__ den, int nmh,
                             float* __restrict__ agg, int nagg) {
    for (int i = blockIdx.x * blockDim.x + threadIdx.x; i < nagg;
         i += gridDim.x * blockDim.x) {
        if (i < nmh) { m[i] = -3e38f; den[i] = 0.0f; }
        agg[i] = 0.0f;
    }
}

// ---------------- edge pass 1: e = lrelu(as[src]+ad[dst]); segment max ----------------
__global__ void edge_scores(const int* __restrict__ src, const int* __restrict__ dst,
                            const float* __restrict__ as_, const float* __restrict__ ad_,
                            float* __restrict__ e, float* __restrict__ m,
                            int E, int heads) {
    int total = E * heads;
    for (int i = blockIdx.x * blockDim.x + threadIdx.x; i < total;
         i += gridDim.x * blockDim.x) {
        int ed = i / heads;
        int hh = i - ed * heads;
        int s = src[ed], d = dst[ed];
        float v = as_[s * heads + hh] + ad_[d * heads + hh];
        v = (v > 0.0f) ? v : NEG_SLOPE * v;
        e[i] = v;
        atomicMaxF(&m[d * heads + hh], v);
    }
}

// ---------------- edge pass 2: p = exp(e - m[dst]); segment sum ----------------
__global__ void edge_exp(const int* __restrict__ dst, float* __restrict__ e,
                         const float* __restrict__ m, float* __restrict__ den,
                         int E, int heads) {
    int total = E * heads;
    for (int i = blockIdx.x * blockDim.x + threadIdx.x; i < total;
         i += gridDim.x * blockDim.x) {
        int ed = i / heads;
        int hh = i - ed * heads;
        int d = dst[ed];
        float p = __expf(e[i] - m[d * heads + hh]);
        e[i] = p;
        atomicAdd(&den[d * heads + hh], p);
    }
}

// ---------------- edge pass 3: scatter msg = h[src] * alpha into agg[dst] ----------------
// one warp per edge
__global__ void edge_scatter(const int* __restrict__ src, const int* __restrict__ dst,
                             const float* __restrict__ h, const float* __restrict__ p,
                             const float* __restrict__ den, float* __restrict__ agg,
                             int E, int heads, int ch) {
    int w = (blockIdx.x * blockDim.x + threadIdx.x) >> 5;
    int lane = threadIdx.x & 31;
    if (w >= E) return;
    int s = src[w], d = dst[w];
    int fd = heads * ch;
    for (int f = lane; f < fd; f += 32) {
        int hh = f / ch;
        float alpha = p[w * heads + hh] / (den[d * heads + hh] + 1e-16f);
        atomicAdd(&agg[(size_t)d * fd + f], h[(size_t)s * fd + f] * alpha);
    }
}

// ---------------- post: x = elu(bn(agg + bias)) ----------------
__global__ void post_bn_elu(const float* __restrict__ agg, const float* __restrict__ bias,
                            const float* __restrict__ g, const float* __restrict__ b,
                            const float* __restrict__ mean, const float* __restrict__ var,
                            float* __restrict__ out, int n, int fd) {
    for (int i = blockIdx.x * blockDim.x + threadIdx.x; i < n * fd;
         i += gridDim.x * blockDim.x) {
        int f = i % fd;
        float v = agg[i] + bias[f];
        v = g[f] * (v - mean[f]) * rsqrtf(var[f] + BN_EPS) + b[f];
        out[i] = (v > 0.0f) ? v : (expf(v) - 1.0f);
    }
}

// ---------------- final: out = agg + bias ----------------
__global__ void final_bias(const float* __restrict__ agg, const float* __restrict__ bias,
                           float* __restrict__ out, int n, int fd) {
    for (int i = blockIdx.x * blockDim.x + threadIdx.x; i < n * fd;
         i += gridDim.x * blockDim.x) {
        out[i] = agg[i] + bias[i % fd];
    }
}

// ---------------- launch ----------------
static inline int cdiv(int a, int b) { return (a + b - 1) / b; }

static void run_gat_layer(const float* x_in, const float* W, const float* asrc,
                          const float* adst, const int* src, const int* dst,
                          int E, int heads, int ch,
                          float* h_buf, float* agg_buf,
                          float* as_buf, float* ad_buf, float* e_buf,
                          float* m_buf, float* den_buf,
                          int Kdim) {
    int fd = heads * ch;
    dim3 ggrid(cdiv(fd, 64), cdiv(NN, 64));
    gemm64<<<ggrid, 256>>>(x_in, W, h_buf, NN, fd, Kdim);

    int pairs = NN * heads;
    attn_scores<<<cdiv(pairs * 32, 256), 256>>>(h_buf, asrc, adst, as_buf, ad_buf,
                                                NN, heads, ch);
    init_buffers<<<cdiv(NN * fd, 256), 256>>>(m_buf, den_buf, NN * heads,
                                              agg_buf, NN * fd);
    int tot = E * heads;
    edge_scores<<<cdiv(tot, 256), 256>>>(src, dst, as_buf, ad_buf, e_buf, m_buf, E, heads);
    edge_exp<<<cdiv(tot, 256), 256>>>(dst, e_buf, m_buf, den_buf, E, heads);
    edge_scatter<<<cdiv(E * 32, 256), 256>>>(src, dst, h_buf, e_buf, den_buf, agg_buf,
                                             E, heads, ch);
}

extern "C" void kernel_launch(void* const* d_in, const int* in_sizes, int n_in,
                              void* d_out, int out_size) {
    const float* x       = (const float*)d_in[0];
    const int*   eidx    = (const int*)d_in[1];
    const float* W0      = (const float*)d_in[2];
    const float* a_src0  = (const float*)d_in[3];
    const float* a_dst0  = (const float*)d_in[4];
    const float* b0      = (const float*)d_in[5];
    const float* bn0_g   = (const float*)d_in[6];
    const float* bn0_b   = (const float*)d_in[7];
    const float* bn0_m   = (const float*)d_in[8];
    const float* bn0_v   = (const float*)d_in[9];
    const float* W1      = (const float*)d_in[10];
    const float* a_src1  = (const float*)d_in[11];
    const float* a_dst1  = (const float*)d_in[12];
    const float* b1      = (const float*)d_in[13];
    const float* bn1_g   = (const float*)d_in[14];
    const float* bn1_b   = (const float*)d_in[15];
    const float* bn1_m   = (const float*)d_in[16];
    const float* bn1_v   = (const float*)d_in[17];
    const float* W2      = (const float*)d_in[18];
    const float* a_src2  = (const float*)d_in[19];
    const float* a_dst2  = (const float*)d_in[20];
    const float* b2      = (const float*)d_in[21];
    float* out = (float*)d_out;

    int E = in_sizes[1] / 2;
    const int* src = eidx;
    const int* dst = eidx + E;

    float *h_buf, *x1_buf, *agg_buf, *as_buf, *ad_buf, *e_buf, *m_buf, *den_buf;
    cudaGetSymbolAddress((void**)&h_buf, g_h);
    cudaGetSymbolAddress((void**)&x1_buf, g_x1);
    cudaGetSymbolAddress((void**)&agg_buf, g_agg);
    cudaGetSymbolAddress((void**)&as_buf, g_as);
    cudaGetSymbolAddress((void**)&ad_buf, g_ad);
    cudaGetSymbolAddress((void**)&e_buf, g_e);
    cudaGetSymbolAddress((void**)&m_buf, g_m);
    cudaGetSymbolAddress((void**)&den_buf, g_den);

    // ---- layer 0 ----
    run_gat_layer(x, W0, a_src0, a_dst0, src, dst, E, HEADS, CH,
                  h_buf, agg_buf, as_buf, ad_buf, e_buf, m_buf, den_buf, 256);
    post_bn_elu<<<cdiv(NN * FD, 256), 256>>>(agg_buf, b0, bn0_g, bn0_b, bn0_m, bn0_v,
                                             x1_buf, NN, FD);

    // ---- layer 1 ----
    run_gat_layer(x1_buf, W1, a_src1, a_dst1, src, dst, E, HEADS, CH,
                  h_buf, agg_buf, as_buf, ad_buf, e_buf, m_buf, den_buf, FD);
    post_bn_elu<<<cdiv(NN * FD, 256), 256>>>(agg_buf, b1, bn1_g, bn1_b, bn1_m, bn1_v,
                                             x1_buf, NN, FD);

    // ---- layer 2 (heads=1, ch=40) ----
    run_gat_layer(x1_buf, W2, a_src2, a_dst2, src, dst, E, 1, OUTD,
                  h_buf, agg_buf, as_buf, ad_buf, e_buf, m_buf, den_buf, FD);
    final_bias<<<cdiv(NN * OUTD, 256), 256>>>(agg_buf, b2, out, NN, OUTD);
}

// round 2
// speedup vs baseline: 2.3649x; 2.3649x over previous
#include <cuda_runtime.h>
#include <math.h>

#define NN 50000
#define EE 850000
#define FD 256      // HEADS*HID
#define HEADS 4
#define CH 64
#define OUTD 40
#define BN_EPS 1e-5f
#define NEG_SLOPE 0.2f

// ---------------- scratch (static, allocation-free) ----------------
__device__ float g_h[NN * FD];     // GEMM output of current layer
__device__ float g_x1[NN * FD];    // activations between layers
__device__ float g_as[NN * HEADS];
__device__ float g_ad[NN * HEADS];
__device__ float g_e[EE * HEADS];  // per-edge scores -> probs
__device__ float g_m[NN * HEADS];
__device__ float g_den[NN * HEADS];
__device__ int   g_deg[NN];
__device__ int   g_cur[NN];
__device__ int   g_rowptr[NN + 1];
__device__ int   g_eids[EE];
__device__ int   g_srcs[EE];

// ---------------- helpers ----------------
__device__ __forceinline__ void atomicMaxF(float* addr, float val) {
    if (val >= 0.0f)
        atomicMax((int*)addr, __float_as_int(val));
    else
        atomicMin((unsigned int*)addr, __float_as_uint(val));
}

static inline int cdiv(int a, int b) { return (a + b - 1) / b; }

// ================= CSR build =================
__global__ void zero_counts(int* __restrict__ deg, int* __restrict__ cur, int n) {
    for (int i = blockIdx.x * blockDim.x + threadIdx.x; i < n;
         i += gridDim.x * blockDim.x) { deg[i] = 0; cur[i] = 0; }
}

__global__ void csr_count(const int* __restrict__ dst, int E, int* __restrict__ deg) {
    for (int i = blockIdx.x * blockDim.x + threadIdx.x; i < E;
         i += gridDim.x * blockDim.x)
        atomicAdd(&deg[dst[i]], 1);
}

// single-block exclusive scan over NN elements
__global__ void csr_scan(const int* __restrict__ deg, int* __restrict__ rowptr, int n, int E) {
    __shared__ int part[1024];
    int t = threadIdx.x;
    int chunk = (n + 1023) / 1024;
    int start = t * chunk;
    int stop = min(start + chunk, n);
    int sum = 0;
    for (int i = start; i < stop; i++) sum += deg[i];
    part[t] = sum;
    __syncthreads();
    // Hillis-Steele inclusive scan
    for (int o = 1; o < 1024; o <<= 1) {
        int v = (t >= o) ? part[t - o] : 0;
        __syncthreads();
        part[t] += v;
        __syncthreads();
    }
    int off = part[t] - sum;   // exclusive prefix for this thread's chunk
    int run = off;
    for (int i = start; i < stop; i++) { rowptr[i] = run; run += deg[i]; }
    if (t == 0) rowptr[n] = E;
}

__global__ void csr_fill(const int* __restrict__ src, const int* __restrict__ dst, int E,
                         const int* __restrict__ rowptr, int* __restrict__ cur,
                         int* __restrict__ eids, int* __restrict__ srcs) {
    for (int i = blockIdx.x * blockDim.x + threadIdx.x; i < E;
         i += gridDim.x * blockDim.x) {
        int d = dst[i];
        int pos = rowptr[d] + atomicAdd(&cur[d], 1);
        eids[pos] = i;
        srcs[pos] = src[i];
    }
}

// ================= GEMM: C[M,N] = A[M,K] @ B[K,N], 128x128 tile =================
__global__ __launch_bounds__(256, 2)
void gemm128(const float* __restrict__ A, const float* __restrict__ B,
             float* __restrict__ C, int M, int N, int K) {
    __shared__ float As[16][128];   // As[k][m]
    __shared__ float Bs[16][128];   // Bs[k][n]
    int tid = threadIdx.x;
    int tx = tid & 15;        // 0..15 -> col group
    int ty = tid >> 4;        // 0..15 -> row group
    int row0 = blockIdx.y * 128;
    int col0 = blockIdx.x * 128;
    float acc[8][8] = {};

    for (int kk = 0; kk < K; kk += 16) {
        // load A tile: 128 rows x 16 k  (512 float4, 2 per thread), transpose into As
        #pragma unroll
        for (int l = 0; l < 2; l++) {
            int i = tid + l * 256;
            int r = i >> 2;          // 0..127
            int c4 = i & 3;          // 0..3
            float4 v = make_float4(0.f, 0.f, 0.f, 0.f);
            if (row0 + r < M)
                v = *(const float4*)&A[(size_t)(row0 + r) * K + kk + c4 * 4];
            As[c4 * 4 + 0][r] = v.x;
            As[c4 * 4 + 1][r] = v.y;
            As[c4 * 4 + 2][r] = v.z;
            As[c4 * 4 + 3][r] = v.w;
        }
        // load B tile: 16 k x 128 cols
        #pragma unroll
        for (int l = 0; l < 2; l++) {
            int i = tid + l * 256;
            int r = i >> 5;          // 0..15
            int c4 = i & 31;         // 0..31
            float4 v = make_float4(0.f, 0.f, 0.f, 0.f);
            if (col0 + c4 * 4 < N)
                v = *(const float4*)&B[(size_t)(kk + r) * N + col0 + c4 * 4];
            *(float4*)&Bs[r][c4 * 4] = v;
        }
        __syncthreads();
        #pragma unroll
        for (int k = 0; k < 16; k++) {
            float a[8], b[8];
            *(float4*)&a[0] = *(const float4*)&As[k][ty * 8];
            *(float4*)&a[4] = *(const float4*)&As[k][ty * 8 + 4];
            *(float4*)&b[0] = *(const float4*)&Bs[k][tx * 8];
            *(float4*)&b[4] = *(const float4*)&Bs[k][tx * 8 + 4];
            #pragma unroll
            for (int i = 0; i < 8; i++)
                #pragma unroll
                for (int j = 0; j < 8; j++)
                    acc[i][j] += a[i] * b[j];
        }
        __syncthreads();
    }
    #pragma unroll
    for (int i = 0; i < 8; i++) {
        int r = row0 + ty * 8 + i;
        if (r >= M) continue;
        #pragma unroll
        for (int j4 = 0; j4 < 2; j4++) {
            int c = col0 + tx * 8 + j4 * 4;
            if (c < N)
                *(float4*)&C[(size_t)r * N + c] =
                    make_float4(acc[i][j4 * 4], acc[i][j4 * 4 + 1],
                                acc[i][j4 * 4 + 2], acc[i][j4 * 4 + 3]);
        }
    }
}

// ---------------- per-node attention dot products (warp per node-head) ----------------
__global__ void attn_scores(const float* __restrict__ h, const float* __restrict__ asrc,
                            const float* __restrict__ adst, float* __restrict__ outs,
                            float* __restrict__ outd, int n, int heads, int ch) {
    int w = (blockIdx.x * blockDim.x + threadIdx.x) >> 5;
    int lane = threadIdx.x & 31;
    if (w >= n * heads) return;
    int node = w / heads;
    int hh = w - node * heads;
    int fd = heads * ch;
    float s = 0.0f, d = 0.0f;
    for (int c = lane; c < ch; c += 32) {
        float v = h[(size_t)node * fd + hh * ch + c];
        s += v * asrc[hh * ch + c];
        d += v * adst[hh * ch + c];
    }
    #pragma unroll
    for (int o = 16; o > 0; o >>= 1) {
        s += __shfl_xor_sync(0xFFFFFFFFu, s, o);
        d += __shfl_xor_sync(0xFFFFFFFFu, d, o);
    }
    if (lane == 0) { outs[w] = s; outd[w] = d; }
}

// ---------------- init: m=-3e38, den=0 ----------------
__global__ void init_md(float* __restrict__ m, float* __restrict__ den, int nmh) {
    for (int i = blockIdx.x * blockDim.x + threadIdx.x; i < nmh;
         i += gridDim.x * blockDim.x) { m[i] = -3e38f; den[i] = 0.0f; }
}

// ---------------- edge pass 1: e = lrelu(as[src]+ad[dst]); segment max ----------------
__global__ void edge_scores(const int* __restrict__ src, const int* __restrict__ dst,
                            const float* __restrict__ as_, const float* __restrict__ ad_,
                            float* __restrict__ e, float* __restrict__ m,
                            int E, int heads) {
    int total = E * heads;
    for (int i = blockIdx.x * blockDim.x + threadIdx.x; i < total;
         i += gridDim.x * blockDim.x) {
        int ed = i / heads;
        int hh = i - ed * heads;
        int s = src[ed], d = dst[ed];
        float v = as_[s * heads + hh] + ad_[d * heads + hh];
        v = (v > 0.0f) ? v : NEG_SLOPE * v;
        e[i] = v;
        atomicMaxF(&m[d * heads + hh], v);
    }
}

// ---------------- edge pass 2: p = exp(e - m[dst]); segment sum ----------------
__global__ void edge_exp(const int* __restrict__ dst, float* __restrict__ e,
                         const float* __restrict__ m, float* __restrict__ den,
                         int E, int heads) {
    int total = E * heads;
    for (int i = blockIdx.x * blockDim.x + threadIdx.x; i < total;
         i += gridDim.x * blockDim.x) {
        int ed = i / heads;
        int hh = i - ed * heads;
        int d = dst[ed];
        float p = __expf(e[i] - m[d * heads + hh]);
        e[i] = p;
        atomicAdd(&den[d * heads + hh], p);
    }
}

// ---------------- CSR gather aggregation + fused epilogue ----------------
// MODE 0: out = elu(bn(acc + bias));  MODE 1: out = acc + bias
template <int H, int C, int MODE>
__global__ void agg_csr(const int* __restrict__ rowptr, const int* __restrict__ eids,
                        const int* __restrict__ srcs,
                        const float* __restrict__ p, const float* __restrict__ den,
                        const float* __restrict__ hbuf,
                        const float* __restrict__ bias,
                        const float* __restrict__ bng, const float* __restrict__ bnb,
                        const float* __restrict__ bnm, const float* __restrict__ bnv,
                        float* __restrict__ out) {
    constexpr int FDIM = H * C;
    constexpr int NF = (FDIM + 31) / 32;
    int w = (blockIdx.x * blockDim.x + threadIdx.x) >> 5;
    int lane = threadIdx.x & 31;
    if (w >= NN) return;
    int d = w;
    float invden = 0.0f;
    if (lane < H) invden = 1.0f / (den[d * H + lane] + 1e-16f);
    float acc[NF];
    #pragma unroll
    for (int k = 0; k < NF; k++) acc[k] = 0.0f;
    int beg = rowptr[d], end = rowptr[d + 1];
    for (int j = beg; j < end; j++) {
        int e = eids[j];
        int s = srcs[j];
        float a = (lane < H) ? p[e * H + lane] * invden : 0.0f;
        #pragma unroll
        for (int k = 0; k < NF; k++) {
            int f = lane + 32 * k;
            float al = __shfl_sync(0xFFFFFFFFu, a, f / C < H ? f / C : 0);
            if ((FDIM % 32 == 0) || f < FDIM)
                acc[k] += hbuf[(size_t)s * FDIM + f] * al;
        }
    }
    #pragma unroll
    for (int k = 0; k < NF; k++) {
        int f = lane + 32 * k;
        if ((FDIM % 32 != 0) && f >= FDIM) continue;
        float v = acc[k] + bias[f];
        if (MODE == 0) {
            v = bng[f] * (v - bnm[f]) * rsqrtf(bnv[f] + BN_EPS) + bnb[f];
            v = (v > 0.0f) ? v : (expf(v) - 1.0f);
        }
        out[(size_t)d * FDIM + f] = v;
    }
}

// ================= launch =================
extern "C" void kernel_launch(void* const* d_in, const int* in_sizes, int n_in,
                              void* d_out, int out_size) {
    const float* x       = (const float*)d_in[0];
    const int*   eidx    = (const int*)d_in[1];
    const float* W0      = (const float*)d_in[2];
    const float* a_src0  = (const float*)d_in[3];
    const float* a_dst0  = (const float*)d_in[4];
    const float* b0      = (const float*)d_in[5];
    const float* bn0_g   = (const float*)d_in[6];
    const float* bn0_b   = (const float*)d_in[7];
    const float* bn0_m   = (const float*)d_in[8];
    const float* bn0_v   = (const float*)d_in[9];
    const float* W1      = (const float*)d_in[10];
    const float* a_src1  = (const float*)d_in[11];
    const float* a_dst1  = (const float*)d_in[12];
    const float* b1      = (const float*)d_in[13];
    const float* bn1_g   = (const float*)d_in[14];
    const float* bn1_b   = (const float*)d_in[15];
    const float* bn1_m   = (const float*)d_in[16];
    const float* bn1_v   = (const float*)d_in[17];
    const float* W2      = (const float*)d_in[18];
    const float* a_src2  = (const float*)d_in[19];
    const float* a_dst2  = (const float*)d_in[20];
    const float* b2      = (const float*)d_in[21];
    float* out = (float*)d_out;

    int E = in_sizes[1] / 2;
    const int* src = eidx;
    const int* dst = eidx + E;

    float *h_buf, *x1_buf, *as_buf, *ad_buf, *e_buf, *m_buf, *den_buf;
    int *deg, *cur, *rowptr, *eids, *srcs;
    cudaGetSymbolAddress((void**)&h_buf, g_h);
    cudaGetSymbolAddress((void**)&x1_buf, g_x1);
    cudaGetSymbolAddress((void**)&as_buf, g_as);
    cudaGetSymbolAddress((void**)&ad_buf, g_ad);
    cudaGetSymbolAddress((void**)&e_buf, g_e);
    cudaGetSymbolAddress((void**)&m_buf, g_m);
    cudaGetSymbolAddress((void**)&den_buf, g_den);
    cudaGetSymbolAddress((void**)&deg, g_deg);
    cudaGetSymbolAddress((void**)&cur, g_cur);
    cudaGetSymbolAddress((void**)&rowptr, g_rowptr);
    cudaGetSymbolAddress((void**)&eids, g_eids);
    cudaGetSymbolAddress((void**)&srcs, g_srcs);

    // ---- CSR by dst ----
    zero_counts<<<cdiv(NN, 256), 256>>>(deg, cur, NN);
    csr_count<<<cdiv(E, 256), 256>>>(dst, E, deg);
    csr_scan<<<1, 1024>>>(deg, rowptr, NN, E);
    csr_fill<<<cdiv(E, 256), 256>>>(src, dst, E, rowptr, cur, eids, srcs);

    // ---- layer 0 ----
    gemm128<<<dim3(cdiv(FD, 128), cdiv(NN, 128)), 256>>>(x, W0, h_buf, NN, FD, 256);
    attn_scores<<<cdiv(NN * HEADS * 32, 256), 256>>>(h_buf, a_src0, a_dst0, as_buf, ad_buf,
                                                     NN, HEADS, CH);
    init_md<<<cdiv(NN * HEADS, 256), 256>>>(m_buf, den_buf, NN * HEADS);
    edge_scores<<<cdiv(E * HEADS, 256), 256>>>(src, dst, as_buf, ad_buf, e_buf, m_buf, E, HEADS);
    edge_exp<<<cdiv(E * HEADS, 256), 256>>>(dst, e_buf, m_buf, den_buf, E, HEADS);
    agg_csr<HEADS, CH, 0><<<cdiv(NN * 32, 256), 256>>>(rowptr, eids, srcs, e_buf, den_buf,
                                                       h_buf, b0, bn0_g, bn0_b, bn0_m, bn0_v,
                                                       x1_buf);

    // ---- layer 1 ----
    gemm128<<<dim3(cdiv(FD, 128), cdiv(NN, 128)), 256>>>(x1_buf, W1, h_buf, NN, FD, FD);
    attn_scores<<<cdiv(NN * HEADS * 32, 256), 256>>>(h_buf, a_src1, a_dst1, as_buf, ad_buf,
                                                     NN, HEADS, CH);
    init_md<<<cdiv(NN * HEADS, 256), 256>>>(m_buf, den_buf, NN * HEADS);
    edge_scores<<<cdiv(E * HEADS, 256), 256>>>(src, dst, as_buf, ad_buf, e_buf, m_buf, E, HEADS);
    edge_exp<<<cdiv(E * HEADS, 256), 256>>>(dst, e_buf, m_buf, den_buf, E, HEADS);
    agg_csr<HEADS, CH, 0><<<cdiv(NN * 32, 256), 256>>>(rowptr, eids, srcs, e_buf, den_buf,
                                                       h_buf, b1, bn1_g, bn1_b, bn1_m, bn1_v,
                                                       x1_buf);

    // ---- layer 2 (heads=1, ch=40) ----
    gemm128<<<dim3(cdiv(OUTD, 128), cdiv(NN, 128)), 256>>>(x1_buf, W2, h_buf, NN, OUTD, FD);
    attn_scores<<<cdiv(NN * 32, 256), 256>>>(h_buf, a_src2, a_dst2, as_buf, ad_buf,
                                             NN, 1, OUTD);
    init_md<<<cdiv(NN, 256), 256>>>(m_buf, den_buf, NN);
    edge_scores<<<cdiv(E, 256), 256>>>(src, dst, as_buf, ad_buf, e_buf, m_buf, E, 1);
    edge_exp<<<cdiv(E, 256), 256>>>(dst, e_buf, m_buf, den_buf, E, 1);
    agg_csr<1, OUTD, 1><<<cdiv(NN * 32, 256), 256>>>(rowptr, eids, srcs, e_buf, den_buf,
                                                     h_buf, b2, nullptr, nullptr, nullptr,
                                                     nullptr, out);
}

// round 3
// speedup vs baseline: 2.6812x; 1.1337x over previous
#include <cuda_runtime.h>
#include <math.h>
#include <stdint.h>

#define NN 50000
#define EE 850000
#define FD 256      // HEADS*HID
#define HEADS 4
#define CH 64
#define OUTD 40
#define BN_EPS 1e-5f
#define NEG_SLOPE 0.2f

// ---------------- scratch (static, allocation-free) ----------------
__device__ float g_h[NN * FD];     // GEMM output of current layer
__device__ float g_x1[NN * FD];    // activations between layers
__device__ float g_as[NN * HEADS];
__device__ float g_ad[NN * HEADS];
__device__ float g_e[EE * HEADS];  // per-edge scores -> probs
__device__ float g_m[NN * HEADS];
__device__ float g_den[NN * HEADS];
__device__ int   g_deg[NN];
__device__ int   g_cur[NN];
__device__ int   g_rowptr[NN + 1];
__device__ int   g_eids[EE];
__device__ int   g_srcs[EE];

// ---------------- helpers ----------------
__device__ __forceinline__ void atomicMaxF(float* addr, float val) {
    if (val >= 0.0f)
        atomicMax((int*)addr, __float_as_int(val));
    else
        atomicMin((unsigned int*)addr, __float_as_uint(val));
}

static inline int cdiv(int a, int b) { return (a + b - 1) / b; }

__device__ __forceinline__ uint32_t f2tf32(float x) {
    uint32_t r;
    asm("cvt.rna.tf32.f32 %0, %1;" : "=r"(r) : "f"(x));
    return r;
}

__device__ __forceinline__ void mma_tf32(float c[4], uint32_t a0, uint32_t a1,
                                         uint32_t a2, uint32_t a3,
                                         uint32_t b0, uint32_t b1) {
    asm volatile(
        "mma.sync.aligned.m16n8k8.row.col.f32.tf32.tf32.f32 "
        "{%0,%1,%2,%3}, {%4,%5,%6,%7}, {%8,%9}, {%0,%1,%2,%3};"
        : "+f"(c[0]), "+f"(c[1]), "+f"(c[2]), "+f"(c[3])
        : "r"(a0), "r"(a1), "r"(a2), "r"(a3), "r"(b0), "r"(b1));
}

// ================= CSR build =================
__global__ void zero_counts(int* __restrict__ deg, int* __restrict__ cur, int n) {
    for (int i = blockIdx.x * blockDim.x + threadIdx.x; i < n;
         i += gridDim.x * blockDim.x) { deg[i] = 0; cur[i] = 0; }
}

__global__ void csr_count(const int* __restrict__ dst, int E, int* __restrict__ deg) {
    for (int i = blockIdx.x * blockDim.x + threadIdx.x; i < E;
         i += gridDim.x * blockDim.x)
        atomicAdd(&deg[dst[i]], 1);
}

// single-block exclusive scan over NN elements
__global__ void csr_scan(const int* __restrict__ deg, int* __restrict__ rowptr, int n, int E) {
    __shared__ int part[1024];
    int t = threadIdx.x;
    int chunk = (n + 1023) / 1024;
    int start = t * chunk;
    int stop = min(start + chunk, n);
    int sum = 0;
    for (int i = start; i < stop; i++) sum += deg[i];
    part[t] = sum;
    __syncthreads();
    for (int o = 1; o < 1024; o <<= 1) {
        int v = (t >= o) ? part[t - o] : 0;
        __syncthreads();
        part[t] += v;
        __syncthreads();
    }
    int run = part[t] - sum;
    for (int i = start; i < stop; i++) { rowptr[i] = run; run += deg[i]; }
    if (t == 0) rowptr[n] = E;
}

__global__ void csr_fill(const int* __restrict__ src, const int* __restrict__ dst, int E,
                         const int* __restrict__ rowptr, int* __restrict__ cur,
                         int* __restrict__ eids, int* __restrict__ srcs) {
    for (int i = blockIdx.x * blockDim.x + threadIdx.x; i < E;
         i += gridDim.x * blockDim.x) {
        int d = dst[i];
        int pos = rowptr[d] + atomicAdd(&cur[d], 1);
        eids[pos] = i;
        srcs[pos] = src[i];
    }
}

// ================= GEMM: tf32 tensor-core, 3xTF32 compensated =================
// C[M,N] = A[M,K] @ B[K,N].  BM=128, BN=64, BK=32. 256 threads, warp tile 32x32.
#define BK_PAD 36
__global__ __launch_bounds__(256, 2)
void gemm_tf32(const float* __restrict__ A, const float* __restrict__ B,
               float* __restrict__ C, int M, int N, int K) {
    __shared__ float As[128][BK_PAD];   // [m][k]
    __shared__ float Bs[64][BK_PAD];    // [n][k]  (transposed)
    int tid = threadIdx.x;
    int lane = tid & 31;
    int warp = tid >> 5;
    int wm = warp & 3;          // 0..3 -> m offset wm*32
    int wn = warp >> 2;         // 0..1 -> n offset wn*32
    int row0 = blockIdx.y * 128;
    int col0 = blockIdx.x * 64;
    int g = lane >> 2;          // group id 0..7
    int tg = lane & 3;          // 0..3

    float acc[2][4][4];
    #pragma unroll
    for (int i = 0; i < 2; i++)
        #pragma unroll
        for (int j = 0; j < 4; j++)
            #pragma unroll
            for (int k = 0; k < 4; k++) acc[i][j][k] = 0.0f;

    bool fullN = (col0 + 64 <= N);

    for (int kk = 0; kk < K; kk += 32) {
        // load A tile: 128x32 floats = 1024 float4
        #pragma unroll
        for (int l = 0; l < 4; l++) {
            int i = tid + l * 256;
            int r = i >> 3, c4 = i & 7;
            float4 v = make_float4(0.f, 0.f, 0.f, 0.f);
            if (row0 + r < M)
                v = *(const float4*)&A[(size_t)(row0 + r) * K + kk + c4 * 4];
            *(float4*)&As[r][c4 * 4] = v;
        }
        // load B tile: 32x64 floats -> Bs[n][k]
        if (fullN) {
            #pragma unroll
            for (int l = 0; l < 2; l++) {
                int i = tid + l * 256;
                int kr = i >> 4, c4 = i & 15;
                float4 v = *(const float4*)&B[(size_t)(kk + kr) * N + col0 + c4 * 4];
                Bs[c4 * 4 + 0][kr] = v.x;
                Bs[c4 * 4 + 1][kr] = v.y;
                Bs[c4 * 4 + 2][kr] = v.z;
                Bs[c4 * 4 + 3][kr] = v.w;
            }
        } else {
            #pragma unroll
            for (int l = 0; l < 8; l++) {
                int i = tid + l * 256;
                int kr = i >> 6, c = i & 63;
                float v = 0.0f;
                if (col0 + c < N) v = B[(size_t)(kk + kr) * N + col0 + c];
                Bs[c][kr] = v;
            }
        }
        __syncthreads();

        #pragma unroll
        for (int ks = 0; ks < 4; ks++) {
            int kb = ks * 8;
            // A fragments (2 m-tiles)
            uint32_t ah[2][4], al[2][4];
            #pragma unroll
            for (int mf = 0; mf < 2; mf++) {
                int rb = wm * 32 + mf * 16 + g;
                float a0 = As[rb][kb + tg];
                float a1 = As[rb + 8][kb + tg];
                float a2 = As[rb][kb + tg + 4];
                float a3 = As[rb + 8][kb + tg + 4];
                ah[mf][0] = f2tf32(a0); al[mf][0] = f2tf32(a0 - __uint_as_float(ah[mf][0]));
                ah[mf][1] = f2tf32(a1); al[mf][1] = f2tf32(a1 - __uint_as_float(ah[mf][1]));
                ah[mf][2] = f2tf32(a2); al[mf][2] = f2tf32(a2 - __uint_as_float(ah[mf][2]));
                ah[mf][3] = f2tf32(a3); al[mf][3] = f2tf32(a3 - __uint_as_float(ah[mf][3]));
            }
            // B fragments (4 n-tiles)
            uint32_t bh[4][2], bl[4][2];
            #pragma unroll
            for (int nf = 0; nf < 4; nf++) {
                int nb = wn * 32 + nf * 8 + g;
                float b0 = Bs[nb][kb + tg];
                float b1 = Bs[nb][kb + tg + 4];
                bh[nf][0] = f2tf32(b0); bl[nf][0] = f2tf32(b0 - __uint_as_float(bh[nf][0]));
                bh[nf][1] = f2tf32(b1); bl[nf][1] = f2tf32(b1 - __uint_as_float(bh[nf][1]));
            }
            #pragma unroll
            for (int mf = 0; mf < 2; mf++)
                #pragma unroll
                for (int nf = 0; nf < 4; nf++) {
                    mma_tf32(acc[mf][nf], al[mf][0], al[mf][1], al[mf][2], al[mf][3],
                             bh[nf][0], bh[nf][1]);
                    mma_tf32(acc[mf][nf], ah[mf][0], ah[mf][1], ah[mf][2], ah[mf][3],
                             bl[nf][0], bl[nf][1]);
                    mma_tf32(acc[mf][nf], ah[mf][0], ah[mf][1], ah[mf][2], ah[mf][3],
                             bh[nf][0], bh[nf][1]);
                }
        }
        __syncthreads();
    }

    // epilogue
    #pragma unroll
    for (int mf = 0; mf < 2; mf++) {
        #pragma unroll
        for (int nf = 0; nf < 4; nf++) {
            int col = col0 + wn * 32 + nf * 8 + 2 * tg;
            #pragma unroll
            for (int half = 0; half < 2; half++) {
                int row = row0 + wm * 32 + mf * 16 + g + half * 8;
                if (row < M && col < N) {
                    float2 v = make_float2(acc[mf][nf][half * 2], acc[mf][nf][half * 2 + 1]);
                    *(float2*)&C[(size_t)row * N + col] = v;
                }
            }
        }
    }
}

// ---------------- per-node attention dot products (warp per node-head) ----------------
__global__ void attn_scores(const float* __restrict__ h, const float* __restrict__ asrc,
                            const float* __restrict__ adst, float* __restrict__ outs,
                            float* __restrict__ outd, int n, int heads, int ch) {
    int w = (blockIdx.x * blockDim.x + threadIdx.x) >> 5;
    int lane = threadIdx.x & 31;
    if (w >= n * heads) return;
    int node = w / heads;
    int hh = w - node * heads;
    int fd = heads * ch;
    float s = 0.0f, d = 0.0f;
    for (int c = lane; c < ch; c += 32) {
        float v = h[(size_t)node * fd + hh * ch + c];
        s += v * asrc[hh * ch + c];
        d += v * adst[hh * ch + c];
    }
    #pragma unroll
    for (int o = 16; o > 0; o >>= 1) {
        s += __shfl_xor_sync(0xFFFFFFFFu, s, o);
        d += __shfl_xor_sync(0xFFFFFFFFu, d, o);
    }
    if (lane == 0) { outs[w] = s; outd[w] = d; }
}

// ---------------- init: m=-3e38, den=0 ----------------
__global__ void init_md(float* __restrict__ m, float* __restrict__ den, int nmh) {
    for (int i = blockIdx.x * blockDim.x + threadIdx.x; i < nmh;
         i += gridDim.x * blockDim.x) { m[i] = -3e38f; den[i] = 0.0f; }
}

// ---------------- edge pass 1 ----------------
__global__ void edge_scores(const int* __restrict__ src, const int* __restrict__ dst,
                            const float* __restrict__ as_, const float* __restrict__ ad_,
                            float* __restrict__ e, float* __restrict__ m,
                            int E, int heads) {
    int total = E * heads;
    for (int i = blockIdx.x * blockDim.x + threadIdx.x; i < total;
         i += gridDim.x * blockDim.x) {
        int ed = i / heads;
        int hh = i - ed * heads;
        int s = src[ed], d = dst[ed];
        float v = as_[s * heads + hh] + ad_[d * heads + hh];
        v = (v > 0.0f) ? v : NEG_SLOPE * v;
        e[i] = v;
        atomicMaxF(&m[d * heads + hh], v);
    }
}

// ---------------- edge pass 2 ----------------
__global__ void edge_exp(const int* __restrict__ dst, float* __restrict__ e,
                         const float* __restrict__ m, float* __restrict__ den,
                         int E, int heads) {
    int total = E * heads;
    for (int i = blockIdx.x * blockDim.x + threadIdx.x; i < total;
         i += gridDim.x * blockDim.x) {
        int ed = i / heads;
        int hh = i - ed * heads;
        int d = dst[ed];
        float p = __expf(e[i] - m[d * heads + hh]);
        e[i] = p;
        atomicAdd(&den[d * heads + hh], p);
    }
}

// ---------------- CSR gather aggregation + fused epilogue ----------------
template <int H, int C, int MODE>
__global__ void agg_csr(const int* __restrict__ rowptr, const int* __restrict__ eids,
                        const int* __restrict__ srcs,
                        const float* __restrict__ p, const float* __restrict__ den,
                        const float* __restrict__ hbuf,
                        const float* __restrict__ bias,
                        const float* __restrict__ bng, const float* __restrict__ bnb,
                        const float* __restrict__ bnm, const float* __restrict__ bnv,
                        float* __restrict__ out) {
    constexpr int FDIM = H * C;
    constexpr int NF = (FDIM + 31) / 32;
    int w = (blockIdx.x * blockDim.x + threadIdx.x) >> 5;
    int lane = threadIdx.x & 31;
    if (w >= NN) return;
    int d = w;
    float invden = 0.0f;
    if (lane < H) invden = 1.0f / (den[d * H + lane] + 1e-16f);
    float acc[NF];
    #pragma unroll
    for (int k = 0; k < NF; k++) acc[k] = 0.0f;
    int beg = rowptr[d], end = rowptr[d + 1];
    for (int j = beg; j < end; j++) {
        int e = eids[j];
        int s = srcs[j];
        float a = (lane < H) ? p[e * H + lane] * invden : 0.0f;
        #pragma unroll
        for (int k = 0; k < NF; k++) {
            int f = lane + 32 * k;
            float al = __shfl_sync(0xFFFFFFFFu, a, f / C < H ? f / C : 0);
            if ((FDIM % 32 == 0) || f < FDIM)
                acc[k] += hbuf[(size_t)s * FDIM + f] * al;
        }
    }
    #pragma unroll
    for (int k = 0; k < NF; k++) {
        int f = lane + 32 * k;
        if ((FDIM % 32 != 0) && f >= FDIM) continue;
        float v = acc[k] + bias[f];
        if (MODE == 0) {
            v = bng[f] * (v - bnm[f]) * rsqrtf(bnv[f] + BN_EPS) + bnb[f];
            v = (v > 0.0f) ? v : (expf(v) - 1.0f);
        }
        out[(size_t)d * FDIM + f] = v;
    }
}

// ================= launch =================
extern "C" void kernel_launch(void* const* d_in, const int* in_sizes, int n_in,
                              void* d_out, int out_size) {
    const float* x       = (const float*)d_in[0];
    const int*   eidx    = (const int*)d_in[1];
    const float* W0      = (const float*)d_in[2];
    const float* a_src0  = (const float*)d_in[3];
    const float* a_dst0  = (const float*)d_in[4];
    const float* b0      = (const float*)d_in[5];
    const float* bn0_g   = (const float*)d_in[6];
    const float* bn0_b   = (const float*)d_in[7];
    const float* bn0_m   = (const float*)d_in[8];
    const float* bn0_v   = (const float*)d_in[9];
    const float* W1      = (const float*)d_in[10];
    const float* a_src1  = (const float*)d_in[11];
    const float* a_dst1  = (const float*)d_in[12];
    const float* b1      = (const float*)d_in[13];
    const float* bn1_g   = (const float*)d_in[14];
    const float* bn1_b   = (const float*)d_in[15];
    const float* bn1_m   = (const float*)d_in[16];
    const float* bn1_v   = (const float*)d_in[17];
    const float* W2      = (const float*)d_in[18];
    const float* a_src2  = (const float*)d_in[19];
    const float* a_dst2  = (const float*)d_in[20];
    const float* b2      = (const float*)d_in[21];
    float* out = (float*)d_out;

    int E = in_sizes[1] / 2;
    const int* src = eidx;
    const int* dst = eidx + E;

    float *h_buf, *x1_buf, *as_buf, *ad_buf, *e_buf, *m_buf, *den_buf;
    int *deg, *cur, *rowptr, *eids, *srcs;
    cudaGetSymbolAddress((void**)&h_buf, g_h);
    cudaGetSymbolAddress((void**)&x1_buf, g_x1);
    cudaGetSymbolAddress((void**)&as_buf, g_as);
    cudaGetSymbolAddress((void**)&ad_buf, g_ad);
    cudaGetSymbolAddress((void**)&e_buf, g_e);
    cudaGetSymbolAddress((void**)&m_buf, g_m);
    cudaGetSymbolAddress((void**)&den_buf, g_den);
    cudaGetSymbolAddress((void**)&deg, g_deg);
    cudaGetSymbolAddress((void**)&cur, g_cur);
    cudaGetSymbolAddress((void**)&rowptr, g_rowptr);
    cudaGetSymbolAddress((void**)&eids, g_eids);
    cudaGetSymbolAddress((void**)&srcs, g_srcs);

    // ---- CSR by dst ----
    zero_counts<<<cdiv(NN, 256), 256>>>(deg, cur, NN);
    csr_count<<<cdiv(E, 256), 256>>>(dst, E, deg);
    csr_scan<<<1, 1024>>>(deg, rowptr, NN, E);
    csr_fill<<<cdiv(E, 256), 256>>>(src, dst, E, rowptr, cur, eids, srcs);

    // ---- layer 0 ----
    gemm_tf32<<<dim3(cdiv(FD, 64), cdiv(NN, 128)), 256>>>(x, W0, h_buf, NN, FD, 256);
    attn_scores<<<cdiv(NN * HEADS * 32, 256), 256>>>(h_buf, a_src0, a_dst0, as_buf, ad_buf,
                                                     NN, HEADS, CH);
    init_md<<<cdiv(NN * HEADS, 256), 256>>>(m_buf, den_buf, NN * HEADS);
    edge_scores<<<cdiv(E * HEADS, 256), 256>>>(src, dst, as_buf, ad_buf, e_buf, m_buf, E, HEADS);
    edge_exp<<<cdiv(E * HEADS, 256), 256>>>(dst, e_buf, m_buf, den_buf, E, HEADS);
    agg_csr<HEADS, CH, 0><<<cdiv(NN * 32, 256), 256>>>(rowptr, eids, srcs, e_buf, den_buf,
                                                       h_buf, b0, bn0_g, bn0_b, bn0_m, bn0_v,
                                                       x1_buf);

    // ---- layer 1 ----
    gemm_tf32<<<dim3(cdiv(FD, 64), cdiv(NN, 128)), 256>>>(x1_buf, W1, h_buf, NN, FD, FD);
    attn_scores<<<cdiv(NN * HEADS * 32, 256), 256>>>(h_buf, a_src1, a_dst1, as_buf, ad_buf,
                                                     NN, HEADS, CH);
    init_md<<<cdiv(NN * HEADS, 256), 256>>>(m_buf, den_buf, NN * HEADS);
    edge_scores<<<cdiv(E * HEADS, 256), 256>>>(src, dst, as_buf, ad_buf, e_buf, m_buf, E, HEADS);
    edge_exp<<<cdiv(E * HEADS, 256), 256>>>(dst, e_buf, m_buf, den_buf, E, HEADS);
    agg_csr<HEADS, CH, 0><<<cdiv(NN * 32, 256), 256>>>(rowptr, eids, srcs, e_buf, den_buf,
                                                       h_buf, b1, bn1_g, bn1_b, bn1_m, bn1_v,
                                                       x1_buf);

    // ---- layer 2 (heads=1, ch=40) ----
    gemm_tf32<<<dim3(cdiv(OUTD, 64), cdiv(NN, 128)), 256>>>(x1_buf, W2, h_buf, NN, OUTD, FD);
    attn_scores<<<cdiv(NN * 32, 256), 256>>>(h_buf, a_src2, a_dst2, as_buf, ad_buf,
                                             NN, 1, OUTD);
    init_md<<<cdiv(NN, 256), 256>>>(m_buf, den_buf, NN);
    edge_scores<<<cdiv(E, 256), 256>>>(src, dst, as_buf, ad_buf, e_buf, m_buf, E, 1);
    edge_exp<<<cdiv(E, 256), 256>>>(dst, e_buf, m_buf, den_buf, E, 1);
    agg_csr<1, OUTD, 1><<<cdiv(NN * 32, 256), 256>>>(rowptr, eids, srcs, e_buf, den_buf,
                                                     h_buf, b2, nullptr, nullptr, nullptr,
                                                     nullptr, out);
}

// round 4
// speedup vs baseline: 3.4524x; 1.2876x over previous
#include <cuda_runtime.h>
#include <math.h>
#include <stdint.h>

#define NN 50000
#define EE 850000
#define FD 256      // HEADS*HID
#define HEADS 4
#define CH 64
#define OUTD 40
#define BN_EPS 1e-5f
#define NEG_SLOPE 0.2f

// ---------------- scratch (static, allocation-free) ----------------
__device__ __align__(256) float g_h[NN * FD];     // GEMM output of current layer
__device__ __align__(256) float g_x1[NN * FD];    // activations between layers
__device__ __align__(256) float g_as[NN * HEADS];
__device__ __align__(256) float g_ad[NN * HEADS];
__device__ int   g_deg[NN];
__device__ int   g_cur[NN];
__device__ int   g_rowptr[NN + 1];
__device__ int   g_srcs[EE];

static inline int cdiv(int a, int b) { return (a + b - 1) / b; }

// ---------------- tf32 split helpers ----------------
__device__ __forceinline__ void split2(float x, uint32_t& hi, uint32_t& lo) {
    hi = __float_as_uint(x) & 0xFFFFE000u;          // exact tf32 (truncated)
    lo = __float_as_uint(x - __uint_as_float(hi));  // residual; HW truncates low bits
}

__device__ __forceinline__ void mma_tf32(float c[4], uint32_t a0, uint32_t a1,
                                         uint32_t a2, uint32_t a3,
                                         uint32_t b0, uint32_t b1) {
    asm volatile(
        "mma.sync.aligned.m16n8k8.row.col.f32.tf32.tf32.f32 "
        "{%0,%1,%2,%3}, {%4,%5,%6,%7}, {%8,%9}, {%0,%1,%2,%3};"
        : "+f"(c[0]), "+f"(c[1]), "+f"(c[2]), "+f"(c[3])
        : "r"(a0), "r"(a1), "r"(a2), "r"(a3), "r"(b0), "r"(b1));
}

// ================= CSR build =================
__global__ void zero_counts(int* __restrict__ deg, int* __restrict__ cur, int n) {
    for (int i = blockIdx.x * blockDim.x + threadIdx.x; i < n;
         i += gridDim.x * blockDim.x) { deg[i] = 0; cur[i] = 0; }
}

__global__ void csr_count(const int* __restrict__ dst, int E, int* __restrict__ deg) {
    for (int i = blockIdx.x * blockDim.x + threadIdx.x; i < E;
         i += gridDim.x * blockDim.x)
        atomicAdd(&deg[dst[i]], 1);
}

__global__ void csr_scan(const int* __restrict__ deg, int* __restrict__ rowptr, int n, int E) {
    __shared__ int part[1024];
    int t = threadIdx.x;
    int chunk = (n + 1023) / 1024;
    int start = t * chunk;
    int stop = min(start + chunk, n);
    int sum = 0;
    for (int i = start; i < stop; i++) sum += deg[i];
    part[t] = sum;
    __syncthreads();
    for (int o = 1; o < 1024; o <<= 1) {
        int v = (t >= o) ? part[t - o] : 0;
        __syncthreads();
        part[t] += v;
        __syncthreads();
    }
    int run = part[t] - sum;
    for (int i = start; i < stop; i++) { rowptr[i] = run; run += deg[i]; }
    if (t == 0) rowptr[n] = E;
}

__global__ void csr_fill(const int* __restrict__ src, const int* __restrict__ dst, int E,
                         const int* __restrict__ rowptr, int* __restrict__ cur,
                         int* __restrict__ srcs) {
    for (int i = blockIdx.x * blockDim.x + threadIdx.x; i < E;
         i += gridDim.x * blockDim.x) {
        int d = dst[i];
        int pos = rowptr[d] + atomicAdd(&cur[d], 1);
        srcs[pos] = src[i];
    }
}

// ================= GEMM: tf32 tensor-core, 3xTF32 compensated =================
#define BK_PAD 36
__global__ __launch_bounds__(256, 2)
void gemm_tf32(const float* __restrict__ A, const float* __restrict__ B,
               float* __restrict__ C, int M, int N, int K) {
    __shared__ float As[128][BK_PAD];   // [m][k]
    __shared__ float Bs[64][BK_PAD];    // [n][k]
    int tid = threadIdx.x;
    int lane = tid & 31;
    int warp = tid >> 5;
    int wm = warp & 3;
    int wn = warp >> 2;
    int row0 = blockIdx.y * 128;
    int col0 = blockIdx.x * 64;
    int g = lane >> 2;
    int tg = lane & 3;

    float acc[2][4][4];
    #pragma unroll
    for (int i = 0; i < 2; i++)
        #pragma unroll
        for (int j = 0; j < 4; j++)
            #pragma unroll
            for (int k = 0; k < 4; k++) acc[i][j][k] = 0.0f;

    bool fullN = (col0 + 64 <= N);

    for (int kk = 0; kk < K; kk += 32) {
        #pragma unroll
        for (int l = 0; l < 4; l++) {
            int i = tid + l * 256;
            int r = i >> 3, c4 = i & 7;
            float4 v = make_float4(0.f, 0.f, 0.f, 0.f);
            if (row0 + r < M)
                v = *(const float4*)&A[(size_t)(row0 + r) * K + kk + c4 * 4];
            *(float4*)&As[r][c4 * 4] = v;
        }
        if (fullN) {
            #pragma unroll
            for (int l = 0; l < 2; l++) {
                int i = tid + l * 256;
                int kr = i >> 4, c4 = i & 15;
                float4 v = *(const float4*)&B[(size_t)(kk + kr) * N + col0 + c4 * 4];
                Bs[c4 * 4 + 0][kr] = v.x;
                Bs[c4 * 4 + 1][kr] = v.y;
                Bs[c4 * 4 + 2][kr] = v.z;
                Bs[c4 * 4 + 3][kr] = v.w;
            }
        } else {
            #pragma unroll
            for (int l = 0; l < 8; l++) {
                int i = tid + l * 256;
                int kr = i >> 6, c = i & 63;
                float v = 0.0f;
                if (col0 + c < N) v = B[(size_t)(kk + kr) * N + col0 + c];
                Bs[c][kr] = v;
            }
        }
        __syncthreads();

        #pragma unroll
        for (int ks = 0; ks < 4; ks++) {
            int kb = ks * 8;
            uint32_t ah[2][4], al[2][4];
            #pragma unroll
            for (int mf = 0; mf < 2; mf++) {
                int rb = wm * 32 + mf * 16 + g;
                split2(As[rb][kb + tg],     ah[mf][0], al[mf][0]);
                split2(As[rb + 8][kb + tg], ah[mf][1], al[mf][1]);
                split2(As[rb][kb + tg + 4],     ah[mf][2], al[mf][2]);
                split2(As[rb + 8][kb + tg + 4], ah[mf][3], al[mf][3]);
            }
            uint32_t bh[4][2], bl[4][2];
            #pragma unroll
            for (int nf = 0; nf < 4; nf++) {
                int nb = wn * 32 + nf * 8 + g;
                split2(Bs[nb][kb + tg],     bh[nf][0], bl[nf][0]);
                split2(Bs[nb][kb + tg + 4], bh[nf][1], bl[nf][1]);
            }
            #pragma unroll
            for (int mf = 0; mf < 2; mf++)
                #pragma unroll
                for (int nf = 0; nf < 4; nf++) {
                    mma_tf32(acc[mf][nf], al[mf][0], al[mf][1], al[mf][2], al[mf][3],
                             bh[nf][0], bh[nf][1]);
                    mma_tf32(acc[mf][nf], ah[mf][0], ah[mf][1], ah[mf][2], ah[mf][3],
                             bl[nf][0], bl[nf][1]);
                    mma_tf32(acc[mf][nf], ah[mf][0], ah[mf][1], ah[mf][2], ah[mf][3],
                             bh[nf][0], bh[nf][1]);
                }
        }
        __syncthreads();
    }

    #pragma unroll
    for (int mf = 0; mf < 2; mf++) {
        #pragma unroll
        for (int nf = 0; nf < 4; nf++) {
            int col = col0 + wn * 32 + nf * 8 + 2 * tg;
            #pragma unroll
            for (int half = 0; half < 2; half++) {
                int row = row0 + wm * 32 + mf * 16 + g + half * 8;
                if (row < M && col < N) {
                    float2 v = make_float2(acc[mf][nf][half * 2], acc[mf][nf][half * 2 + 1]);
                    *(float2*)&C[(size_t)row * N + col] = v;
                }
            }
        }
    }
}

// ---------------- per-node attention dot products (warp per node-head) ----------------
__global__ void attn_scores(const float* __restrict__ h, const float* __restrict__ asrc,
                            const float* __restrict__ adst, float* __restrict__ outs,
                            float* __restrict__ outd, int n, int heads, int ch) {
    int w = (blockIdx.x * blockDim.x + threadIdx.x) >> 5;
    int lane = threadIdx.x & 31;
    if (w >= n * heads) return;
    int node = w / heads;
    int hh = w - node * heads;
    int fd = heads * ch;
    float s = 0.0f, d = 0.0f;
    for (int c = lane; c < ch; c += 32) {
        float v = h[(size_t)node * fd + hh * ch + c];
        s += v * asrc[hh * ch + c];
        d += v * adst[hh * ch + c];
    }
    #pragma unroll
    for (int o = 16; o > 0; o >>= 1) {
        s += __shfl_xor_sync(0xFFFFFFFFu, s, o);
        d += __shfl_xor_sync(0xFFFFFFFFu, d, o);
    }
    if (lane == 0) { outs[w] = s; outd[w] = d; }
}

// ---------------- fully fused softmax + aggregation, H=4 C=64, BN+ELU epilogue ----------------
__global__ __launch_bounds__(256)
void agg_fused4(const int* __restrict__ rowptr, const int* __restrict__ srcs,
                const float* __restrict__ as_, const float* __restrict__ ad_,
                const float* __restrict__ hbuf, const float* __restrict__ bias,
                const float* __restrict__ bng, const float* __restrict__ bnb,
                const float* __restrict__ bnm, const float* __restrict__ bnv,
                float* __restrict__ out) {
    int w = (blockIdx.x * blockDim.x + threadIdx.x) >> 5;
    int lane = threadIdx.x & 31;
    if (w >= NN) return;
    int d = w;
    float4 add = *(const float4*)&ad_[d * 4];
    int beg = rowptr[d], end = rowptr[d + 1];

    // pass 1: segment max per head (lanes over edges)
    float mx0 = -3e38f, mx1 = -3e38f, mx2 = -3e38f, mx3 = -3e38f;
    for (int j = beg + lane; j < end; j += 32) {
        int s = srcs[j];
        float4 av = *(const float4*)&as_[s * 4];
        float e0 = av.x + add.x; e0 = (e0 > 0.f) ? e0 : NEG_SLOPE * e0;
        float e1 = av.y + add.y; e1 = (e1 > 0.f) ? e1 : NEG_SLOPE * e1;
        float e2 = av.z + add.z; e2 = (e2 > 0.f) ? e2 : NEG_SLOPE * e2;
        float e3 = av.w + add.w; e3 = (e3 > 0.f) ? e3 : NEG_SLOPE * e3;
        mx0 = fmaxf(mx0, e0); mx1 = fmaxf(mx1, e1);
        mx2 = fmaxf(mx2, e2); mx3 = fmaxf(mx3, e3);
    }
    #pragma unroll
    for (int o = 16; o > 0; o >>= 1) {
        mx0 = fmaxf(mx0, __shfl_xor_sync(0xFFFFFFFFu, mx0, o));
        mx1 = fmaxf(mx1, __shfl_xor_sync(0xFFFFFFFFu, mx1, o));
        mx2 = fmaxf(mx2, __shfl_xor_sync(0xFFFFFFFFu, mx2, o));
        mx3 = fmaxf(mx3, __shfl_xor_sync(0xFFFFFFFFu, mx3, o));
    }

    // pass 2: denominators
    float d0 = 0.f, d1 = 0.f, d2 = 0.f, d3 = 0.f;
    for (int j = beg + lane; j < end; j += 32) {
        int s = srcs[j];
        float4 av = *(const float4*)&as_[s * 4];
        float e0 = av.x + add.x; e0 = (e0 > 0.f) ? e0 : NEG_SLOPE * e0;
        float e1 = av.y + add.y; e1 = (e1 > 0.f) ? e1 : NEG_SLOPE * e1;
        float e2 = av.z + add.z; e2 = (e2 > 0.f) ? e2 : NEG_SLOPE * e2;
        float e3 = av.w + add.w; e3 = (e3 > 0.f) ? e3 : NEG_SLOPE * e3;
        d0 += __expf(e0 - mx0); d1 += __expf(e1 - mx1);
        d2 += __expf(e2 - mx2); d3 += __expf(e3 - mx3);
    }
    #pragma unroll
    for (int o = 16; o > 0; o >>= 1) {
        d0 += __shfl_xor_sync(0xFFFFFFFFu, d0, o);
        d1 += __shfl_xor_sync(0xFFFFFFFFu, d1, o);
        d2 += __shfl_xor_sync(0xFFFFFFFFu, d2, o);
        d3 += __shfl_xor_sync(0xFFFFFFFFu, d3, o);
    }

    // per-lane head params (lanes 0..3 active for alpha compute)
    float mxl = (lane == 1) ? mx1 : (lane == 2) ? mx2 : (lane == 3) ? mx3 : mx0;
    float denl = (lane == 1) ? d1 : (lane == 2) ? d2 : (lane == 3) ? d3 : d0;
    float adl = (lane == 1) ? add.y : (lane == 2) ? add.z : (lane == 3) ? add.w : add.x;
    float invden = 1.0f / (denl + 1e-16f);

    int hs0 = lane >> 4;        // head of feature lane*4
    int hs1 = 2 + (lane >> 4);  // head of feature 128+lane*4

    float4 acc0 = make_float4(0.f, 0.f, 0.f, 0.f);
    float4 acc1 = make_float4(0.f, 0.f, 0.f, 0.f);

    // pass 3: weighted gather (lanes over features)
    for (int j = beg; j < end; j++) {
        int s = srcs[j];
        float a = 0.f;
        if (lane < 4) {
            float e = as_[s * 4 + lane] + adl;
            e = (e > 0.f) ? e : NEG_SLOPE * e;
            a = __expf(e - mxl) * invden;
        }
        float a0 = __shfl_sync(0xFFFFFFFFu, a, hs0);
        float a1 = __shfl_sync(0xFFFFFFFFu, a, hs1);
        const float4* hp = (const float4*)(hbuf + (size_t)s * FD);
        float4 h0 = hp[lane];
        float4 h1 = hp[32 + lane];
        acc0.x += h0.x * a0; acc0.y += h0.y * a0; acc0.z += h0.z * a0; acc0.w += h0.w * a0;
        acc1.x += h1.x * a1; acc1.y += h1.y * a1; acc1.z += h1.z * a1; acc1.w += h1.w * a1;
    }

    // fused epilogue: bias + BN + ELU
    int f0 = lane * 4, f1 = 128 + lane * 4;
    #pragma unroll
    for (int c = 0; c < 2; c++) {
        int f = c ? f1 : f0;
        float4 acc = c ? acc1 : acc0;
        float4 bv = *(const float4*)&bias[f];
        float4 gv = *(const float4*)&bng[f];
        float4 betav = *(const float4*)&bnb[f];
        float4 mv = *(const float4*)&bnm[f];
        float4 vv = *(const float4*)&bnv[f];
        float4 r;
        r.x = gv.x * (acc.x + bv.x - mv.x) * rsqrtf(vv.x + BN_EPS) + betav.x;
        r.y = gv.y * (acc.y + bv.y - mv.y) * rsqrtf(vv.y + BN_EPS) + betav.y;
        r.z = gv.z * (acc.z + bv.z - mv.z) * rsqrtf(vv.z + BN_EPS) + betav.z;
        r.w = gv.w * (acc.w + bv.w - mv.w) * rsqrtf(vv.w + BN_EPS) + betav.w;
        r.x = (r.x > 0.f) ? r.x : (expf(r.x) - 1.f);
        r.y = (r.y > 0.f) ? r.y : (expf(r.y) - 1.f);
        r.z = (r.z > 0.f) ? r.z : (expf(r.z) - 1.f);
        r.w = (r.w > 0.f) ? r.w : (expf(r.w) - 1.f);
        *(float4*)&out[(size_t)d * FD + f] = r;
    }
}

// ---------------- fused softmax + aggregation, H=1 C=40, bias epilogue ----------------
__global__ __launch_bounds__(256)
void agg_fused1(const int* __restrict__ rowptr, const int* __restrict__ srcs,
                const float* __restrict__ as_, const float* __restrict__ ad_,
                const float* __restrict__ hbuf, const float* __restrict__ bias,
                float* __restrict__ out) {
    int w = (blockIdx.x * blockDim.x + threadIdx.x) >> 5;
    int lane = threadIdx.x & 31;
    if (w >= NN) return;
    int d = w;
    float adl = ad_[d];
    int beg = rowptr[d], end = rowptr[d + 1];

    float mx = -3e38f;
    for (int j = beg + lane; j < end; j += 32) {
        float e = as_[srcs[j]] + adl;
        e = (e > 0.f) ? e : NEG_SLOPE * e;
        mx = fmaxf(mx, e);
    }
    #pragma unroll
    for (int o = 16; o > 0; o >>= 1)
        mx = fmaxf(mx, __shfl_xor_sync(0xFFFFFFFFu, mx, o));

    float den = 0.f;
    for (int j = beg + lane; j < end; j += 32) {
        float e = as_[srcs[j]] + adl;
        e = (e > 0.f) ? e : NEG_SLOPE * e;
        den += __expf(e - mx);
    }
    #pragma unroll
    for (int o = 16; o > 0; o >>= 1)
        den += __shfl_xor_sync(0xFFFFFFFFu, den, o);
    float invden = 1.0f / (den + 1e-16f);

    float acc0 = 0.f, acc1 = 0.f;
    for (int j = beg; j < end; j++) {
        int s = srcs[j];
        float a = 0.f;
        if (lane == 0) {
            float e = as_[s] + adl;
            e = (e > 0.f) ? e : NEG_SLOPE * e;
            a = __expf(e - mx) * invden;
        }
        a = __shfl_sync(0xFFFFFFFFu, a, 0);
        acc0 += hbuf[(size_t)s * OUTD + lane] * a;
        if (lane < OUTD - 32) acc1 += hbuf[(size_t)s * OUTD + 32 + lane] * a;
    }
    out[(size_t)d * OUTD + lane] = acc0 + bias[lane];
    if (lane < OUTD - 32)
        out[(size_t)d * OUTD + 32 + lane] = acc1 + bias[32 + lane];
}

// ================= launch =================
extern "C" void kernel_launch(void* const* d_in, const int* in_sizes, int n_in,
                              void* d_out, int out_size) {
    const float* x       = (const float*)d_in[0];
    const int*   eidx    = (const int*)d_in[1];
    const float* W0      = (const float*)d_in[2];
    const float* a_src0  = (const float*)d_in[3];
    const float* a_dst0  = (const float*)d_in[4];
    const float* b0      = (const float*)d_in[5];
    const float* bn0_g   = (const float*)d_in[6];
    const float* bn0_b   = (const float*)d_in[7];
    const float* bn0_m   = (const float*)d_in[8];
    const float* bn0_v   = (const float*)d_in[9];
    const float* W1      = (const float*)d_in[10];
    const float* a_src1  = (const float*)d_in[11];
    const float* a_dst1  = (const float*)d_in[12];
    const float* b1      = (const float*)d_in[13];
    const float* bn1_g   = (const float*)d_in[14];
    const float* bn1_b   = (const float*)d_in[15];
    const float* bn1_m   = (const float*)d_in[16];
    const float* bn1_v   = (const float*)d_in[17];
    const float* W2      = (const float*)d_in[18];
    const float* a_src2  = (const float*)d_in[19];
    const float* a_dst2  = (const float*)d_in[20];
    const float* b2      = (const float*)d_in[21];
    float* out = (float*)d_out;

    int E = in_sizes[1] / 2;
    const int* src = eidx;
    const int* dst = eidx + E;

    float *h_buf, *x1_buf, *as_buf, *ad_buf;
    int *deg, *cur, *rowptr, *srcs;
    cudaGetSymbolAddress((void**)&h_buf, g_h);
    cudaGetSymbolAddress((void**)&x1_buf, g_x1);
    cudaGetSymbolAddress((void**)&as_buf, g_as);
    cudaGetSymbolAddress((void**)&ad_buf, g_ad);
    cudaGetSymbolAddress((void**)&deg, g_deg);
    cudaGetSymbolAddress((void**)&cur, g_cur);
    cudaGetSymbolAddress((void**)&rowptr, g_rowptr);
    cudaGetSymbolAddress((void**)&srcs, g_srcs);

    // ---- CSR by dst ----
    zero_counts<<<cdiv(NN, 256), 256>>>(deg, cur, NN);
    csr_count<<<cdiv(E, 256), 256>>>(dst, E, deg);
    csr_scan<<<1, 1024>>>(deg, rowptr, NN, E);
    csr_fill<<<cdiv(E, 256), 256>>>(src, dst, E, rowptr, cur, srcs);

    // ---- layer 0 ----
    gemm_tf32<<<dim3(cdiv(FD, 64), cdiv(NN, 128)), 256>>>(x, W0, h_buf, NN, FD, 256);
    attn_scores<<<cdiv(NN * HEADS * 32, 256), 256>>>(h_buf, a_src0, a_dst0, as_buf, ad_buf,
                                                     NN, HEADS, CH);
    agg_fused4<<<cdiv(NN * 32, 256), 256>>>(rowptr, srcs, as_buf, ad_buf, h_buf,
                                            b0, bn0_g, bn0_b, bn0_m, bn0_v, x1_buf);

    // ---- layer 1 ----
    gemm_tf32<<<dim3(cdiv(FD, 64), cdiv(NN, 128)), 256>>>(x1_buf, W1, h_buf, NN, FD, FD);
    attn_scores<<<cdiv(NN * HEADS * 32, 256), 256>>>(h_buf, a_src1, a_dst1, as_buf, ad_buf,
                                                     NN, HEADS, CH);
    agg_fused4<<<cdiv(NN * 32, 256), 256>>>(rowptr, srcs, as_buf, ad_buf, h_buf,
                                            b1, bn1_g, bn1_b, bn1_m, bn1_v, x1_buf);

    // ---- layer 2 (heads=1, ch=40) ----
    gemm_tf32<<<dim3(cdiv(OUTD, 64), cdiv(NN, 128)), 256>>>(x1_buf, W2, h_buf, NN, OUTD, FD);
    attn_scores<<<cdiv(NN * 32, 256), 256>>>(h_buf, a_src2, a_dst2, as_buf, ad_buf,
                                             NN, 1, OUTD);
    agg_fused1<<<cdiv(NN * 32, 256), 256>>>(rowptr, srcs, as_buf, ad_buf, h_buf, b2, out);
}

// round 5
// speedup vs baseline: 3.8752x; 1.1225x over previous
#include <cuda_runtime.h>
#include <math.h>
#include <stdint.h>

#define NN 50000
#define EE 850000
#define FD 256      // HEADS*HID
#define HEADS 4
#define CH 64
#define OUTD 40
#define BN_EPS 1e-5f
#define NEG_SLOPE 0.2f

// ---------------- scratch (static, allocation-free) ----------------
__device__ __align__(256) float g_h[NN * FD];     // GEMM output of current layer
__device__ __align__(256) float g_x1[NN * FD];    // activations between layers
__device__ __align__(256) float g_as[NN * HEADS];
__device__ __align__(256) float g_ad[NN * HEADS];
__device__ __align__(256) float g_alpha[(size_t)EE * HEADS];  // per-edge exp values
__device__ int   g_deg[NN];
__device__ int   g_cur[NN];
__device__ int   g_rowptr[NN + 1];
__device__ int   g_srcs[EE];

static inline int cdiv(int a, int b) { return (a + b - 1) / b; }

// ---------------- tf32 split helpers ----------------
__device__ __forceinline__ void split2(float x, uint32_t& hi, uint32_t& lo) {
    hi = __float_as_uint(x) & 0xFFFFE000u;          // exact tf32 (truncated)
    lo = __float_as_uint(x - __uint_as_float(hi));  // residual
}

__device__ __forceinline__ void mma_tf32(float c[4], uint32_t a0, uint32_t a1,
                                         uint32_t a2, uint32_t a3,
                                         uint32_t b0, uint32_t b1) {
    asm volatile(
        "mma.sync.aligned.m16n8k8.row.col.f32.tf32.tf32.f32 "
        "{%0,%1,%2,%3}, {%4,%5,%6,%7}, {%8,%9}, {%0,%1,%2,%3};"
        : "+f"(c[0]), "+f"(c[1]), "+f"(c[2]), "+f"(c[3])
        : "r"(a0), "r"(a1), "r"(a2), "r"(a3), "r"(b0), "r"(b1));
}

// ================= CSR build =================
__global__ void zero_counts(int* __restrict__ deg, int* __restrict__ cur, int n) {
    for (int i = blockIdx.x * blockDim.x + threadIdx.x; i < n;
         i += gridDim.x * blockDim.x) { deg[i] = 0; cur[i] = 0; }
}

__global__ void csr_count(const int* __restrict__ dst, int E, int* __restrict__ deg) {
    for (int i = blockIdx.x * blockDim.x + threadIdx.x; i < E;
         i += gridDim.x * blockDim.x)
        atomicAdd(&deg[dst[i]], 1);
}

__global__ void csr_scan(const int* __restrict__ deg, int* __restrict__ rowptr, int n, int E) {
    __shared__ int part[1024];
    int t = threadIdx.x;
    int chunk = (n + 1023) / 1024;
    int start = t * chunk;
    int stop = min(start + chunk, n);
    int sum = 0;
    for (int i = start; i < stop; i++) sum += deg[i];
    part[t] = sum;
    __syncthreads();
    for (int o = 1; o < 1024; o <<= 1) {
        int v = (t >= o) ? part[t - o] : 0;
        __syncthreads();
        part[t] += v;
        __syncthreads();
    }
    int run = part[t] - sum;
    for (int i = start; i < stop; i++) { rowptr[i] = run; run += deg[i]; }
    if (t == 0) rowptr[n] = E;
}

__global__ void csr_fill(const int* __restrict__ src, const int* __restrict__ dst, int E,
                         const int* __restrict__ rowptr, int* __restrict__ cur,
                         int* __restrict__ srcs) {
    for (int i = blockIdx.x * blockDim.x + threadIdx.x; i < E;
         i += gridDim.x * blockDim.x) {
        int d = dst[i];
        int pos = rowptr[d] + atomicAdd(&cur[d], 1);
        srcs[pos] = src[i];
    }
}

// ================= GEMM: tf32 tensor-core, 3xTF32, reg double-buffered =================
#define BK_PAD 36
__global__ __launch_bounds__(256, 2)
void gemm_tf32(const float* __restrict__ A, const float* __restrict__ B,
               float* __restrict__ C, int M, int N, int K) {
    __shared__ float As[128][BK_PAD];   // [m][k]
    __shared__ float Bs[64][BK_PAD];    // [n][k]
    int tid = threadIdx.x;
    int lane = tid & 31;
    int warp = tid >> 5;
    int wm = warp & 3;
    int wn = warp >> 2;
    int row0 = blockIdx.y * 128;
    int col0 = blockIdx.x * 64;
    int g = lane >> 2;
    int tg = lane & 3;

    float acc[2][4][4];
    #pragma unroll
    for (int i = 0; i < 2; i++)
        #pragma unroll
        for (int j = 0; j < 4; j++)
            #pragma unroll
            for (int k = 0; k < 4; k++) acc[i][j][k] = 0.0f;

    bool fullN = (col0 + 64 <= N);

    // A-load geometry (shared by both paths)
    int ar = (tid << 1) >> 3;        // not used; computed per l below

    if (fullN) {
        float4 ra[4], rb[2];
        // prologue: load k-tile 0
        #pragma unroll
        for (int l = 0; l < 4; l++) {
            int i = tid + l * 256;
            int r = i >> 3, c4 = i & 7;
            ra[l] = make_float4(0.f, 0.f, 0.f, 0.f);
            if (row0 + r < M)
                ra[l] = *(const float4*)&A[(size_t)(row0 + r) * K + c4 * 4];
        }
        #pragma unroll
        for (int l = 0; l < 2; l++) {
            int i = tid + l * 256;
            int kr = i >> 4, c4 = i & 15;
            rb[l] = *(const float4*)&B[(size_t)kr * N + col0 + c4 * 4];
        }

        for (int kk = 0; kk < K; kk += 32) {
            // store staged regs to smem
            #pragma unroll
            for (int l = 0; l < 4; l++) {
                int i = tid + l * 256;
                int r = i >> 3, c4 = i & 7;
                *(float4*)&As[r][c4 * 4] = ra[l];
            }
            #pragma unroll
            for (int l = 0; l < 2; l++) {
                int i = tid + l * 256;
                int kr = i >> 4, c4 = i & 15;
                Bs[c4 * 4 + 0][kr] = rb[l].x;
                Bs[c4 * 4 + 1][kr] = rb[l].y;
                Bs[c4 * 4 + 2][kr] = rb[l].z;
                Bs[c4 * 4 + 3][kr] = rb[l].w;
            }
            __syncthreads();

            // prefetch next k-tile
            if (kk + 32 < K) {
                #pragma unroll
                for (int l = 0; l < 4; l++) {
                    int i = tid + l * 256;
                    int r = i >> 3, c4 = i & 7;
                    ra[l] = make_float4(0.f, 0.f, 0.f, 0.f);
                    if (row0 + r < M)
                        ra[l] = *(const float4*)&A[(size_t)(row0 + r) * K + kk + 32 + c4 * 4];
                }
                #pragma unroll
                for (int l = 0; l < 2; l++) {
                    int i = tid + l * 256;
                    int kr = i >> 4, c4 = i & 15;
                    rb[l] = *(const float4*)&B[(size_t)(kk + 32 + kr) * N + col0 + c4 * 4];
                }
            }

            #pragma unroll
            for (int ks = 0; ks < 4; ks++) {
                int kb = ks * 8;
                uint32_t ah[2][4], al[2][4];
                #pragma unroll
                for (int mf = 0; mf < 2; mf++) {
                    int rb_ = wm * 32 + mf * 16 + g;
                    split2(As[rb_][kb + tg],         ah[mf][0], al[mf][0]);
                    split2(As[rb_ + 8][kb + tg],     ah[mf][1], al[mf][1]);
                    split2(As[rb_][kb + tg + 4],     ah[mf][2], al[mf][2]);
                    split2(As[rb_ + 8][kb + tg + 4], ah[mf][3], al[mf][3]);
                }
                uint32_t bh[4][2], bl[4][2];
                #pragma unroll
                for (int nf = 0; nf < 4; nf++) {
                    int nb = wn * 32 + nf * 8 + g;
                    split2(Bs[nb][kb + tg],     bh[nf][0], bl[nf][0]);
                    split2(Bs[nb][kb + tg + 4], bh[nf][1], bl[nf][1]);
                }
                #pragma unroll
                for (int mf = 0; mf < 2; mf++)
                    #pragma unroll
                    for (int nf = 0; nf < 4; nf++) {
                        mma_tf32(acc[mf][nf], al[mf][0], al[mf][1], al[mf][2], al[mf][3],
                                 bh[nf][0], bh[nf][1]);
                        mma_tf32(acc[mf][nf], ah[mf][0], ah[mf][1], ah[mf][2], ah[mf][3],
                                 bl[nf][0], bl[nf][1]);
                        mma_tf32(acc[mf][nf], ah[mf][0], ah[mf][1], ah[mf][2], ah[mf][3],
                                 bh[nf][0], bh[nf][1]);
                    }
            }
            __syncthreads();
        }
    } else {
        for (int kk = 0; kk < K; kk += 32) {
            #pragma unroll
            for (int l = 0; l < 4; l++) {
                int i = tid + l * 256;
                int r = i >> 3, c4 = i & 7;
                float4 v = make_float4(0.f, 0.f, 0.f, 0.f);
                if (row0 + r < M)
                    v = *(const float4*)&A[(size_t)(row0 + r) * K + kk + c4 * 4];
                *(float4*)&As[r][c4 * 4] = v;
            }
            #pragma unroll
            for (int l = 0; l < 8; l++) {
                int i = tid + l * 256;
                int kr = i >> 6, c = i & 63;
                float v = 0.0f;
                if (col0 + c < N) v = B[(size_t)(kk + kr) * N + col0 + c];
                Bs[c][kr] = v;
            }
            __syncthreads();
            #pragma unroll
            for (int ks = 0; ks < 4; ks++) {
                int kb = ks * 8;
                uint32_t ah[2][4], al[2][4];
                #pragma unroll
                for (int mf = 0; mf < 2; mf++) {
                    int rb_ = wm * 32 + mf * 16 + g;
                    split2(As[rb_][kb + tg],         ah[mf][0], al[mf][0]);
                    split2(As[rb_ + 8][kb + tg],     ah[mf][1], al[mf][1]);
                    split2(As[rb_][kb + tg + 4],     ah[mf][2], al[mf][2]);
                    split2(As[rb_ + 8][kb + tg + 4], ah[mf][3], al[mf][3]);
                }
                uint32_t bh[4][2], bl[4][2];
                #pragma unroll
                for (int nf = 0; nf < 4; nf++) {
                    int nb = wn * 32 + nf * 8 + g;
                    split2(Bs[nb][kb + tg],     bh[nf][0], bl[nf][0]);
                    split2(Bs[nb][kb + tg + 4], bh[nf][1], bl[nf][1]);
                }
                #pragma unroll
                for (int mf = 0; mf < 2; mf++)
                    #pragma unroll
                    for (int nf = 0; nf < 4; nf++) {
                        mma_tf32(acc[mf][nf], al[mf][0], al[mf][1], al[mf][2], al[mf][3],
                                 bh[nf][0], bh[nf][1]);
                        mma_tf32(acc[mf][nf], ah[mf][0], ah[mf][1], ah[mf][2], ah[mf][3],
                                 bl[nf][0], bl[nf][1]);
                        mma_tf32(acc[mf][nf], ah[mf][0], ah[mf][1], ah[mf][2], ah[mf][3],
                                 bh[nf][0], bh[nf][1]);
                    }
            }
            __syncthreads();
        }
    }

    #pragma unroll
    for (int mf = 0; mf < 2; mf++) {
        #pragma unroll
        for (int nf = 0; nf < 4; nf++) {
            int col = col0 + wn * 32 + nf * 8 + 2 * tg;
            #pragma unroll
            for (int half = 0; half < 2; half++) {
                int row = row0 + wm * 32 + mf * 16 + g + half * 8;
                if (row < M && col < N) {
                    float2 v = make_float2(acc[mf][nf][half * 2], acc[mf][nf][half * 2 + 1]);
                    *(float2*)&C[(size_t)row * N + col] = v;
                }
            }
        }
    }
}

// ---------------- per-node attention dot products (warp per node-head) ----------------
__global__ void attn_scores(const float* __restrict__ h, const float* __restrict__ asrc,
                            const float* __restrict__ adst, float* __restrict__ outs,
                            float* __restrict__ outd, int n, int heads, int ch) {
    int w = (blockIdx.x * blockDim.x + threadIdx.x) >> 5;
    int lane = threadIdx.x & 31;
    if (w >= n * heads) return;
    int node = w / heads;
    int hh = w - node * heads;
    int fd = heads * ch;
    float s = 0.0f, d = 0.0f;
    for (int c = lane; c < ch; c += 32) {
        float v = h[(size_t)node * fd + hh * ch + c];
        s += v * asrc[hh * ch + c];
        d += v * adst[hh * ch + c];
    }
    #pragma unroll
    for (int o = 16; o > 0; o >>= 1) {
        s += __shfl_xor_sync(0xFFFFFFFFu, s, o);
        d += __shfl_xor_sync(0xFFFFFFFFu, d, o);
    }
    if (lane == 0) { outs[w] = s; outd[w] = d; }
}

// ---------------- fused softmax + aggregation, H=4 C=64, BN+ELU epilogue ----------------
__global__ __launch_bounds__(256)
void agg_fused4(const int* __restrict__ rowptr, const int* __restrict__ srcs,
                const float* __restrict__ as_, const float* __restrict__ ad_,
                float* __restrict__ alpha,
                const float* __restrict__ hbuf, const float* __restrict__ bias,
                const float* __restrict__ bng, const float* __restrict__ bnb,
                const float* __restrict__ bnm, const float* __restrict__ bnv,
                float* __restrict__ out) {
    __shared__ float s_al[8][32][4];
    __shared__ int   s_sr[8][32];
    int w = (blockIdx.x * blockDim.x + threadIdx.x) >> 5;
    int lane = threadIdx.x & 31;
    int wi = (threadIdx.x >> 5);
    if (w >= NN) return;
    int d = w;
    float4 add = *(const float4*)&ad_[d * 4];
    int beg = rowptr[d], end = rowptr[d + 1];

    // pass 1: segment max per head (lanes over edges)
    float mx0 = -3e38f, mx1 = -3e38f, mx2 = -3e38f, mx3 = -3e38f;
    for (int j = beg + lane; j < end; j += 32) {
        int s = srcs[j];
        float4 av = *(const float4*)&as_[s * 4];
        float e0 = av.x + add.x; e0 = (e0 > 0.f) ? e0 : NEG_SLOPE * e0;
        float e1 = av.y + add.y; e1 = (e1 > 0.f) ? e1 : NEG_SLOPE * e1;
        float e2 = av.z + add.z; e2 = (e2 > 0.f) ? e2 : NEG_SLOPE * e2;
        float e3 = av.w + add.w; e3 = (e3 > 0.f) ? e3 : NEG_SLOPE * e3;
        mx0 = fmaxf(mx0, e0); mx1 = fmaxf(mx1, e1);
        mx2 = fmaxf(mx2, e2); mx3 = fmaxf(mx3, e3);
    }
    #pragma unroll
    for (int o = 16; o > 0; o >>= 1) {
        mx0 = fmaxf(mx0, __shfl_xor_sync(0xFFFFFFFFu, mx0, o));
        mx1 = fmaxf(mx1, __shfl_xor_sync(0xFFFFFFFFu, mx1, o));
        mx2 = fmaxf(mx2, __shfl_xor_sync(0xFFFFFFFFu, mx2, o));
        mx3 = fmaxf(mx3, __shfl_xor_sync(0xFFFFFFFFu, mx3, o));
    }

    // pass 2: exp + denominators; store unnormalized p per edge
    float d0 = 0.f, d1 = 0.f, d2 = 0.f, d3 = 0.f;
    for (int j = beg + lane; j < end; j += 32) {
        int s = srcs[j];
        float4 av = *(const float4*)&as_[s * 4];
        float e0 = av.x + add.x; e0 = (e0 > 0.f) ? e0 : NEG_SLOPE * e0;
        float e1 = av.y + add.y; e1 = (e1 > 0.f) ? e1 : NEG_SLOPE * e1;
        float e2 = av.z + add.z; e2 = (e2 > 0.f) ? e2 : NEG_SLOPE * e2;
        float e3 = av.w + add.w; e3 = (e3 > 0.f) ? e3 : NEG_SLOPE * e3;
        float p0 = __expf(e0 - mx0), p1 = __expf(e1 - mx1);
        float p2 = __expf(e2 - mx2), p3 = __expf(e3 - mx3);
        *(float4*)&alpha[(size_t)j * 4] = make_float4(p0, p1, p2, p3);
        d0 += p0; d1 += p1; d2 += p2; d3 += p3;
    }
    #pragma unroll
    for (int o = 16; o > 0; o >>= 1) {
        d0 += __shfl_xor_sync(0xFFFFFFFFu, d0, o);
        d1 += __shfl_xor_sync(0xFFFFFFFFu, d1, o);
        d2 += __shfl_xor_sync(0xFFFFFFFFu, d2, o);
        d3 += __shfl_xor_sync(0xFFFFFFFFu, d3, o);
    }
    float4 inv = make_float4(1.f / (d0 + 1e-16f), 1.f / (d1 + 1e-16f),
                             1.f / (d2 + 1e-16f), 1.f / (d3 + 1e-16f));

    int h0 = lane >> 4;        // head of feature lane*4
    int h1 = 2 + (lane >> 4);  // head of feature 128+lane*4

    float4 acc0 = make_float4(0.f, 0.f, 0.f, 0.f);
    float4 acc1 = make_float4(0.f, 0.f, 0.f, 0.f);

    // pass 3: chunk-staged weighted gather (lanes over features)
    for (int jb = beg; jb < end; jb += 32) {
        int j = jb + lane;
        int s = 0;
        float4 p = make_float4(0.f, 0.f, 0.f, 0.f);
        if (j < end) {
            s = srcs[j];
            p = *(const float4*)&alpha[(size_t)j * 4];
        }
        p.x *= inv.x; p.y *= inv.y; p.z *= inv.z; p.w *= inv.w;
        __syncwarp();
        s_sr[wi][lane] = s;
        *(float4*)&s_al[wi][lane][0] = p;
        __syncwarp();
        int n = min(32, end - jb);
        #pragma unroll 4
        for (int t = 0; t < n; t++) {
            int ss = s_sr[wi][t];
            float a0 = s_al[wi][t][h0];
            float a1 = s_al[wi][t][h1];
            const float4* hp = (const float4*)(hbuf + (size_t)ss * FD);
            float4 v0 = hp[lane];
            float4 v1 = hp[32 + lane];
            acc0.x += v0.x * a0; acc0.y += v0.y * a0;
            acc0.z += v0.z * a0; acc0.w += v0.w * a0;
            acc1.x += v1.x * a1; acc1.y += v1.y * a1;
            acc1.z += v1.z * a1; acc1.w += v1.w * a1;
        }
    }

    // fused epilogue: bias + BN + ELU
    int f0 = lane * 4, f1 = 128 + lane * 4;
    #pragma unroll
    for (int c = 0; c < 2; c++) {
        int f = c ? f1 : f0;
        float4 acc = c ? acc1 : acc0;
        float4 bv = *(const float4*)&bias[f];
        float4 gv = *(const float4*)&bng[f];
        float4 betav = *(const float4*)&bnb[f];
        float4 mv = *(const float4*)&bnm[f];
        float4 vv = *(const float4*)&bnv[f];
        float4 r;
        r.x = gv.x * (acc.x + bv.x - mv.x) * rsqrtf(vv.x + BN_EPS) + betav.x;
        r.y = gv.y * (acc.y + bv.y - mv.y) * rsqrtf(vv.y + BN_EPS) + betav.y;
        r.z = gv.z * (acc.z + bv.z - mv.z) * rsqrtf(vv.z + BN_EPS) + betav.z;
        r.w = gv.w * (acc.w + bv.w - mv.w) * rsqrtf(vv.w + BN_EPS) + betav.w;
        r.x = (r.x > 0.f) ? r.x : (expf(r.x) - 1.f);
        r.y = (r.y > 0.f) ? r.y : (expf(r.y) - 1.f);
        r.z = (r.z > 0.f) ? r.z : (expf(r.z) - 1.f);
        r.w = (r.w > 0.f) ? r.w : (expf(r.w) - 1.f);
        *(float4*)&out[(size_t)d * FD + f] = r;
    }
}

// ---------------- fused softmax + aggregation, H=1 C=40, bias epilogue ----------------
__global__ __launch_bounds__(256)
void agg_fused1(const int* __restrict__ rowptr, const int* __restrict__ srcs,
                const float* __restrict__ as_, const float* __restrict__ ad_,
                float* __restrict__ alpha,
                const float* __restrict__ hbuf, const float* __restrict__ bias,
                float* __restrict__ out) {
    __shared__ float s_al[8][32];
    __shared__ int   s_sr[8][32];
    int w = (blockIdx.x * blockDim.x + threadIdx.x) >> 5;
    int lane = threadIdx.x & 31;
    int wi = (threadIdx.x >> 5);
    if (w >= NN) return;
    int d = w;
    float adl = ad_[d];
    int beg = rowptr[d], end = rowptr[d + 1];

    float mx = -3e38f;
    for (int j = beg + lane; j < end; j += 32) {
        float e = as_[srcs[j]] + adl;
        e = (e > 0.f) ? e : NEG_SLOPE * e;
        mx = fmaxf(mx, e);
    }
    #pragma unroll
    for (int o = 16; o > 0; o >>= 1)
        mx = fmaxf(mx, __shfl_xor_sync(0xFFFFFFFFu, mx, o));

    float den = 0.f;
    for (int j = beg + lane; j < end; j += 32) {
        float e = as_[srcs[j]] + adl;
        e = (e > 0.f) ? e : NEG_SLOPE * e;
        float p = __expf(e - mx);
        alpha[j] = p;
        den += p;
    }
    #pragma unroll
    for (int o = 16; o > 0; o >>= 1)
        den += __shfl_xor_sync(0xFFFFFFFFu, den, o);
    float invden = 1.0f / (den + 1e-16f);

    float acc0 = 0.f, acc1 = 0.f;
    for (int jb = beg; jb < end; jb += 32) {
        int j = jb + lane;
        int s = 0; float p = 0.f;
        if (j < end) { s = srcs[j]; p = alpha[j]; }
        __syncwarp();
        s_sr[wi][lane] = s;
        s_al[wi][lane] = p * invden;
        __syncwarp();
        int n = min(32, end - jb);
        #pragma unroll 4
        for (int t = 0; t < n; t++) {
            int ss = s_sr[wi][t];
            float a = s_al[wi][t];
            acc0 += hbuf[(size_t)ss * OUTD + lane] * a;
            if (lane < OUTD - 32)
                acc1 += hbuf[(size_t)ss * OUTD + 32 + lane] * a;
        }
    }
    out[(size_t)d * OUTD + lane] = acc0 + bias[lane];
    if (lane < OUTD - 32)
        out[(size_t)d * OUTD + 32 + lane] = acc1 + bias[32 + lane];
}

// ================= launch =================
extern "C" void kernel_launch(void* const* d_in, const int* in_sizes, int n_in,
                              void* d_out, int out_size) {
    const float* x       = (const float*)d_in[0];
    const int*   eidx    = (const int*)d_in[1];
    const float* W0      = (const float*)d_in[2];
    const float* a_src0  = (const float*)d_in[3];
    const float* a_dst0  = (const float*)d_in[4];
    const float* b0      = (const float*)d_in[5];
    const float* bn0_g   = (const float*)d_in[6];
    const float* bn0_b   = (const float*)d_in[7];
    const float* bn0_m   = (const float*)d_in[8];
    const float* bn0_v   = (const float*)d_in[9];
    const float* W1      = (const float*)d_in[10];
    const float* a_src1  = (const float*)d_in[11];
    const float* a_dst1  = (const float*)d_in[12];
    const float* b1      = (const float*)d_in[13];
    const float* bn1_g   = (const float*)d_in[14];
    const float* bn1_b   = (const float*)d_in[15];
    const float* bn1_m   = (const float*)d_in[16];
    const float* bn1_v   = (const float*)d_in[17];
    const float* W2      = (const float*)d_in[18];
    const float* a_src2  = (const float*)d_in[19];
    const float* a_dst2  = (const float*)d_in[20];
    const float* b2      = (const float*)d_in[21];
    float* out = (float*)d_out;

    int E = in_sizes[1] / 2;
    const int* src = eidx;
    const int* dst = eidx + E;

    float *h_buf, *x1_buf, *as_buf, *ad_buf, *al_buf;
    int *deg, *cur, *rowptr, *srcs;
    cudaGetSymbolAddress((void**)&h_buf, g_h);
    cudaGetSymbolAddress((void**)&x1_buf, g_x1);
    cudaGetSymbolAddress((void**)&as_buf, g_as);
    cudaGetSymbolAddress((void**)&ad_buf, g_ad);
    cudaGetSymbolAddress((void**)&al_buf, g_alpha);
    cudaGetSymbolAddress((void**)&deg, g_deg);
    cudaGetSymbolAddress((void**)&cur, g_cur);
    cudaGetSymbolAddress((void**)&rowptr, g_rowptr);
    cudaGetSymbolAddress((void**)&srcs, g_srcs);

    // ---- CSR by dst ----
    zero_counts<<<cdiv(NN, 256), 256>>>(deg, cur, NN);
    csr_count<<<cdiv(E, 256), 256>>>(dst, E, deg);
    csr_scan<<<1, 1024>>>(deg, rowptr, NN, E);
    csr_fill<<<cdiv(E, 256), 256>>>(src, dst, E, rowptr, cur, srcs);

    // ---- layer 0 ----
    gemm_tf32<<<dim3(cdiv(FD, 64), cdiv(NN, 128)), 256>>>(x, W0, h_buf, NN, FD, 256);
    attn_scores<<<cdiv(NN * HEADS * 32, 256), 256>>>(h_buf, a_src0, a_dst0, as_buf, ad_buf,
                                                     NN, HEADS, CH);
    agg_fused4<<<cdiv(NN * 32, 256), 256>>>(rowptr, srcs, as_buf, ad_buf, al_buf, h_buf,
                                            b0, bn0_g, bn0_b, bn0_m, bn0_v, x1_buf);

    // ---- layer 1 ----
    gemm_tf32<<<dim3(cdiv(FD, 64), cdiv(NN, 128)), 256>>>(x1_buf, W1, h_buf, NN, FD, FD);
    attn_scores<<<cdiv(NN * HEADS * 32, 256), 256>>>(h_buf, a_src1, a_dst1, as_buf, ad_buf,
                                                     NN, HEADS, CH);
    agg_fused4<<<cdiv(NN * 32, 256), 256>>>(rowptr, srcs, as_buf, ad_buf, al_buf, h_buf,
                                            b1, bn1_g, bn1_b, bn1_m, bn1_v, x1_buf);

    // ---- layer 2 (heads=1, ch=40) ----
    gemm_tf32<<<dim3(cdiv(OUTD, 64), cdiv(NN, 128)), 256>>>(x1_buf, W2, h_buf, NN, OUTD, FD);
    attn_scores<<<cdiv(NN * 32, 256), 256>>>(h_buf, a_src2, a_dst2, as_buf, ad_buf,
                                             NN, 1, OUTD);
    agg_fused1<<<cdiv(NN * 32, 256), 256>>>(rowptr, srcs, as_buf, ad_buf, al_buf,
                                            h_buf, b2, out);
}

// round 6
// speedup vs baseline: 4.2589x; 1.0990x over previous
#include <cuda_runtime.h>
#include <math.h>
#include <stdint.h>

#define NN 50000
#define EE 850000
#define FD 256      // HEADS*HID
#define HEADS 4
#define CH 64
#define OUTD 40
#define BN_EPS 1e-5f
#define NEG_SLOPE 0.2f

// ---------------- scratch (static, allocation-free) ----------------
__device__ __align__(256) float g_h[NN * FD];
__device__ __align__(256) float g_x1[NN * FD];
__device__ __align__(256) float g_as[NN * HEADS];
__device__ __align__(256) float g_ad[NN * HEADS];
__device__ __align__(256) float g_alpha[(size_t)EE * HEADS];
__device__ int   g_deg[NN];
__device__ int   g_cur[NN];
__device__ int   g_rowptr[NN + 1];
__device__ int   g_srcs[EE];

static inline int cdiv(int a, int b) { return (a + b - 1) / b; }

// ---------------- tf32 split helpers ----------------
__device__ __forceinline__ void split2(float x, uint32_t& hi, uint32_t& lo) {
    hi = __float_as_uint(x) & 0xFFFFE000u;
    lo = __float_as_uint(x - __uint_as_float(hi));
}

__device__ __forceinline__ void mma_tf32(float c[4], uint32_t a0, uint32_t a1,
                                         uint32_t a2, uint32_t a3,
                                         uint32_t b0, uint32_t b1) {
    asm volatile(
        "mma.sync.aligned.m16n8k8.row.col.f32.tf32.tf32.f32 "
        "{%0,%1,%2,%3}, {%4,%5,%6,%7}, {%8,%9}, {%0,%1,%2,%3};"
        : "+f"(c[0]), "+f"(c[1]), "+f"(c[2]), "+f"(c[3])
        : "r"(a0), "r"(a1), "r"(a2), "r"(a3), "r"(b0), "r"(b1));
}

// ================= CSR build =================
__global__ void zero_counts(int* __restrict__ deg, int* __restrict__ cur, int n) {
    for (int i = blockIdx.x * blockDim.x + threadIdx.x; i < n;
         i += gridDim.x * blockDim.x) { deg[i] = 0; cur[i] = 0; }
}

__global__ void csr_count(const int* __restrict__ dst, int E, int* __restrict__ deg) {
    for (int i = blockIdx.x * blockDim.x + threadIdx.x; i < E;
         i += gridDim.x * blockDim.x)
        atomicAdd(&deg[dst[i]], 1);
}

__global__ void csr_scan(const int* __restrict__ deg, int* __restrict__ rowptr, int n, int E) {
    __shared__ int part[1024];
    int t = threadIdx.x;
    int chunk = (n + 1023) / 1024;
    int start = t * chunk;
    int stop = min(start + chunk, n);
    int sum = 0;
    for (int i = start; i < stop; i++) sum += deg[i];
    part[t] = sum;
    __syncthreads();
    for (int o = 1; o < 1024; o <<= 1) {
        int v = (t >= o) ? part[t - o] : 0;
        __syncthreads();
        part[t] += v;
        __syncthreads();
    }
    int run = part[t] - sum;
    for (int i = start; i < stop; i++) { rowptr[i] = run; run += deg[i]; }
    if (t == 0) rowptr[n] = E;
}

__global__ void csr_fill(const int* __restrict__ src, const int* __restrict__ dst, int E,
                         const int* __restrict__ rowptr, int* __restrict__ cur,
                         int* __restrict__ srcs) {
    for (int i = blockIdx.x * blockDim.x + threadIdx.x; i < E;
         i += gridDim.x * blockDim.x) {
        int d = dst[i];
        int pos = rowptr[d] + atomicAdd(&cur[d], 1);
        srcs[pos] = src[i];
    }
}

// ================= GEMM tf32 3-split, fused attn-score epilogue =================
// Each block column (64 cols) maps to exactly one head, so as/ad dot products
// reduce entirely inside the block.
#define BK_PAD 36
__global__ __launch_bounds__(256, 2)
void gemm_tf32(const float* __restrict__ A, const float* __restrict__ B,
               float* __restrict__ C, int M, int N, int K,
               const float* __restrict__ asrc, const float* __restrict__ adst,
               float* __restrict__ as_out, float* __restrict__ ad_out, int heads) {
    __shared__ float As[128][BK_PAD];
    __shared__ float Bs[64][BK_PAD];
    __shared__ float s_as[128], s_ad[128];
    int tid = threadIdx.x;
    int lane = tid & 31;
    int warp = tid >> 5;
    int wm = warp & 3;
    int wn = warp >> 2;
    int row0 = blockIdx.y * 128;
    int col0 = blockIdx.x * 64;
    int g = lane >> 2;
    int tg = lane & 3;

    if (tid < 128) { s_as[tid] = 0.0f; s_ad[tid] = 0.0f; }

    float acc[2][4][4];
    #pragma unroll
    for (int i = 0; i < 2; i++)
        #pragma unroll
        for (int j = 0; j < 4; j++)
            #pragma unroll
            for (int k = 0; k < 4; k++) acc[i][j][k] = 0.0f;

    bool fullN = (col0 + 64 <= N);

    if (fullN) {
        float4 ra[4], rb[2];
        #pragma unroll
        for (int l = 0; l < 4; l++) {
            int i = tid + l * 256;
            int r = i >> 3, c4 = i & 7;
            ra[l] = make_float4(0.f, 0.f, 0.f, 0.f);
            if (row0 + r < M)
                ra[l] = *(const float4*)&A[(size_t)(row0 + r) * K + c4 * 4];
        }
        #pragma unroll
        for (int l = 0; l < 2; l++) {
            int i = tid + l * 256;
            int kr = i >> 4, c4 = i & 15;
            rb[l] = *(const float4*)&B[(size_t)kr * N + col0 + c4 * 4];
        }

        for (int kk = 0; kk < K; kk += 32) {
            #pragma unroll
            for (int l = 0; l < 4; l++) {
                int i = tid + l * 256;
                int r = i >> 3, c4 = i & 7;
                *(float4*)&As[r][c4 * 4] = ra[l];
            }
            #pragma unroll
            for (int l = 0; l < 2; l++) {
                int i = tid + l * 256;
                int kr = i >> 4, c4 = i & 15;
                Bs[c4 * 4 + 0][kr] = rb[l].x;
                Bs[c4 * 4 + 1][kr] = rb[l].y;
                Bs[c4 * 4 + 2][kr] = rb[l].z;
                Bs[c4 * 4 + 3][kr] = rb[l].w;
            }
            __syncthreads();

            if (kk + 32 < K) {
                #pragma unroll
                for (int l = 0; l < 4; l++) {
                    int i = tid + l * 256;
                    int r = i >> 3, c4 = i & 7;
                    ra[l] = make_float4(0.f, 0.f, 0.f, 0.f);
                    if (row0 + r < M)
                        ra[l] = *(const float4*)&A[(size_t)(row0 + r) * K + kk + 32 + c4 * 4];
                }
                #pragma unroll
                for (int l = 0; l < 2; l++) {
                    int i = tid + l * 256;
                    int kr = i >> 4, c4 = i & 15;
                    rb[l] = *(const float4*)&B[(size_t)(kk + 32 + kr) * N + col0 + c4 * 4];
                }
            }

            #pragma unroll
            for (int ks = 0; ks < 4; ks++) {
                int kb = ks * 8;
                uint32_t ah[2][4], al[2][4];
                #pragma unroll
                for (int mf = 0; mf < 2; mf++) {
                    int rb_ = wm * 32 + mf * 16 + g;
                    split2(As[rb_][kb + tg],         ah[mf][0], al[mf][0]);
                    split2(As[rb_ + 8][kb + tg],     ah[mf][1], al[mf][1]);
                    split2(As[rb_][kb + tg + 4],     ah[mf][2], al[mf][2]);
                    split2(As[rb_ + 8][kb + tg + 4], ah[mf][3], al[mf][3]);
                }
                uint32_t bh[4][2], bl[4][2];
                #pragma unroll
                for (int nf = 0; nf < 4; nf++) {
                    int nb = wn * 32 + nf * 8 + g;
                    split2(Bs[nb][kb + tg],     bh[nf][0], bl[nf][0]);
                    split2(Bs[nb][kb + tg + 4], bh[nf][1], bl[nf][1]);
                }
                #pragma unroll
                for (int mf = 0; mf < 2; mf++)
                    #pragma unroll
                    for (int nf = 0; nf < 4; nf++) {
                        mma_tf32(acc[mf][nf], al[mf][0], al[mf][1], al[mf][2], al[mf][3],
                                 bh[nf][0], bh[nf][1]);
                        mma_tf32(acc[mf][nf], ah[mf][0], ah[mf][1], ah[mf][2], ah[mf][3],
                                 bl[nf][0], bl[nf][1]);
                        mma_tf32(acc[mf][nf], ah[mf][0], ah[mf][1], ah[mf][2], ah[mf][3],
                                 bh[nf][0], bh[nf][1]);
                    }
            }
            __syncthreads();
        }
    } else {
        for (int kk = 0; kk < K; kk += 32) {
            #pragma unroll
            for (int l = 0; l < 4; l++) {
                int i = tid + l * 256;
                int r = i >> 3, c4 = i & 7;
                float4 v = make_float4(0.f, 0.f, 0.f, 0.f);
                if (row0 + r < M)
                    v = *(const float4*)&A[(size_t)(row0 + r) * K + kk + c4 * 4];
                *(float4*)&As[r][c4 * 4] = v;
            }
            #pragma unroll
            for (int l = 0; l < 8; l++) {
                int i = tid + l * 256;
                int kr = i >> 6, c = i & 63;
                float v = 0.0f;
                if (col0 + c < N) v = B[(size_t)(kk + kr) * N + col0 + c];
                Bs[c][kr] = v;
            }
            __syncthreads();
            #pragma unroll
            for (int ks = 0; ks < 4; ks++) {
                int kb = ks * 8;
                uint32_t ah[2][4], al[2][4];
                #pragma unroll
                for (int mf = 0; mf < 2; mf++) {
                    int rb_ = wm * 32 + mf * 16 + g;
                    split2(As[rb_][kb + tg],         ah[mf][0], al[mf][0]);
                    split2(As[rb_ + 8][kb + tg],     ah[mf][1], al[mf][1]);
                    split2(As[rb_][kb + tg + 4],     ah[mf][2], al[mf][2]);
                    split2(As[rb_ + 8][kb + tg + 4], ah[mf][3], al[mf][3]);
                }
                uint32_t bh[4][2], bl[4][2];
                #pragma unroll
                for (int nf = 0; nf < 4; nf++) {
                    int nb = wn * 32 + nf * 8 + g;
                    split2(Bs[nb][kb + tg],     bh[nf][0], bl[nf][0]);
                    split2(Bs[nb][kb + tg + 4], bh[nf][1], bl[nf][1]);
                }
                #pragma unroll
                for (int mf = 0; mf < 2; mf++)
                    #pragma unroll
                    for (int nf = 0; nf < 4; nf++) {
                        mma_tf32(acc[mf][nf], al[mf][0], al[mf][1], al[mf][2], al[mf][3],
                                 bh[nf][0], bh[nf][1]);
                        mma_tf32(acc[mf][nf], ah[mf][0], ah[mf][1], ah[mf][2], ah[mf][3],
                                 bl[nf][0], bl[nf][1]);
                        mma_tf32(acc[mf][nf], ah[mf][0], ah[mf][1], ah[mf][2], ah[mf][3],
                                 bh[nf][0], bh[nf][1]);
                    }
            }
            __syncthreads();
        }
    }

    // ---- write C + attn partials ----
    float pa[2][2] = {}, pd[2][2] = {};
    #pragma unroll
    for (int nf = 0; nf < 4; nf++) {
        int col = col0 + wn * 32 + nf * 8 + 2 * tg;
        float av0 = 0.f, av1 = 0.f, dv0 = 0.f, dv1 = 0.f;
        if (col < N)     { av0 = asrc[col];     dv0 = adst[col]; }
        if (col + 1 < N) { av1 = asrc[col + 1]; dv1 = adst[col + 1]; }
        #pragma unroll
        for (int mf = 0; mf < 2; mf++) {
            #pragma unroll
            for (int half = 0; half < 2; half++) {
                int row = row0 + wm * 32 + mf * 16 + g + half * 8;
                float c0 = acc[mf][nf][half * 2], c1 = acc[mf][nf][half * 2 + 1];
                if (row < M && col < N)
                    *(float2*)&C[(size_t)row * N + col] = make_float2(c0, c1);
                pa[mf][half] += c0 * av0 + c1 * av1;
                pd[mf][half] += c0 * dv0 + c1 * dv1;
            }
        }
    }
    // reduce over tg lanes (same row)
    #pragma unroll
    for (int o = 1; o <= 2; o <<= 1) {
        #pragma unroll
        for (int mf = 0; mf < 2; mf++)
            #pragma unroll
            for (int half = 0; half < 2; half++) {
                pa[mf][half] += __shfl_xor_sync(0xFFFFFFFFu, pa[mf][half], o);
                pd[mf][half] += __shfl_xor_sync(0xFFFFFFFFu, pd[mf][half], o);
            }
    }
    if (tg == 0) {
        #pragma unroll
        for (int mf = 0; mf < 2; mf++)
            #pragma unroll
            for (int half = 0; half < 2; half++) {
                int lr = wm * 32 + mf * 16 + g + half * 8;
                atomicAdd(&s_as[lr], pa[mf][half]);
                atomicAdd(&s_ad[lr], pd[mf][half]);
            }
    }
    __syncthreads();
    if (tid < 128) {
        int row = row0 + tid;
        if (row < M) {
            int head = (heads == 1) ? 0 : (col0 >> 6);
            as_out[row * heads + head] = s_as[tid];
            ad_out[row * heads + head] = s_ad[tid];
        }
    }
}

// ---------------- fused softmax + aggregation, H=4 C=64, BN+ELU epilogue ----------------
__global__ __launch_bounds__(256)
void agg_fused4(const int* __restrict__ rowptr, const int* __restrict__ srcs,
                const float* __restrict__ as_, const float* __restrict__ ad_,
                float* __restrict__ alpha,
                const float* __restrict__ hbuf, const float* __restrict__ bias,
                const float* __restrict__ bng, const float* __restrict__ bnb,
                const float* __restrict__ bnm, const float* __restrict__ bnv,
                float* __restrict__ out) {
    __shared__ float s_al[8][32][4];
    __shared__ int   s_sr[8][32];
    int w = (blockIdx.x * blockDim.x + threadIdx.x) >> 5;
    int lane = threadIdx.x & 31;
    int wi = (threadIdx.x >> 5);
    if (w >= NN) return;
    int d = w;
    float4 add = *(const float4*)&ad_[d * 4];
    int beg = rowptr[d], end = rowptr[d + 1];

    // pass 1: compute scores, store raw e, track max
    float mx0 = -3e38f, mx1 = -3e38f, mx2 = -3e38f, mx3 = -3e38f;
    for (int j = beg + lane; j < end; j += 32) {
        int s = srcs[j];
        float4 av = *(const float4*)&as_[s * 4];
        float e0 = av.x + add.x; e0 = (e0 > 0.f) ? e0 : NEG_SLOPE * e0;
        float e1 = av.y + add.y; e1 = (e1 > 0.f) ? e1 : NEG_SLOPE * e1;
        float e2 = av.z + add.z; e2 = (e2 > 0.f) ? e2 : NEG_SLOPE * e2;
        float e3 = av.w + add.w; e3 = (e3 > 0.f) ? e3 : NEG_SLOPE * e3;
        *(float4*)&alpha[(size_t)j * 4] = make_float4(e0, e1, e2, e3);
        mx0 = fmaxf(mx0, e0); mx1 = fmaxf(mx1, e1);
        mx2 = fmaxf(mx2, e2); mx3 = fmaxf(mx3, e3);
    }
    #pragma unroll
    for (int o = 16; o > 0; o >>= 1) {
        mx0 = fmaxf(mx0, __shfl_xor_sync(0xFFFFFFFFu, mx0, o));
        mx1 = fmaxf(mx1, __shfl_xor_sync(0xFFFFFFFFu, mx1, o));
        mx2 = fmaxf(mx2, __shfl_xor_sync(0xFFFFFFFFu, mx2, o));
        mx3 = fmaxf(mx3, __shfl_xor_sync(0xFFFFFFFFu, mx3, o));
    }

    // pass 2: exp (coalesced read of e) + denominators
    float d0 = 0.f, d1 = 0.f, d2 = 0.f, d3 = 0.f;
    for (int j = beg + lane; j < end; j += 32) {
        float4 ev = *(const float4*)&alpha[(size_t)j * 4];
        float p0 = __expf(ev.x - mx0), p1 = __expf(ev.y - mx1);
        float p2 = __expf(ev.z - mx2), p3 = __expf(ev.w - mx3);
        *(float4*)&alpha[(size_t)j * 4] = make_float4(p0, p1, p2, p3);
        d0 += p0; d1 += p1; d2 += p2; d3 += p3;
    }
    #pragma unroll
    for (int o = 16; o > 0; o >>= 1) {
        d0 += __shfl_xor_sync(0xFFFFFFFFu, d0, o);
        d1 += __shfl_xor_sync(0xFFFFFFFFu, d1, o);
        d2 += __shfl_xor_sync(0xFFFFFFFFu, d2, o);
        d3 += __shfl_xor_sync(0xFFFFFFFFu, d3, o);
    }
    float4 inv = make_float4(1.f / (d0 + 1e-16f), 1.f / (d1 + 1e-16f),
                             1.f / (d2 + 1e-16f), 1.f / (d3 + 1e-16f));

    int h0 = lane >> 4;
    int h1 = 2 + (lane >> 4);

    float4 acc0 = make_float4(0.f, 0.f, 0.f, 0.f);
    float4 acc1 = make_float4(0.f, 0.f, 0.f, 0.f);

    // pass 3: chunk-staged weighted gather
    for (int jb = beg; jb < end; jb += 32) {
        int j = jb + lane;
        int s = 0;
        float4 p = make_float4(0.f, 0.f, 0.f, 0.f);
        if (j < end) {
            s = srcs[j];
            p = *(const float4*)&alpha[(size_t)j * 4];
        }
        p.x *= inv.x; p.y *= inv.y; p.z *= inv.z; p.w *= inv.w;
        __syncwarp();
        s_sr[wi][lane] = s;
        *(float4*)&s_al[wi][lane][0] = p;
        __syncwarp();
        int n = min(32, end - jb);
        #pragma unroll 4
        for (int t = 0; t < n; t++) {
            int ss = s_sr[wi][t];
            float a0 = s_al[wi][t][h0];
            float a1 = s_al[wi][t][h1];
            const float4* hp = (const float4*)(hbuf + (size_t)ss * FD);
            float4 v0 = hp[lane];
            float4 v1 = hp[32 + lane];
            acc0.x += v0.x * a0; acc0.y += v0.y * a0;
            acc0.z += v0.z * a0; acc0.w += v0.w * a0;
            acc1.x += v1.x * a1; acc1.y += v1.y * a1;
            acc1.z += v1.z * a1; acc1.w += v1.w * a1;
        }
    }

    int f0 = lane * 4, f1 = 128 + lane * 4;
    #pragma unroll
    for (int c = 0; c < 2; c++) {
        int f = c ? f1 : f0;
        float4 acc = c ? acc1 : acc0;
        float4 bv = *(const float4*)&bias[f];
        float4 gv = *(const float4*)&bng[f];
        float4 betav = *(const float4*)&bnb[f];
        float4 mv = *(const float4*)&bnm[f];
        float4 vv = *(const float4*)&bnv[f];
        float4 r;
        r.x = gv.x * (acc.x + bv.x - mv.x) * rsqrtf(vv.x + BN_EPS) + betav.x;
        r.y = gv.y * (acc.y + bv.y - mv.y) * rsqrtf(vv.y + BN_EPS) + betav.y;
        r.z = gv.z * (acc.z + bv.z - mv.z) * rsqrtf(vv.z + BN_EPS) + betav.z;
        r.w = gv.w * (acc.w + bv.w - mv.w) * rsqrtf(vv.w + BN_EPS) + betav.w;
        r.x = (r.x > 0.f) ? r.x : (expf(r.x) - 1.f);
        r.y = (r.y > 0.f) ? r.y : (expf(r.y) - 1.f);
        r.z = (r.z > 0.f) ? r.z : (expf(r.z) - 1.f);
        r.w = (r.w > 0.f) ? r.w : (expf(r.w) - 1.f);
        *(float4*)&out[(size_t)d * FD + f] = r;
    }
}

// ---------------- fused softmax + aggregation, H=1 C=40 ----------------
__global__ __launch_bounds__(256)
void agg_fused1(const int* __restrict__ rowptr, const int* __restrict__ srcs,
                const float* __restrict__ as_, const float* __restrict__ ad_,
                float* __restrict__ alpha,
                const float* __restrict__ hbuf, const float* __restrict__ bias,
                float* __restrict__ out) {
    __shared__ float s_al[8][32];
    __shared__ int   s_sr[8][32];
    int w = (blockIdx.x * blockDim.x + threadIdx.x) >> 5;
    int lane = threadIdx.x & 31;
    int wi = (threadIdx.x >> 5);
    if (w >= NN) return;
    int d = w;
    float adl = ad_[d];
    int beg = rowptr[d], end = rowptr[d + 1];

    float mx = -3e38f;
    for (int j = beg + lane; j < end; j += 32) {
        float e = as_[srcs[j]] + adl;
        e = (e > 0.f) ? e : NEG_SLOPE * e;
        alpha[j] = e;
        mx = fmaxf(mx, e);
    }
    #pragma unroll
    for (int o = 16; o > 0; o >>= 1)
        mx = fmaxf(mx, __shfl_xor_sync(0xFFFFFFFFu, mx, o));

    float den = 0.f;
    for (int j = beg + lane; j < end; j += 32) {
        float p = __expf(alpha[j] - mx);
        alpha[j] = p;
        den += p;
    }
    #pragma unroll
    for (int o = 16; o > 0; o >>= 1)
        den += __shfl_xor_sync(0xFFFFFFFFu, den, o);
    float invden = 1.0f / (den + 1e-16f);

    float acc0 = 0.f, acc1 = 0.f;
    for (int jb = beg; jb < end; jb += 32) {
        int j = jb + lane;
        int s = 0; float p = 0.f;
        if (j < end) { s = srcs[j]; p = alpha[j]; }
        __syncwarp();
        s_sr[wi][lane] = s;
        s_al[wi][lane] = p * invden;
        __syncwarp();
        int n = min(32, end - jb);
        #pragma unroll 4
        for (int t = 0; t < n; t++) {
            int ss = s_sr[wi][t];
            float a = s_al[wi][t];
            acc0 += hbuf[(size_t)ss * OUTD + lane] * a;
            if (lane < OUTD - 32)
                acc1 += hbuf[(size_t)ss * OUTD + 32 + lane] * a;
        }
    }
    out[(size_t)d * OUTD + lane] = acc0 + bias[lane];
    if (lane < OUTD - 32)
        out[(size_t)d * OUTD + 32 + lane] = acc1 + bias[32 + lane];
}

// ================= launch =================
extern "C" void kernel_launch(void* const* d_in, const int* in_sizes, int n_in,
                              void* d_out, int out_size) {
    const float* x       = (const float*)d_in[0];
    const int*   eidx    = (const int*)d_in[1];
    const float* W0      = (const float*)d_in[2];
    const float* a_src0  = (const float*)d_in[3];
    const float* a_dst0  = (const float*)d_in[4];
    const float* b0      = (const float*)d_in[5];
    const float* bn0_g   = (const float*)d_in[6];
    const float* bn0_b   = (const float*)d_in[7];
    const float* bn0_m   = (const float*)d_in[8];
    const float* bn0_v   = (const float*)d_in[9];
    const float* W1      = (const float*)d_in[10];
    const float* a_src1  = (const float*)d_in[11];
    const float* a_dst1  = (const float*)d_in[12];
    const float* b1      = (const float*)d_in[13];
    const float* bn1_g   = (const float*)d_in[14];
    const float* bn1_b   = (const float*)d_in[15];
    const float* bn1_m   = (const float*)d_in[16];
    const float* bn1_v   = (const float*)d_in[17];
    const float* W2      = (const float*)d_in[18];
    const float* a_src2  = (const float*)d_in[19];
    const float* a_dst2  = (const float*)d_in[20];
    const float* b2      = (const float*)d_in[21];
    float* out = (float*)d_out;

    int E = in_sizes[1] / 2;
    const int* src = eidx;
    const int* dst = eidx + E;

    float *h_buf, *x1_buf, *as_buf, *ad_buf, *al_buf;
    int *deg, *cur, *rowptr, *srcs;
    cudaGetSymbolAddress((void**)&h_buf, g_h);
    cudaGetSymbolAddress((void**)&x1_buf, g_x1);
    cudaGetSymbolAddress((void**)&as_buf, g_as);
    cudaGetSymbolAddress((void**)&ad_buf, g_ad);
    cudaGetSymbolAddress((void**)&al_buf, g_alpha);
    cudaGetSymbolAddress((void**)&deg, g_deg);
    cudaGetSymbolAddress((void**)&cur, g_cur);
    cudaGetSymbolAddress((void**)&rowptr, g_rowptr);
    cudaGetSymbolAddress((void**)&srcs, g_srcs);

    // ---- CSR by dst ----
    zero_counts<<<cdiv(NN, 256), 256>>>(deg, cur, NN);
    csr_count<<<cdiv(E, 256), 256>>>(dst, E, deg);
    csr_scan<<<1, 1024>>>(deg, rowptr, NN, E);
    csr_fill<<<cdiv(E, 256), 256>>>(src, dst, E, rowptr, cur, srcs);

    // ---- layer 0 ----
    gemm_tf32<<<dim3(cdiv(FD, 64), cdiv(NN, 128)), 256>>>(
        x, W0, h_buf, NN, FD, 256, a_src0, a_dst0, as_buf, ad_buf, HEADS);
    agg_fused4<<<cdiv(NN * 32, 256), 256>>>(rowptr, srcs, as_buf, ad_buf, al_buf, h_buf,
                                            b0, bn0_g, bn0_b, bn0_m, bn0_v, x1_buf);

    // ---- layer 1 ----
    gemm_tf32<<<dim3(cdiv(FD, 64), cdiv(NN, 128)), 256>>>(
        x1_buf, W1, h_buf, NN, FD, FD, a_src1, a_dst1, as_buf, ad_buf, HEADS);
    agg_fused4<<<cdiv(NN * 32, 256), 256>>>(rowptr, srcs, as_buf, ad_buf, al_buf, h_buf,
                                            b1, bn1_g, bn1_b, bn1_m, bn1_v, x1_buf);

    // ---- layer 2 (heads=1, ch=40) ----
    gemm_tf32<<<dim3(cdiv(OUTD, 64), cdiv(NN, 128)), 256>>>(
        x1_buf, W2, h_buf, NN, OUTD, FD, a_src2, a_dst2, as_buf, ad_buf, 1);
    agg_fused1<<<cdiv(NN * 32, 256), 256>>>(rowptr, srcs, as_buf, ad_buf, al_buf,
                                            h_buf, b2, out);
}

// round 7
// speedup vs baseline: 4.3989x; 1.0329x over previous
#include <cuda_runtime.h>
#include <math.h>
#include <stdint.h>

#define NN 50000
#define EE 850000
#define FD 256      // HEADS*HID
#define HEADS 4
#define CH 64
#define OUTD 40
#define BN_EPS 1e-5f
#define NEG_SLOPE 0.2f

// ---------------- scratch (static, allocation-free) ----------------
__device__ __align__(256) float g_h[NN * FD];
__device__ __align__(256) float g_x1[NN * FD];
__device__ __align__(256) float g_as[NN * HEADS];
__device__ __align__(256) float g_ad[NN * HEADS];
__device__ __align__(256) float g_alpha[(size_t)EE * HEADS];
__device__ int   g_deg[NN];
__device__ int   g_cur[NN];
__device__ int   g_rowptr[NN + 1];
__device__ int   g_srcs[EE];

static inline int cdiv(int a, int b) { return (a + b - 1) / b; }

// ---------------- tf32 split helpers ----------------
__device__ __forceinline__ void split2(float x, uint32_t& hi, uint32_t& lo) {
    hi = __float_as_uint(x) & 0xFFFFE000u;
    lo = __float_as_uint(x - __uint_as_float(hi));
}

__device__ __forceinline__ void mma_tf32(float c[4], uint32_t a0, uint32_t a1,
                                         uint32_t a2, uint32_t a3,
                                         uint32_t b0, uint32_t b1) {
    asm volatile(
        "mma.sync.aligned.m16n8k8.row.col.f32.tf32.tf32.f32 "
        "{%0,%1,%2,%3}, {%4,%5,%6,%7}, {%8,%9}, {%0,%1,%2,%3};"
        : "+f"(c[0]), "+f"(c[1]), "+f"(c[2]), "+f"(c[3])
        : "r"(a0), "r"(a1), "r"(a2), "r"(a3), "r"(b0), "r"(b1));
}

// ================= CSR build =================
__global__ void zero_counts(int* __restrict__ deg, int* __restrict__ cur, int n) {
    for (int i = blockIdx.x * blockDim.x + threadIdx.x; i < n;
         i += gridDim.x * blockDim.x) { deg[i] = 0; cur[i] = 0; }
}

__global__ void csr_count(const int* __restrict__ dst, int E, int* __restrict__ deg) {
    for (int i = blockIdx.x * blockDim.x + threadIdx.x; i < E;
         i += gridDim.x * blockDim.x)
        atomicAdd(&deg[dst[i]], 1);
}

__global__ void csr_scan(const int* __restrict__ deg, int* __restrict__ rowptr, int n, int E) {
    __shared__ int part[1024];
    int t = threadIdx.x;
    int chunk = (n + 1023) / 1024;
    int start = t * chunk;
    int stop = min(start + chunk, n);
    int sum = 0;
    for (int i = start; i < stop; i++) sum += deg[i];
    part[t] = sum;
    __syncthreads();
    for (int o = 1; o < 1024; o <<= 1) {
        int v = (t >= o) ? part[t - o] : 0;
        __syncthreads();
        part[t] += v;
        __syncthreads();
    }
    int run = part[t] - sum;
    for (int i = start; i < stop; i++) { rowptr[i] = run; run += deg[i]; }
    if (t == 0) rowptr[n] = E;
}

__global__ void csr_fill(const int* __restrict__ src, const int* __restrict__ dst, int E,
                         const int* __restrict__ rowptr, int* __restrict__ cur,
                         int* __restrict__ srcs) {
    for (int i = blockIdx.x * blockDim.x + threadIdx.x; i < E;
         i += gridDim.x * blockDim.x) {
        int d = dst[i];
        int pos = rowptr[d] + atomicAdd(&cur[d], 1);
        srcs[pos] = src[i];
    }
}

// ================= GEMM tf32 3-split, fused attn-score epilogue =================
#define BK_PAD 36
__global__ __launch_bounds__(256, 2)
void gemm_tf32(const float* __restrict__ A, const float* __restrict__ B,
               float* __restrict__ C, int M, int N, int K,
               const float* __restrict__ asrc, const float* __restrict__ adst,
               float* __restrict__ as_out, float* __restrict__ ad_out, int heads) {
    __shared__ float As[128][BK_PAD];
    __shared__ float Bs[64][BK_PAD];
    __shared__ float s_as[128], s_ad[128];
    int tid = threadIdx.x;
    int lane = tid & 31;
    int warp = tid >> 5;
    int wm = warp & 3;
    int wn = warp >> 2;
    int row0 = blockIdx.y * 128;
    int col0 = blockIdx.x * 64;
    int g = lane >> 2;
    int tg = lane & 3;

    if (tid < 128) { s_as[tid] = 0.0f; s_ad[tid] = 0.0f; }

    float acc[2][4][4];
    #pragma unroll
    for (int i = 0; i < 2; i++)
        #pragma unroll
        for (int j = 0; j < 4; j++)
            #pragma unroll
            for (int k = 0; k < 4; k++) acc[i][j][k] = 0.0f;

    bool fullN = (col0 + 64 <= N);

    if (fullN) {
        float4 ra[4], rb[2];
        #pragma unroll
        for (int l = 0; l < 4; l++) {
            int i = tid + l * 256;
            int r = i >> 3, c4 = i & 7;
            ra[l] = make_float4(0.f, 0.f, 0.f, 0.f);
            if (row0 + r < M)
                ra[l] = *(const float4*)&A[(size_t)(row0 + r) * K + c4 * 4];
        }
        #pragma unroll
        for (int l = 0; l < 2; l++) {
            int i = tid + l * 256;
            int kr = i >> 4, c4 = i & 15;
            rb[l] = *(const float4*)&B[(size_t)kr * N + col0 + c4 * 4];
        }

        for (int kk = 0; kk < K; kk += 32) {
            #pragma unroll
            for (int l = 0; l < 4; l++) {
                int i = tid + l * 256;
                int r = i >> 3, c4 = i & 7;
                *(float4*)&As[r][c4 * 4] = ra[l];
            }
            #pragma unroll
            for (int l = 0; l < 2; l++) {
                int i = tid + l * 256;
                int kr = i >> 4, c4 = i & 15;
                Bs[c4 * 4 + 0][kr] = rb[l].x;
                Bs[c4 * 4 + 1][kr] = rb[l].y;
                Bs[c4 * 4 + 2][kr] = rb[l].z;
                Bs[c4 * 4 + 3][kr] = rb[l].w;
            }
            __syncthreads();

            if (kk + 32 < K) {
                #pragma unroll
                for (int l = 0; l < 4; l++) {
                    int i = tid + l * 256;
                    int r = i >> 3, c4 = i & 7;
                    ra[l] = make_float4(0.f, 0.f, 0.f, 0.f);
                    if (row0 + r < M)
                        ra[l] = *(const float4*)&A[(size_t)(row0 + r) * K + kk + 32 + c4 * 4];
                }
                #pragma unroll
                for (int l = 0; l < 2; l++) {
                    int i = tid + l * 256;
                    int kr = i >> 4, c4 = i & 15;
                    rb[l] = *(const float4*)&B[(size_t)(kk + 32 + kr) * N + col0 + c4 * 4];
                }
            }

            #pragma unroll
            for (int ks = 0; ks < 4; ks++) {
                int kb = ks * 8;
                uint32_t ah[2][4], al[2][4];
                #pragma unroll
                for (int mf = 0; mf < 2; mf++) {
                    int rb_ = wm * 32 + mf * 16 + g;
                    split2(As[rb_][kb + tg],         ah[mf][0], al[mf][0]);
                    split2(As[rb_ + 8][kb + tg],     ah[mf][1], al[mf][1]);
                    split2(As[rb_][kb + tg + 4],     ah[mf][2], al[mf][2]);
                    split2(As[rb_ + 8][kb + tg + 4], ah[mf][3], al[mf][3]);
                }
                uint32_t bh[4][2], bl[4][2];
                #pragma unroll
                for (int nf = 0; nf < 4; nf++) {
                    int nb = wn * 32 + nf * 8 + g;
                    split2(Bs[nb][kb + tg],     bh[nf][0], bl[nf][0]);
                    split2(Bs[nb][kb + tg + 4], bh[nf][1], bl[nf][1]);
                }
                #pragma unroll
                for (int mf = 0; mf < 2; mf++)
                    #pragma unroll
                    for (int nf = 0; nf < 4; nf++) {
                        mma_tf32(acc[mf][nf], al[mf][0], al[mf][1], al[mf][2], al[mf][3],
                                 bh[nf][0], bh[nf][1]);
                        mma_tf32(acc[mf][nf], ah[mf][0], ah[mf][1], ah[mf][2], ah[mf][3],
                                 bl[nf][0], bl[nf][1]);
                        mma_tf32(acc[mf][nf], ah[mf][0], ah[mf][1], ah[mf][2], ah[mf][3],
                                 bh[nf][0], bh[nf][1]);
                    }
            }
            __syncthreads();
        }
    } else {
        for (int kk = 0; kk < K; kk += 32) {
            #pragma unroll
            for (int l = 0; l < 4; l++) {
                int i = tid + l * 256;
                int r = i >> 3, c4 = i & 7;
                float4 v = make_float4(0.f, 0.f, 0.f, 0.f);
                if (row0 + r < M)
                    v = *(const float4*)&A[(size_t)(row0 + r) * K + kk + c4 * 4];
                *(float4*)&As[r][c4 * 4] = v;
            }
            #pragma unroll
            for (int l = 0; l < 8; l++) {
                int i = tid + l * 256;
                int kr = i >> 6, c = i & 63;
                float v = 0.0f;
                if (col0 + c < N) v = B[(size_t)(kk + kr) * N + col0 + c];
                Bs[c][kr] = v;
            }
            __syncthreads();
            #pragma unroll
            for (int ks = 0; ks < 4; ks++) {
                int kb = ks * 8;
                uint32_t ah[2][4], al[2][4];
                #pragma unroll
                for (int mf = 0; mf < 2; mf++) {
                    int rb_ = wm * 32 + mf * 16 + g;
                    split2(As[rb_][kb + tg],         ah[mf][0], al[mf][0]);
                    split2(As[rb_ + 8][kb + tg],     ah[mf][1], al[mf][1]);
                    split2(As[rb_][kb + tg + 4],     ah[mf][2], al[mf][2]);
                    split2(As[rb_ + 8][kb + tg + 4], ah[mf][3], al[mf][3]);
                }
                uint32_t bh[4][2], bl[4][2];
                #pragma unroll
                for (int nf = 0; nf < 4; nf++) {
                    int nb = wn * 32 + nf * 8 + g;
                    split2(Bs[nb][kb + tg],     bh[nf][0], bl[nf][0]);
                    split2(Bs[nb][kb + tg + 4], bh[nf][1], bl[nf][1]);
                }
                #pragma unroll
                for (int mf = 0; mf < 2; mf++)
                    #pragma unroll
                    for (int nf = 0; nf < 4; nf++) {
                        mma_tf32(acc[mf][nf], al[mf][0], al[mf][1], al[mf][2], al[mf][3],
                                 bh[nf][0], bh[nf][1]);
                        mma_tf32(acc[mf][nf], ah[mf][0], ah[mf][1], ah[mf][2], ah[mf][3],
                                 bl[nf][0], bl[nf][1]);
                        mma_tf32(acc[mf][nf], ah[mf][0], ah[mf][1], ah[mf][2], ah[mf][3],
                                 bh[nf][0], bh[nf][1]);
                    }
            }
            __syncthreads();
        }
    }

    // ---- write C + attn partials ----
    float pa[2][2] = {}, pd[2][2] = {};
    #pragma unroll
    for (int nf = 0; nf < 4; nf++) {
        int col = col0 + wn * 32 + nf * 8 + 2 * tg;
        float av0 = 0.f, av1 = 0.f, dv0 = 0.f, dv1 = 0.f;
        if (col < N)     { av0 = asrc[col];     dv0 = adst[col]; }
        if (col + 1 < N) { av1 = asrc[col + 1]; dv1 = adst[col + 1]; }
        #pragma unroll
        for (int mf = 0; mf < 2; mf++) {
            #pragma unroll
            for (int half = 0; half < 2; half++) {
                int row = row0 + wm * 32 + mf * 16 + g + half * 8;
                float c0 = acc[mf][nf][half * 2], c1 = acc[mf][nf][half * 2 + 1];
                if (row < M && col < N)
                    *(float2*)&C[(size_t)row * N + col] = make_float2(c0, c1);
                pa[mf][half] += c0 * av0 + c1 * av1;
                pd[mf][half] += c0 * dv0 + c1 * dv1;
            }
        }
    }
    #pragma unroll
    for (int o = 1; o <= 2; o <<= 1) {
        #pragma unroll
        for (int mf = 0; mf < 2; mf++)
            #pragma unroll
            for (int half = 0; half < 2; half++) {
                pa[mf][half] += __shfl_xor_sync(0xFFFFFFFFu, pa[mf][half], o);
                pd[mf][half] += __shfl_xor_sync(0xFFFFFFFFu, pd[mf][half], o);
            }
    }
    if (tg == 0) {
        #pragma unroll
        for (int mf = 0; mf < 2; mf++)
            #pragma unroll
            for (int half = 0; half < 2; half++) {
                int lr = wm * 32 + mf * 16 + g + half * 8;
                atomicAdd(&s_as[lr], pa[mf][half]);
                atomicAdd(&s_ad[lr], pd[mf][half]);
            }
    }
    __syncthreads();
    if (tid < 128) {
        int row = row0 + tid;
        if (row < M) {
            int head = (heads == 1) ? 0 : (col0 >> 6);
            as_out[row * heads + head] = s_as[tid];
            ad_out[row * heads + head] = s_ad[tid];
        }
    }
}

// ---------------- fused softmax + aggregation, H=4 C=64, BN+ELU epilogue ----------------
// No-max softmax: alpha = exp(e)/sum(exp(e)) (identical to exp(e-m)/sum since m cancels).
__global__ __launch_bounds__(256)
void agg_fused4(const int* __restrict__ rowptr, const int* __restrict__ srcs,
                const float* __restrict__ as_, const float* __restrict__ ad_,
                float* __restrict__ alpha,
                const float* __restrict__ hbuf, const float* __restrict__ bias,
                const float* __restrict__ bng, const float* __restrict__ bnb,
                const float* __restrict__ bnm, const float* __restrict__ bnv,
                float* __restrict__ out) {
    __shared__ float s_al[8][32][4];
    __shared__ int   s_sr[8][32];
    int w = (blockIdx.x * blockDim.x + threadIdx.x) >> 5;
    int lane = threadIdx.x & 31;
    int wi = (threadIdx.x >> 5);
    if (w >= NN) return;
    int d = w;
    float4 add = *(const float4*)&ad_[d * 4];
    int beg = rowptr[d], end = rowptr[d + 1];

    // single gather pass: p = exp(lrelu(as[src]+ad[dst])), accumulate denom
    float d0 = 0.f, d1 = 0.f, d2 = 0.f, d3 = 0.f;
    for (int j = beg + lane; j < end; j += 32) {
        int s = srcs[j];
        float4 av = *(const float4*)&as_[s * 4];
        float e0 = av.x + add.x; e0 = (e0 > 0.f) ? e0 : NEG_SLOPE * e0;
        float e1 = av.y + add.y; e1 = (e1 > 0.f) ? e1 : NEG_SLOPE * e1;
        float e2 = av.z + add.z; e2 = (e2 > 0.f) ? e2 : NEG_SLOPE * e2;
        float e3 = av.w + add.w; e3 = (e3 > 0.f) ? e3 : NEG_SLOPE * e3;
        float p0 = __expf(e0), p1 = __expf(e1);
        float p2 = __expf(e2), p3 = __expf(e3);
        *(float4*)&alpha[(size_t)j * 4] = make_float4(p0, p1, p2, p3);
        d0 += p0; d1 += p1; d2 += p2; d3 += p3;
    }
    #pragma unroll
    for (int o = 16; o > 0; o >>= 1) {
        d0 += __shfl_xor_sync(0xFFFFFFFFu, d0, o);
        d1 += __shfl_xor_sync(0xFFFFFFFFu, d1, o);
        d2 += __shfl_xor_sync(0xFFFFFFFFu, d2, o);
        d3 += __shfl_xor_sync(0xFFFFFFFFu, d3, o);
    }
    float4 inv = make_float4(1.f / (d0 + 1e-16f), 1.f / (d1 + 1e-16f),
                             1.f / (d2 + 1e-16f), 1.f / (d3 + 1e-16f));

    int h0 = lane >> 4;
    int h1 = 2 + (lane >> 4);

    float4 acc0 = make_float4(0.f, 0.f, 0.f, 0.f);
    float4 acc1 = make_float4(0.f, 0.f, 0.f, 0.f);

    // chunk-staged weighted gather (lanes over features)
    for (int jb = beg; jb < end; jb += 32) {
        int j = jb + lane;
        int s = 0;
        float4 p = make_float4(0.f, 0.f, 0.f, 0.f);
        if (j < end) {
            s = srcs[j];
            p = *(const float4*)&alpha[(size_t)j * 4];
        }
        p.x *= inv.x; p.y *= inv.y; p.z *= inv.z; p.w *= inv.w;
        __syncwarp();
        s_sr[wi][lane] = s;
        *(float4*)&s_al[wi][lane][0] = p;
        __syncwarp();
        int n = min(32, end - jb);
        #pragma unroll 4
        for (int t = 0; t < n; t++) {
            int ss = s_sr[wi][t];
            float a0 = s_al[wi][t][h0];
            float a1 = s_al[wi][t][h1];
            const float4* hp = (const float4*)(hbuf + (size_t)ss * FD);
            float4 v0 = hp[lane];
            float4 v1 = hp[32 + lane];
            acc0.x += v0.x * a0; acc0.y += v0.y * a0;
            acc0.z += v0.z * a0; acc0.w += v0.w * a0;
            acc1.x += v1.x * a1; acc1.y += v1.y * a1;
            acc1.z += v1.z * a1; acc1.w += v1.w * a1;
        }
    }

    int f0 = lane * 4, f1 = 128 + lane * 4;
    #pragma unroll
    for (int c = 0; c < 2; c++) {
        int f = c ? f1 : f0;
        float4 acc = c ? acc1 : acc0;
        float4 bv = *(const float4*)&bias[f];
        float4 gv = *(const float4*)&bng[f];
        float4 betav = *(const float4*)&bnb[f];
        float4 mv = *(const float4*)&bnm[f];
        float4 vv = *(const float4*)&bnv[f];
        float4 r;
        r.x = gv.x * (acc.x + bv.x - mv.x) * rsqrtf(vv.x + BN_EPS) + betav.x;
        r.y = gv.y * (acc.y + bv.y - mv.y) * rsqrtf(vv.y + BN_EPS) + betav.y;
        r.z = gv.z * (acc.z + bv.z - mv.z) * rsqrtf(vv.z + BN_EPS) + betav.z;
        r.w = gv.w * (acc.w + bv.w - mv.w) * rsqrtf(vv.w + BN_EPS) + betav.w;
        r.x = (r.x > 0.f) ? r.x : (expf(r.x) - 1.f);
        r.y = (r.y > 0.f) ? r.y : (expf(r.y) - 1.f);
        r.z = (r.z > 0.f) ? r.z : (expf(r.z) - 1.f);
        r.w = (r.w > 0.f) ? r.w : (expf(r.w) - 1.f);
        *(float4*)&out[(size_t)d * FD + f] = r;
    }
}

// ---------------- fused softmax + aggregation, H=1 C=40 ----------------
__global__ __launch_bounds__(256)
void agg_fused1(const int* __restrict__ rowptr, const int* __restrict__ srcs,
                const float* __restrict__ as_, const float* __restrict__ ad_,
                float* __restrict__ alpha,
                const float* __restrict__ hbuf, const float* __restrict__ bias,
                float* __restrict__ out) {
    __shared__ float s_al[8][32];
    __shared__ int   s_sr[8][32];
    int w = (blockIdx.x * blockDim.x + threadIdx.x) >> 5;
    int lane = threadIdx.x & 31;
    int wi = (threadIdx.x >> 5);
    if (w >= NN) return;
    int d = w;
    float adl = ad_[d];
    int beg = rowptr[d], end = rowptr[d + 1];

    float den = 0.f;
    for (int j = beg + lane; j < end; j += 32) {
        float e = as_[srcs[j]] + adl;
        e = (e > 0.f) ? e : NEG_SLOPE * e;
        float p = __expf(e);
        alpha[j] = p;
        den += p;
    }
    #pragma unroll
    for (int o = 16; o > 0; o >>= 1)
        den += __shfl_xor_sync(0xFFFFFFFFu, den, o);
    float invden = 1.0f / (den + 1e-16f);

    float acc0 = 0.f, acc1 = 0.f;
    for (int jb = beg; jb < end; jb += 32) {
        int j = jb + lane;
        int s = 0; float p = 0.f;
        if (j < end) { s = srcs[j]; p = alpha[j]; }
        __syncwarp();
        s_sr[wi][lane] = s;
        s_al[wi][lane] = p * invden;
        __syncwarp();
        int n = min(32, end - jb);
        #pragma unroll 4
        for (int t = 0; t < n; t++) {
            int ss = s_sr[wi][t];
            float a = s_al[wi][t];
            acc0 += hbuf[(size_t)ss * OUTD + lane] * a;
            if (lane < OUTD - 32)
                acc1 += hbuf[(size_t)ss * OUTD + 32 + lane] * a;
        }
    }
    out[(size_t)d * OUTD + lane] = acc0 + bias[lane];
    if (lane < OUTD - 32)
        out[(size_t)d * OUTD + 32 + lane] = acc1 + bias[32 + lane];
}

// ================= launch =================
extern "C" void kernel_launch(void* const* d_in, const int* in_sizes, int n_in,
                              void* d_out, int out_size) {
    const float* x       = (const float*)d_in[0];
    const int*   eidx    = (const int*)d_in[1];
    const float* W0      = (const float*)d_in[2];
    const float* a_src0  = (const float*)d_in[3];
    const float* a_dst0  = (const float*)d_in[4];
    const float* b0      = (const float*)d_in[5];
    const float* bn0_g   = (const float*)d_in[6];
    const float* bn0_b   = (const float*)d_in[7];
    const float* bn0_m   = (const float*)d_in[8];
    const float* bn0_v   = (const float*)d_in[9];
    const float* W1      = (const float*)d_in[10];
    const float* a_src1  = (const float*)d_in[11];
    const float* a_dst1  = (const float*)d_in[12];
    const float* b1      = (const float*)d_in[13];
    const float* bn1_g   = (const float*)d_in[14];
    const float* bn1_b   = (const float*)d_in[15];
    const float* bn1_m   = (const float*)d_in[16];
    const float* bn1_v   = (const float*)d_in[17];
    const float* W2      = (const float*)d_in[18];
    const float* a_src2  = (const float*)d_in[19];
    const float* a_dst2  = (const float*)d_in[20];
    const float* b2      = (const float*)d_in[21];
    float* out = (float*)d_out;

    int E = in_sizes[1] / 2;
    const int* src = eidx;
    const int* dst = eidx + E;

    float *h_buf, *x1_buf, *as_buf, *ad_buf, *al_buf;
    int *deg, *cur, *rowptr, *srcs;
    cudaGetSymbolAddress((void**)&h_buf, g_h);
    cudaGetSymbolAddress((void**)&x1_buf, g_x1);
    cudaGetSymbolAddress((void**)&as_buf, g_as);
    cudaGetSymbolAddress((void**)&ad_buf, g_ad);
    cudaGetSymbolAddress((void**)&al_buf, g_alpha);
    cudaGetSymbolAddress((void**)&deg, g_deg);
    cudaGetSymbolAddress((void**)&cur, g_cur);
    cudaGetSymbolAddress((void**)&rowptr, g_rowptr);
    cudaGetSymbolAddress((void**)&srcs, g_srcs);

    // side stream + events for CSR || GEMM0 overlap (host objects only; created once)
    static cudaStream_t s2 = nullptr;
    static cudaEvent_t ev_fork = nullptr, ev_join = nullptr;
    if (s2 == nullptr) {
        cudaStreamCreateWithFlags(&s2, cudaStreamNonBlocking);
        cudaEventCreateWithFlags(&ev_fork, cudaEventDisableTiming);
        cudaEventCreateWithFlags(&ev_join, cudaEventDisableTiming);
    }

    // ---- fork: CSR build on s2, concurrent with layer-0 GEMM on main stream ----
    cudaEventRecord(ev_fork, 0);
    cudaStreamWaitEvent(s2, ev_fork, 0);
    zero_counts<<<cdiv(NN, 256), 256, 0, s2>>>(deg, cur, NN);
    csr_count<<<cdiv(E, 256), 256, 0, s2>>>(dst, E, deg);
    csr_scan<<<1, 1024, 0, s2>>>(deg, rowptr, NN, E);
    csr_fill<<<cdiv(E, 256), 256, 0, s2>>>(src, dst, E, rowptr, cur, srcs);
    cudaEventRecord(ev_join, s2);

    // ---- layer 0 GEMM (independent of CSR) ----
    gemm_tf32<<<dim3(cdiv(FD, 64), cdiv(NN, 128)), 256>>>(
        x, W0, h_buf, NN, FD, 256, a_src0, a_dst0, as_buf, ad_buf, HEADS);

    // join: aggregation needs CSR
    cudaStreamWaitEvent(0, ev_join, 0);
    agg_fused4<<<cdiv(NN * 32, 256), 256>>>(rowptr, srcs, as_buf, ad_buf, al_buf, h_buf,
                                            b0, bn0_g, bn0_b, bn0_m, bn0_v, x1_buf);

    // ---- layer 1 ----
    gemm_tf32<<<dim3(cdiv(FD, 64), cdiv(NN, 128)), 256>>>(
        x1_buf, W1, h_buf, NN, FD, FD, a_src1, a_dst1, as_buf, ad_buf, HEADS);
    agg_fused4<<<cdiv(NN * 32, 256), 256>>>(rowptr, srcs, as_buf, ad_buf, al_buf, h_buf,
                                            b1, bn1_g, bn1_b, bn1_m, bn1_v, x1_buf);

    // ---- layer 2 (heads=1, ch=40) ----
    gemm_tf32<<<dim3(cdiv(OUTD, 64), cdiv(NN, 128)), 256>>>(
        x1_buf, W2, h_buf, NN, OUTD, FD, a_src2, a_dst2, as_buf, ad_buf, 1);
    agg_fused1<<<cdiv(NN * 32, 256), 256>>>(rowptr, srcs, as_buf, ad_buf, al_buf,
                                            h_buf, b2, out);
}

// round 8
// speedup vs baseline: 5.0485x; 1.1477x over previous
#include <cuda_runtime.h>
#include <math.h>
#include <stdint.h>

#define NN 50000
#define EE 850000
#define FD 256      // HEADS*HID
#define HEADS 4
#define CH 64
#define OUTD 40
#define BN_EPS 1e-5f
#define NEG_SLOPE 0.2f

// ---------------- scratch (static, allocation-free) ----------------
__device__ __align__(256) float g_h[NN * FD];
__device__ __align__(256) float g_x1[NN * FD];
__device__ __align__(256) float g_as[NN * HEADS];
__device__ __align__(256) float g_ad[NN * HEADS];
__device__ __align__(256) float g_alpha[(size_t)EE * HEADS];
__device__ int   g_deg[NN];
__device__ int   g_cur[NN];
__device__ int   g_rowptr[NN + 1];
__device__ int   g_srcs[EE];

static inline int cdiv(int a, int b) { return (a + b - 1) / b; }

// ---------------- bf16 split helpers ----------------
// pack (x0 -> low half, x1 -> high half) as bf16x2, round-to-nearest
__device__ __forceinline__ uint32_t cvt2_bf16(float x1, float x0) {
    uint32_t r;
    asm("cvt.rn.bf16x2.f32 %0, %1, %2;" : "=r"(r) : "f"(x1), "f"(x0));
    return r;
}
// split a k-pair (x0 = even k, x1 = odd k) into hi/lo bf16x2
__device__ __forceinline__ void split_pair(float x0, float x1, uint32_t& h, uint32_t& l) {
    h = cvt2_bf16(x1, x0);
    float h0 = __uint_as_float(h << 16);
    float h1 = __uint_as_float(h & 0xFFFF0000u);
    l = cvt2_bf16(x1 - h1, x0 - h0);
}
// single-float split to two bf16 (u16)
__device__ __forceinline__ void split_one(float x, uint16_t& h, uint16_t& l) {
    asm("cvt.rn.bf16.f32 %0, %1;" : "=h"(h) : "f"(x));
    float hf = __uint_as_float(((uint32_t)h) << 16);
    asm("cvt.rn.bf16.f32 %0, %1;" : "=h"(l) : "f"(x - hf));
}

__device__ __forceinline__ void mma_bf16(float c[4], uint32_t a0, uint32_t a1,
                                         uint32_t a2, uint32_t a3,
                                         uint32_t b0, uint32_t b1) {
    asm volatile(
        "mma.sync.aligned.m16n8k16.row.col.f32.bf16.bf16.f32 "
        "{%0,%1,%2,%3}, {%4,%5,%6,%7}, {%8,%9}, {%0,%1,%2,%3};"
        : "+f"(c[0]), "+f"(c[1]), "+f"(c[2]), "+f"(c[3])
        : "r"(a0), "r"(a1), "r"(a2), "r"(a3), "r"(b0), "r"(b1));
}

// ================= CSR build =================
__global__ void zero_counts(int* __restrict__ deg, int* __restrict__ cur, int n) {
    for (int i = blockIdx.x * blockDim.x + threadIdx.x; i < n;
         i += gridDim.x * blockDim.x) { deg[i] = 0; cur[i] = 0; }
}

__global__ void csr_count(const int* __restrict__ dst, int E, int* __restrict__ deg) {
    for (int i = blockIdx.x * blockDim.x + threadIdx.x; i < E;
         i += gridDim.x * blockDim.x)
        atomicAdd(&deg[dst[i]], 1);
}

__global__ void csr_scan(const int* __restrict__ deg, int* __restrict__ rowptr, int n, int E) {
    __shared__ int part[1024];
    int t = threadIdx.x;
    int chunk = (n + 1023) / 1024;
    int start = t * chunk;
    int stop = min(start + chunk, n);
    int sum = 0;
    for (int i = start; i < stop; i++) sum += deg[i];
    part[t] = sum;
    __syncthreads();
    for (int o = 1; o < 1024; o <<= 1) {
        int v = (t >= o) ? part[t - o] : 0;
        __syncthreads();
        part[t] += v;
        __syncthreads();
    }
    int run = part[t] - sum;
    for (int i = start; i < stop; i++) { rowptr[i] = run; run += deg[i]; }
    if (t == 0) rowptr[n] = E;
}

__global__ void csr_fill(const int* __restrict__ src, const int* __restrict__ dst, int E,
                         const int* __restrict__ rowptr, int* __restrict__ cur,
                         int* __restrict__ srcs) {
    for (int i = blockIdx.x * blockDim.x + threadIdx.x; i < E;
         i += gridDim.x * blockDim.x) {
        int d = dst[i];
        int pos = rowptr[d] + atomicAdd(&cur[d], 1);
        srcs[pos] = src[i];
    }
}

// ================= GEMM: split-bf16 3-term, m16n8k16, fused attn epilogue =================
#define APITCH 20   // u32 pitch for A pair planes (conflict-free fragment loads)
#define BPITCH 17   // u32 pitch for B pair planes
__global__ __launch_bounds__(256, 2)
void gemm_bf16s(const float* __restrict__ A, const float* __restrict__ B,
                float* __restrict__ C, int M, int N, int K,
                const float* __restrict__ asrc, const float* __restrict__ adst,
                float* __restrict__ as_out, float* __restrict__ ad_out, int heads) {
    __shared__ uint32_t Ah[128][APITCH], Alo[128][APITCH];
    __shared__ uint32_t Bh[64][BPITCH], Blo[64][BPITCH];
    __shared__ float s_as[128], s_ad[128];
    int tid = threadIdx.x;
    int lane = tid & 31;
    int warp = tid >> 5;
    int wm = warp & 3;
    int wn = warp >> 2;
    int row0 = blockIdx.y * 128;
    int col0 = blockIdx.x * 64;
    int g = lane >> 2;
    int tg = lane & 3;

    if (tid < 128) { s_as[tid] = 0.0f; s_ad[tid] = 0.0f; }

    float acc[2][4][4];
    #pragma unroll
    for (int i = 0; i < 2; i++)
        #pragma unroll
        for (int j = 0; j < 4; j++)
            #pragma unroll
            for (int k = 0; k < 4; k++) acc[i][j][k] = 0.0f;

    bool fullN = (col0 + 64 <= N);

    if (fullN) {
        float4 ra[4], rbv[2];
        #pragma unroll
        for (int l = 0; l < 4; l++) {
            int i = tid + l * 256;
            int r = i >> 3, c4 = i & 7;
            ra[l] = make_float4(0.f, 0.f, 0.f, 0.f);
            if (row0 + r < M)
                ra[l] = *(const float4*)&A[(size_t)(row0 + r) * K + c4 * 4];
        }
        #pragma unroll
        for (int l = 0; l < 2; l++) {
            int i = tid + l * 256;
            int kr = i >> 4, c4 = i & 15;
            rbv[l] = *(const float4*)&B[(size_t)kr * N + col0 + c4 * 4];
        }

        for (int kk = 0; kk < K; kk += 32) {
            // split-store A (pairs along k)
            #pragma unroll
            for (int l = 0; l < 4; l++) {
                int i = tid + l * 256;
                int r = i >> 3, c4 = i & 7;
                uint32_t h0, l0, h1, l1;
                split_pair(ra[l].x, ra[l].y, h0, l0);
                split_pair(ra[l].z, ra[l].w, h1, l1);
                Ah[r][c4 * 2] = h0;  Ah[r][c4 * 2 + 1] = h1;
                Alo[r][c4 * 2] = l0; Alo[r][c4 * 2 + 1] = l1;
            }
            // split-store B (u16 scatter: pairs along k, transposed)
            #pragma unroll
            for (int l = 0; l < 2; l++) {
                int i = tid + l * 256;
                int kr = i >> 4, c4 = i & 15;
                int pr = kr >> 1, hf = kr & 1;
                float vals[4] = {rbv[l].x, rbv[l].y, rbv[l].z, rbv[l].w};
                #pragma unroll
                for (int j = 0; j < 4; j++) {
                    int n = c4 * 4 + j;
                    uint16_t bh16, bl16;
                    split_one(vals[j], bh16, bl16);
                    ((uint16_t*)Bh)[(n * BPITCH + pr) * 2 + hf] = bh16;
                    ((uint16_t*)Blo)[(n * BPITCH + pr) * 2 + hf] = bl16;
                }
            }
            __syncthreads();

            if (kk + 32 < K) {
                #pragma unroll
                for (int l = 0; l < 4; l++) {
                    int i = tid + l * 256;
                    int r = i >> 3, c4 = i & 7;
                    ra[l] = make_float4(0.f, 0.f, 0.f, 0.f);
                    if (row0 + r < M)
                        ra[l] = *(const float4*)&A[(size_t)(row0 + r) * K + kk + 32 + c4 * 4];
                }
                #pragma unroll
                for (int l = 0; l < 2; l++) {
                    int i = tid + l * 256;
                    int kr = i >> 4, c4 = i & 15;
                    rbv[l] = *(const float4*)&B[(size_t)(kk + 32 + kr) * N + col0 + c4 * 4];
                }
            }

            #pragma unroll
            for (int ks = 0; ks < 2; ks++) {
                int p0 = ks * 8 + tg, p1 = p0 + 4;
                uint32_t ah[2][4], alr[2][4];
                #pragma unroll
                for (int mf = 0; mf < 2; mf++) {
                    int rb_ = wm * 32 + mf * 16 + g;
                    ah[mf][0] = Ah[rb_][p0];      ah[mf][1] = Ah[rb_ + 8][p0];
                    ah[mf][2] = Ah[rb_][p1];      ah[mf][3] = Ah[rb_ + 8][p1];
                    alr[mf][0] = Alo[rb_][p0];    alr[mf][1] = Alo[rb_ + 8][p0];
                    alr[mf][2] = Alo[rb_][p1];    alr[mf][3] = Alo[rb_ + 8][p1];
                }
                uint32_t bh_[4][2], bl_[4][2];
                #pragma unroll
                for (int nf = 0; nf < 4; nf++) {
                    int nb = wn * 32 + nf * 8 + g;
                    bh_[nf][0] = Bh[nb][p0];  bh_[nf][1] = Bh[nb][p1];
                    bl_[nf][0] = Blo[nb][p0]; bl_[nf][1] = Blo[nb][p1];
                }
                #pragma unroll
                for (int mf = 0; mf < 2; mf++)
                    #pragma unroll
                    for (int nf = 0; nf < 4; nf++) {
                        mma_bf16(acc[mf][nf], alr[mf][0], alr[mf][1], alr[mf][2], alr[mf][3],
                                 bh_[nf][0], bh_[nf][1]);
                        mma_bf16(acc[mf][nf], ah[mf][0], ah[mf][1], ah[mf][2], ah[mf][3],
                                 bl_[nf][0], bl_[nf][1]);
                        mma_bf16(acc[mf][nf], ah[mf][0], ah[mf][1], ah[mf][2], ah[mf][3],
                                 bh_[nf][0], bh_[nf][1]);
                    }
            }
            __syncthreads();
        }
    } else {
        for (int kk = 0; kk < K; kk += 32) {
            #pragma unroll
            for (int l = 0; l < 4; l++) {
                int i = tid + l * 256;
                int r = i >> 3, c4 = i & 7;
                float4 v = make_float4(0.f, 0.f, 0.f, 0.f);
                if (row0 + r < M)
                    v = *(const float4*)&A[(size_t)(row0 + r) * K + kk + c4 * 4];
                uint32_t h0, l0, h1, l1;
                split_pair(v.x, v.y, h0, l0);
                split_pair(v.z, v.w, h1, l1);
                Ah[r][c4 * 2] = h0;  Ah[r][c4 * 2 + 1] = h1;
                Alo[r][c4 * 2] = l0; Alo[r][c4 * 2 + 1] = l1;
            }
            #pragma unroll
            for (int l = 0; l < 8; l++) {
                int i = tid + l * 256;
                int kr = i >> 6, c = i & 63;
                float v = 0.0f;
                if (col0 + c < N) v = B[(size_t)(kk + kr) * N + col0 + c];
                int pr = kr >> 1, hf = kr & 1;
                uint16_t bh16, bl16;
                split_one(v, bh16, bl16);
                ((uint16_t*)Bh)[(c * BPITCH + pr) * 2 + hf] = bh16;
                ((uint16_t*)Blo)[(c * BPITCH + pr) * 2 + hf] = bl16;
            }
            __syncthreads();
            #pragma unroll
            for (int ks = 0; ks < 2; ks++) {
                int p0 = ks * 8 + tg, p1 = p0 + 4;
                uint32_t ah[2][4], alr[2][4];
                #pragma unroll
                for (int mf = 0; mf < 2; mf++) {
                    int rb_ = wm * 32 + mf * 16 + g;
                    ah[mf][0] = Ah[rb_][p0];      ah[mf][1] = Ah[rb_ + 8][p0];
                    ah[mf][2] = Ah[rb_][p1];      ah[mf][3] = Ah[rb_ + 8][p1];
                    alr[mf][0] = Alo[rb_][p0];    alr[mf][1] = Alo[rb_ + 8][p0];
                    alr[mf][2] = Alo[rb_][p1];    alr[mf][3] = Alo[rb_ + 8][p1];
                }
                uint32_t bh_[4][2], bl_[4][2];
                #pragma unroll
                for (int nf = 0; nf < 4; nf++) {
                    int nb = wn * 32 + nf * 8 + g;
                    bh_[nf][0] = Bh[nb][p0];  bh_[nf][1] = Bh[nb][p1];
                    bl_[nf][0] = Blo[nb][p0]; bl_[nf][1] = Blo[nb][p1];
                }
                #pragma unroll
                for (int mf = 0; mf < 2; mf++)
                    #pragma unroll
                    for (int nf = 0; nf < 4; nf++) {
                        mma_bf16(acc[mf][nf], alr[mf][0], alr[mf][1], alr[mf][2], alr[mf][3],
                                 bh_[nf][0], bh_[nf][1]);
                        mma_bf16(acc[mf][nf], ah[mf][0], ah[mf][1], ah[mf][2], ah[mf][3],
                                 bl_[nf][0], bl_[nf][1]);
                        mma_bf16(acc[mf][nf], ah[mf][0], ah[mf][1], ah[mf][2], ah[mf][3],
                                 bh_[nf][0], bh_[nf][1]);
                    }
            }
            __syncthreads();
        }
    }

    // ---- write C + attn partials ----
    float pa[2][2] = {}, pd[2][2] = {};
    #pragma unroll
    for (int nf = 0; nf < 4; nf++) {
        int col = col0 + wn * 32 + nf * 8 + 2 * tg;
        float av0 = 0.f, av1 = 0.f, dv0 = 0.f, dv1 = 0.f;
        if (col < N)     { av0 = asrc[col];     dv0 = adst[col]; }
        if (col + 1 < N) { av1 = asrc[col + 1]; dv1 = adst[col + 1]; }
        #pragma unroll
        for (int mf = 0; mf < 2; mf++) {
            #pragma unroll
            for (int half = 0; half < 2; half++) {
                int row = row0 + wm * 32 + mf * 16 + g + half * 8;
                float c0 = acc[mf][nf][half * 2], c1 = acc[mf][nf][half * 2 + 1];
                if (row < M && col < N)
                    *(float2*)&C[(size_t)row * N + col] = make_float2(c0, c1);
                pa[mf][half] += c0 * av0 + c1 * av1;
                pd[mf][half] += c0 * dv0 + c1 * dv1;
            }
        }
    }
    #pragma unroll
    for (int o = 1; o <= 2; o <<= 1) {
        #pragma unroll
        for (int mf = 0; mf < 2; mf++)
            #pragma unroll
            for (int half = 0; half < 2; half++) {
                pa[mf][half] += __shfl_xor_sync(0xFFFFFFFFu, pa[mf][half], o);
                pd[mf][half] += __shfl_xor_sync(0xFFFFFFFFu, pd[mf][half], o);
            }
    }
    if (tg == 0) {
        #pragma unroll
        for (int mf = 0; mf < 2; mf++)
            #pragma unroll
            for (int half = 0; half < 2; half++) {
                int lr = wm * 32 + mf * 16 + g + half * 8;
                atomicAdd(&s_as[lr], pa[mf][half]);
                atomicAdd(&s_ad[lr], pd[mf][half]);
            }
    }
    __syncthreads();
    if (tid < 128) {
        int row = row0 + tid;
        if (row < M) {
            int head = (heads == 1) ? 0 : (col0 >> 6);
            as_out[row * heads + head] = s_as[tid];
            ad_out[row * heads + head] = s_ad[tid];
        }
    }
}

// ---------------- fused softmax + aggregation, H=4 C=64, BN+ELU epilogue ----------------
__global__ __launch_bounds__(256)
void agg_fused4(const int* __restrict__ rowptr, const int* __restrict__ srcs,
                const float* __restrict__ as_, const float* __restrict__ ad_,
                float* __restrict__ alpha,
                const float* __restrict__ hbuf, const float* __restrict__ bias,
                const float* __restrict__ bng, const float* __restrict__ bnb,
                const float* __restrict__ bnm, const float* __restrict__ bnv,
                float* __restrict__ out) {
    __shared__ float s_al[8][32][4];
    __shared__ int   s_sr[8][32];
    int w = (blockIdx.x * blockDim.x + threadIdx.x) >> 5;
    int lane = threadIdx.x & 31;
    int wi = (threadIdx.x >> 5);
    if (w >= NN) return;
    int d = w;
    float4 add = *(const float4*)&ad_[d * 4];
    int beg = rowptr[d], end = rowptr[d + 1];

    float d0 = 0.f, d1 = 0.f, d2 = 0.f, d3 = 0.f;
    for (int j = beg + lane; j < end; j += 32) {
        int s = srcs[j];
        float4 av = *(const float4*)&as_[s * 4];
        float e0 = av.x + add.x; e0 = (e0 > 0.f) ? e0 : NEG_SLOPE * e0;
        float e1 = av.y + add.y; e1 = (e1 > 0.f) ? e1 : NEG_SLOPE * e1;
        float e2 = av.z + add.z; e2 = (e2 > 0.f) ? e2 : NEG_SLOPE * e2;
        float e3 = av.w + add.w; e3 = (e3 > 0.f) ? e3 : NEG_SLOPE * e3;
        float p0 = __expf(e0), p1 = __expf(e1);
        float p2 = __expf(e2), p3 = __expf(e3);
        *(float4*)&alpha[(size_t)j * 4] = make_float4(p0, p1, p2, p3);
        d0 += p0; d1 += p1; d2 += p2; d3 += p3;
    }
    #pragma unroll
    for (int o = 16; o > 0; o >>= 1) {
        d0 += __shfl_xor_sync(0xFFFFFFFFu, d0, o);
        d1 += __shfl_xor_sync(0xFFFFFFFFu, d1, o);
        d2 += __shfl_xor_sync(0xFFFFFFFFu, d2, o);
        d3 += __shfl_xor_sync(0xFFFFFFFFu, d3, o);
    }
    float4 inv = make_float4(1.f / (d0 + 1e-16f), 1.f / (d1 + 1e-16f),
                             1.f / (d2 + 1e-16f), 1.f / (d3 + 1e-16f));

    int h0 = lane >> 4;
    int h1 = 2 + (lane >> 4);

    float4 acc0 = make_float4(0.f, 0.f, 0.f, 0.f);
    float4 acc1 = make_float4(0.f, 0.f, 0.f, 0.f);

    for (int jb = beg; jb < end; jb += 32) {
        int j = jb + lane;
        int s = 0;
        float4 p = make_float4(0.f, 0.f, 0.f, 0.f);
        if (j < end) {
            s = srcs[j];
            p = *(const float4*)&alpha[(size_t)j * 4];
        }
        p.x *= inv.x; p.y *= inv.y; p.z *= inv.z; p.w *= inv.w;
        __syncwarp();
        s_sr[wi][lane] = s;
        *(float4*)&s_al[wi][lane][0] = p;
        __syncwarp();
        int n = min(32, end - jb);
        #pragma unroll 4
        for (int t = 0; t < n; t++) {
            int ss = s_sr[wi][t];
            float a0 = s_al[wi][t][h0];
            float a1 = s_al[wi][t][h1];
            const float4* hp = (const float4*)(hbuf + (size_t)ss * FD);
            float4 v0 = hp[lane];
            float4 v1 = hp[32 + lane];
            acc0.x += v0.x * a0; acc0.y += v0.y * a0;
            acc0.z += v0.z * a0; acc0.w += v0.w * a0;
            acc1.x += v1.x * a1; acc1.y += v1.y * a1;
            acc1.z += v1.z * a1; acc1.w += v1.w * a1;
        }
    }

    int f0 = lane * 4, f1 = 128 + lane * 4;
    #pragma unroll
    for (int c = 0; c < 2; c++) {
        int f = c ? f1 : f0;
        float4 acc = c ? acc1 : acc0;
        float4 bv = *(const float4*)&bias[f];
        float4 gv = *(const float4*)&bng[f];
        float4 betav = *(const float4*)&bnb[f];
        float4 mv = *(const float4*)&bnm[f];
        float4 vv = *(const float4*)&bnv[f];
        float4 r;
        r.x = gv.x * (acc.x + bv.x - mv.x) * rsqrtf(vv.x + BN_EPS) + betav.x;
        r.y = gv.y * (acc.y + bv.y - mv.y) * rsqrtf(vv.y + BN_EPS) + betav.y;
        r.z = gv.z * (acc.z + bv.z - mv.z) * rsqrtf(vv.z + BN_EPS) + betav.z;
        r.w = gv.w * (acc.w + bv.w - mv.w) * rsqrtf(vv.w + BN_EPS) + betav.w;
        r.x = (r.x > 0.f) ? r.x : (expf(r.x) - 1.f);
        r.y = (r.y > 0.f) ? r.y : (expf(r.y) - 1.f);
        r.z = (r.z > 0.f) ? r.z : (expf(r.z) - 1.f);
        r.w = (r.w > 0.f) ? r.w : (expf(r.w) - 1.f);
        *(float4*)&out[(size_t)d * FD + f] = r;
    }
}

// ---------------- fused softmax + aggregation, H=1 C=40 ----------------
__global__ __launch_bounds__(256)
void agg_fused1(const int* __restrict__ rowptr, const int* __restrict__ srcs,
                const float* __restrict__ as_, const float* __restrict__ ad_,
                float* __restrict__ alpha,
                const float* __restrict__ hbuf, const float* __restrict__ bias,
                float* __restrict__ out) {
    __shared__ float s_al[8][32];
    __shared__ int   s_sr[8][32];
    int w = (blockIdx.x * blockDim.x + threadIdx.x) >> 5;
    int lane = threadIdx.x & 31;
    int wi = (threadIdx.x >> 5);
    if (w >= NN) return;
    int d = w;
    float adl = ad_[d];
    int beg = rowptr[d], end = rowptr[d + 1];

    float den = 0.f;
    for (int j = beg + lane; j < end; j += 32) {
        float e = as_[srcs[j]] + adl;
        e = (e > 0.f) ? e : NEG_SLOPE * e;
        float p = __expf(e);
        alpha[j] = p;
        den += p;
    }
    #pragma unroll
    for (int o = 16; o > 0; o >>= 1)
        den += __shfl_xor_sync(0xFFFFFFFFu, den, o);
    float invden = 1.0f / (den + 1e-16f);

    float acc0 = 0.f, acc1 = 0.f;
    for (int jb = beg; jb < end; jb += 32) {
        int j = jb + lane;
        int s = 0; float p = 0.f;
        if (j < end) { s = srcs[j]; p = alpha[j]; }
        __syncwarp();
        s_sr[wi][lane] = s;
        s_al[wi][lane] = p * invden;
        __syncwarp();
        int n = min(32, end - jb);
        #pragma unroll 4
        for (int t = 0; t < n; t++) {
            int ss = s_sr[wi][t];
            float a = s_al[wi][t];
            acc0 += hbuf[(size_t)ss * OUTD + lane] * a;
            if (lane < OUTD - 32)
                acc1 += hbuf[(size_t)ss * OUTD + 32 + lane] * a;
        }
    }
    out[(size_t)d * OUTD + lane] = acc0 + bias[lane];
    if (lane < OUTD - 32)
        out[(size_t)d * OUTD + 32 + lane] = acc1 + bias[32 + lane];
}

// ================= launch =================
extern "C" void kernel_launch(void* const* d_in, const int* in_sizes, int n_in,
                              void* d_out, int out_size) {
    const float* x       = (const float*)d_in[0];
    const int*   eidx    = (const int*)d_in[1];
    const float* W0      = (const float*)d_in[2];
    const float* a_src0  = (const float*)d_in[3];
    const float* a_dst0  = (const float*)d_in[4];
    const float* b0      = (const float*)d_in[5];
    const float* bn0_g   = (const float*)d_in[6];
    const float* bn0_b   = (const float*)d_in[7];
    const float* bn0_m   = (const float*)d_in[8];
    const float* bn0_v   = (const float*)d_in[9];
    const float* W1      = (const float*)d_in[10];
    const float* a_src1  = (const float*)d_in[11];
    const float* a_dst1  = (const float*)d_in[12];
    const float* b1      = (const float*)d_in[13];
    const float* bn1_g   = (const float*)d_in[14];
    const float* bn1_b   = (const float*)d_in[15];
    const float* bn1_m   = (const float*)d_in[16];
    const float* bn1_v   = (const float*)d_in[17];
    const float* W2      = (const float*)d_in[18];
    const float* a_src2  = (const float*)d_in[19];
    const float* a_dst2  = (const float*)d_in[20];
    const float* b2      = (const float*)d_in[21];
    float* out = (float*)d_out;

    int E = in_sizes[1] / 2;
    const int* src = eidx;
    const int* dst = eidx + E;

    float *h_buf, *x1_buf, *as_buf, *ad_buf, *al_buf;
    int *deg, *cur, *rowptr, *srcs;
    cudaGetSymbolAddress((void**)&h_buf, g_h);
    cudaGetSymbolAddress((void**)&x1_buf, g_x1);
    cudaGetSymbolAddress((void**)&as_buf, g_as);
    cudaGetSymbolAddress((void**)&ad_buf, g_ad);
    cudaGetSymbolAddress((void**)&al_buf, g_alpha);
    cudaGetSymbolAddress((void**)&deg, g_deg);
    cudaGetSymbolAddress((void**)&cur, g_cur);
    cudaGetSymbolAddress((void**)&rowptr, g_rowptr);
    cudaGetSymbolAddress((void**)&srcs, g_srcs);

    static cudaStream_t s2 = nullptr;
    static cudaEvent_t ev_fork = nullptr, ev_join = nullptr;
    if (s2 == nullptr) {
        cudaStreamCreateWithFlags(&s2, cudaStreamNonBlocking);
        cudaEventCreateWithFlags(&ev_fork, cudaEventDisableTiming);
        cudaEventCreateWithFlags(&ev_join, cudaEventDisableTiming);
    }

    // ---- fork: CSR build on s2, concurrent with layer-0 GEMM ----
    cudaEventRecord(ev_fork, 0);
    cudaStreamWaitEvent(s2, ev_fork, 0);
    zero_counts<<<cdiv(NN, 256), 256, 0, s2>>>(deg, cur, NN);
    csr_count<<<cdiv(E, 256), 256, 0, s2>>>(dst, E, deg);
    csr_scan<<<1, 1024, 0, s2>>>(deg, rowptr, NN, E);
    csr_fill<<<cdiv(E, 256), 256, 0, s2>>>(src, dst, E, rowptr, cur, srcs);
    cudaEventRecord(ev_join, s2);

    // ---- layer 0 ----
    gemm_bf16s<<<dim3(cdiv(FD, 64), cdiv(NN, 128)), 256>>>(
        x, W0, h_buf, NN, FD, 256, a_src0, a_dst0, as_buf, ad_buf, HEADS);
    cudaStreamWaitEvent(0, ev_join, 0);
    agg_fused4<<<cdiv(NN * 32, 256), 256>>>(rowptr, srcs, as_buf, ad_buf, al_buf, h_buf,
                                            b0, bn0_g, bn0_b, bn0_m, bn0_v, x1_buf);

    // ---- layer 1 ----
    gemm_bf16s<<<dim3(cdiv(FD, 64), cdiv(NN, 128)), 256>>>(
        x1_buf, W1, h_buf, NN, FD, FD, a_src1, a_dst1, as_buf, ad_buf, HEADS);
    agg_fused4<<<cdiv(NN * 32, 256), 256>>>(rowptr, srcs, as_buf, ad_buf, al_buf, h_buf,
                                            b1, bn1_g, bn1_b, bn1_m, bn1_v, x1_buf);

    // ---- layer 2 (heads=1, ch=40) ----
    gemm_bf16s<<<dim3(cdiv(OUTD, 64), cdiv(NN, 128)), 256>>>(
        x1_buf, W2, h_buf, NN, OUTD, FD, a_src2, a_dst2, as_buf, ad_buf, 1);
    agg_fused1<<<cdiv(NN * 32, 256), 256>>>(rowptr, srcs, as_buf, ad_buf, al_buf,
                                            h_buf, b2, out);
}

// round 9
// speedup vs baseline: 5.4005x; 1.0697x over previous
#include <cuda_runtime.h>
#include <cuda_fp16.h>
#include <math.h>
#include <stdint.h>

#define NN 50000
#define EE 850000
#define FD 256      // HEADS*HID
#define HEADS 4
#define CH 64
#define OUTD 40
#define BN_EPS 1e-5f
#define NEG_SLOPE 0.2f

// ---------------- scratch (static, allocation-free) ----------------
__device__ __align__(256) __half g_h16[NN * FD];   // GEMM output (fp16) for aggregation
__device__ __align__(256) float g_x1[NN * FD];
__device__ __align__(256) float g_as[NN * HEADS];
__device__ __align__(256) float g_ad[NN * HEADS];
__device__ __align__(256) float g_alpha[(size_t)EE * HEADS];
__device__ int   g_deg[NN];
__device__ int   g_cur[NN];
__device__ int   g_rowptr[NN + 1];
__device__ int   g_srcs[EE];

static inline int cdiv(int a, int b) { return (a + b - 1) / b; }

// ---------------- bf16 split helpers (GEMM inputs) ----------------
__device__ __forceinline__ uint32_t cvt2_bf16(float x1, float x0) {
    uint32_t r;
    asm("cvt.rn.bf16x2.f32 %0, %1, %2;" : "=r"(r) : "f"(x1), "f"(x0));
    return r;
}
__device__ __forceinline__ void split_pair(float x0, float x1, uint32_t& h, uint32_t& l) {
    h = cvt2_bf16(x1, x0);
    float h0 = __uint_as_float(h << 16);
    float h1 = __uint_as_float(h & 0xFFFF0000u);
    l = cvt2_bf16(x1 - h1, x0 - h0);
}
__device__ __forceinline__ void split_one(float x, uint16_t& h, uint16_t& l) {
    asm("cvt.rn.bf16.f32 %0, %1;" : "=h"(h) : "f"(x));
    float hf = __uint_as_float(((uint32_t)h) << 16);
    asm("cvt.rn.bf16.f32 %0, %1;" : "=h"(l) : "f"(x - hf));
}

__device__ __forceinline__ void mma_bf16(float c[4], uint32_t a0, uint32_t a1,
                                         uint32_t a2, uint32_t a3,
                                         uint32_t b0, uint32_t b1) {
    asm volatile(
        "mma.sync.aligned.m16n8k16.row.col.f32.bf16.bf16.f32 "
        "{%0,%1,%2,%3}, {%4,%5,%6,%7}, {%8,%9}, {%0,%1,%2,%3};"
        : "+f"(c[0]), "+f"(c[1]), "+f"(c[2]), "+f"(c[3])
        : "r"(a0), "r"(a1), "r"(a2), "r"(a3), "r"(b0), "r"(b1));
}

// ================= CSR build =================
__global__ void zero_counts(int* __restrict__ deg, int* __restrict__ cur, int n) {
    for (int i = blockIdx.x * blockDim.x + threadIdx.x; i < n;
         i += gridDim.x * blockDim.x) { deg[i] = 0; cur[i] = 0; }
}

__global__ void csr_count(const int* __restrict__ dst, int E, int* __restrict__ deg) {
    for (int i = blockIdx.x * blockDim.x + threadIdx.x; i < E;
         i += gridDim.x * blockDim.x)
        atomicAdd(&deg[dst[i]], 1);
}

__global__ void csr_scan(const int* __restrict__ deg, int* __restrict__ rowptr, int n, int E) {
    __shared__ int part[1024];
    int t = threadIdx.x;
    int chunk = (n + 1023) / 1024;
    int start = t * chunk;
    int stop = min(start + chunk, n);
    int sum = 0;
    for (int i = start; i < stop; i++) sum += deg[i];
    part[t] = sum;
    __syncthreads();
    for (int o = 1; o < 1024; o <<= 1) {
        int v = (t >= o) ? part[t - o] : 0;
        __syncthreads();
        part[t] += v;
        __syncthreads();
    }
    int run = part[t] - sum;
    for (int i = start; i < stop; i++) { rowptr[i] = run; run += deg[i]; }
    if (t == 0) rowptr[n] = E;
}

__global__ void csr_fill(const int* __restrict__ src, const int* __restrict__ dst, int E,
                         const int* __restrict__ rowptr, int* __restrict__ cur,
                         int* __restrict__ srcs) {
    for (int i = blockIdx.x * blockDim.x + threadIdx.x; i < E;
         i += gridDim.x * blockDim.x) {
        int d = dst[i];
        int pos = rowptr[d] + atomicAdd(&cur[d], 1);
        srcs[pos] = src[i];
    }
}

// ================= GEMM: split-bf16 3-term, fp16 C, fused attn epilogue =================
#define APITCH 20
#define BPITCH 17
__global__ __launch_bounds__(256, 2)
void gemm_bf16s(const float* __restrict__ A, const float* __restrict__ B,
                __half* __restrict__ C, int M, int N, int K,
                const float* __restrict__ asrc, const float* __restrict__ adst,
                float* __restrict__ as_out, float* __restrict__ ad_out, int heads) {
    __shared__ uint32_t Ah[128][APITCH], Alo[128][APITCH];
    __shared__ uint32_t Bh[64][BPITCH], Blo[64][BPITCH];
    __shared__ float s_as[128], s_ad[128];
    int tid = threadIdx.x;
    int lane = tid & 31;
    int warp = tid >> 5;
    int wm = warp & 3;
    int wn = warp >> 2;
    int row0 = blockIdx.y * 128;
    int col0 = blockIdx.x * 64;
    int g = lane >> 2;
    int tg = lane & 3;

    if (tid < 128) { s_as[tid] = 0.0f; s_ad[tid] = 0.0f; }

    float acc[2][4][4];
    #pragma unroll
    for (int i = 0; i < 2; i++)
        #pragma unroll
        for (int j = 0; j < 4; j++)
            #pragma unroll
            for (int k = 0; k < 4; k++) acc[i][j][k] = 0.0f;

    bool fullN = (col0 + 64 <= N);

    if (fullN) {
        float4 ra[4], rbv[2];
        #pragma unroll
        for (int l = 0; l < 4; l++) {
            int i = tid + l * 256;
            int r = i >> 3, c4 = i & 7;
            ra[l] = make_float4(0.f, 0.f, 0.f, 0.f);
            if (row0 + r < M)
                ra[l] = *(const float4*)&A[(size_t)(row0 + r) * K + c4 * 4];
        }
        #pragma unroll
        for (int l = 0; l < 2; l++) {
            int i = tid + l * 256;
            int kr = i >> 4, c4 = i & 15;
            rbv[l] = *(const float4*)&B[(size_t)kr * N + col0 + c4 * 4];
        }

        for (int kk = 0; kk < K; kk += 32) {
            #pragma unroll
            for (int l = 0; l < 4; l++) {
                int i = tid + l * 256;
                int r = i >> 3, c4 = i & 7;
                uint32_t h0, l0, h1, l1;
                split_pair(ra[l].x, ra[l].y, h0, l0);
                split_pair(ra[l].z, ra[l].w, h1, l1);
                Ah[r][c4 * 2] = h0;  Ah[r][c4 * 2 + 1] = h1;
                Alo[r][c4 * 2] = l0; Alo[r][c4 * 2 + 1] = l1;
            }
            #pragma unroll
            for (int l = 0; l < 2; l++) {
                int i = tid + l * 256;
                int kr = i >> 4, c4 = i & 15;
                int pr = kr >> 1, hf = kr & 1;
                float vals[4] = {rbv[l].x, rbv[l].y, rbv[l].z, rbv[l].w};
                #pragma unroll
                for (int j = 0; j < 4; j++) {
                    int n = c4 * 4 + j;
                    uint16_t bh16, bl16;
                    split_one(vals[j], bh16, bl16);
                    ((uint16_t*)Bh)[(n * BPITCH + pr) * 2 + hf] = bh16;
                    ((uint16_t*)Blo)[(n * BPITCH + pr) * 2 + hf] = bl16;
                }
            }
            __syncthreads();

            if (kk + 32 < K) {
                #pragma unroll
                for (int l = 0; l < 4; l++) {
                    int i = tid + l * 256;
                    int r = i >> 3, c4 = i & 7;
                    ra[l] = make_float4(0.f, 0.f, 0.f, 0.f);
                    if (row0 + r < M)
                        ra[l] = *(const float4*)&A[(size_t)(row0 + r) * K + kk + 32 + c4 * 4];
                }
                #pragma unroll
                for (int l = 0; l < 2; l++) {
                    int i = tid + l * 256;
                    int kr = i >> 4, c4 = i & 15;
                    rbv[l] = *(const float4*)&B[(size_t)(kk + 32 + kr) * N + col0 + c4 * 4];
                }
            }

            #pragma unroll
            for (int ks = 0; ks < 2; ks++) {
                int p0 = ks * 8 + tg, p1 = p0 + 4;
                uint32_t ah[2][4], alr[2][4];
                #pragma unroll
                for (int mf = 0; mf < 2; mf++) {
                    int rb_ = wm * 32 + mf * 16 + g;
                    ah[mf][0] = Ah[rb_][p0];      ah[mf][1] = Ah[rb_ + 8][p0];
                    ah[mf][2] = Ah[rb_][p1];      ah[mf][3] = Ah[rb_ + 8][p1];
                    alr[mf][0] = Alo[rb_][p0];    alr[mf][1] = Alo[rb_ + 8][p0];
                    alr[mf][2] = Alo[rb_][p1];    alr[mf][3] = Alo[rb_ + 8][p1];
                }
                uint32_t bh_[4][2], bl_[4][2];
                #pragma unroll
                for (int nf = 0; nf < 4; nf++) {
                    int nb = wn * 32 + nf * 8 + g;
                    bh_[nf][0] = Bh[nb][p0];  bh_[nf][1] = Bh[nb][p1];
                    bl_[nf][0] = Blo[nb][p0]; bl_[nf][1] = Blo[nb][p1];
                }
                #pragma unroll
                for (int mf = 0; mf < 2; mf++)
                    #pragma unroll
                    for (int nf = 0; nf < 4; nf++) {
                        mma_bf16(acc[mf][nf], alr[mf][0], alr[mf][1], alr[mf][2], alr[mf][3],
                                 bh_[nf][0], bh_[nf][1]);
                        mma_bf16(acc[mf][nf], ah[mf][0], ah[mf][1], ah[mf][2], ah[mf][3],
                                 bl_[nf][0], bl_[nf][1]);
                        mma_bf16(acc[mf][nf], ah[mf][0], ah[mf][1], ah[mf][2], ah[mf][3],
                                 bh_[nf][0], bh_[nf][1]);
                    }
            }
            __syncthreads();
        }
    } else {
        for (int kk = 0; kk < K; kk += 32) {
            #pragma unroll
            for (int l = 0; l < 4; l++) {
                int i = tid + l * 256;
                int r = i >> 3, c4 = i & 7;
                float4 v = make_float4(0.f, 0.f, 0.f, 0.f);
                if (row0 + r < M)
                    v = *(const float4*)&A[(size_t)(row0 + r) * K + kk + c4 * 4];
                uint32_t h0, l0, h1, l1;
                split_pair(v.x, v.y, h0, l0);
                split_pair(v.z, v.w, h1, l1);
                Ah[r][c4 * 2] = h0;  Ah[r][c4 * 2 + 1] = h1;
                Alo[r][c4 * 2] = l0; Alo[r][c4 * 2 + 1] = l1;
            }
            #pragma unroll
            for (int l = 0; l < 8; l++) {
                int i = tid + l * 256;
                int kr = i >> 6, c = i & 63;
                float v = 0.0f;
                if (col0 + c < N) v = B[(size_t)(kk + kr) * N + col0 + c];
                int pr = kr >> 1, hf = kr & 1;
                uint16_t bh16, bl16;
                split_one(v, bh16, bl16);
                ((uint16_t*)Bh)[(c * BPITCH + pr) * 2 + hf] = bh16;
                ((uint16_t*)Blo)[(c * BPITCH + pr) * 2 + hf] = bl16;
            }
            __syncthreads();
            #pragma unroll
            for (int ks = 0; ks < 2; ks++) {
                int p0 = ks * 8 + tg, p1 = p0 + 4;
                uint32_t ah[2][4], alr[2][4];
                #pragma unroll
                for (int mf = 0; mf < 2; mf++) {
                    int rb_ = wm * 32 + mf * 16 + g;
                    ah[mf][0] = Ah[rb_][p0];      ah[mf][1] = Ah[rb_ + 8][p0];
                    ah[mf][2] = Ah[rb_][p1];      ah[mf][3] = Ah[rb_ + 8][p1];
                    alr[mf][0] = Alo[rb_][p0];    alr[mf][1] = Alo[rb_ + 8][p0];
                    alr[mf][2] = Alo[rb_][p1];    alr[mf][3] = Alo[rb_ + 8][p1];
                }
                uint32_t bh_[4][2], bl_[4][2];
                #pragma unroll
                for (int nf = 0; nf < 4; nf++) {
                    int nb = wn * 32 + nf * 8 + g;
                    bh_[nf][0] = Bh[nb][p0];  bh_[nf][1] = Bh[nb][p1];
                    bl_[nf][0] = Blo[nb][p0]; bl_[nf][1] = Blo[nb][p1];
                }
                #pragma unroll
                for (int mf = 0; mf < 2; mf++)
                    #pragma unroll
                    for (int nf = 0; nf < 4; nf++) {
                        mma_bf16(acc[mf][nf], alr[mf][0], alr[mf][1], alr[mf][2], alr[mf][3],
                                 bh_[nf][0], bh_[nf][1]);
                        mma_bf16(acc[mf][nf], ah[mf][0], ah[mf][1], ah[mf][2], ah[mf][3],
                                 bl_[nf][0], bl_[nf][1]);
                        mma_bf16(acc[mf][nf], ah[mf][0], ah[mf][1], ah[mf][2], ah[mf][3],
                                 bh_[nf][0], bh_[nf][1]);
                    }
            }
            __syncthreads();
        }
    }

    // ---- write C (fp16) + attn partials (from fp32 acc) ----
    float pa[2][2] = {}, pd[2][2] = {};
    #pragma unroll
    for (int nf = 0; nf < 4; nf++) {
        int col = col0 + wn * 32 + nf * 8 + 2 * tg;
        float av0 = 0.f, av1 = 0.f, dv0 = 0.f, dv1 = 0.f;
        if (col < N)     { av0 = asrc[col];     dv0 = adst[col]; }
        if (col + 1 < N) { av1 = asrc[col + 1]; dv1 = adst[col + 1]; }
        #pragma unroll
        for (int mf = 0; mf < 2; mf++) {
            #pragma unroll
            for (int half_ = 0; half_ < 2; half_++) {
                int row = row0 + wm * 32 + mf * 16 + g + half_ * 8;
                float c0 = acc[mf][nf][half_ * 2], c1 = acc[mf][nf][half_ * 2 + 1];
                if (row < M && col < N)
                    *(__half2*)&C[(size_t)row * N + col] = __floats2half2_rn(c0, c1);
                pa[mf][half_] += c0 * av0 + c1 * av1;
                pd[mf][half_] += c0 * dv0 + c1 * dv1;
            }
        }
    }
    #pragma unroll
    for (int o = 1; o <= 2; o <<= 1) {
        #pragma unroll
        for (int mf = 0; mf < 2; mf++)
            #pragma unroll
            for (int half_ = 0; half_ < 2; half_++) {
                pa[mf][half_] += __shfl_xor_sync(0xFFFFFFFFu, pa[mf][half_], o);
                pd[mf][half_] += __shfl_xor_sync(0xFFFFFFFFu, pd[mf][half_], o);
            }
    }
    if (tg == 0) {
        #pragma unroll
        for (int mf = 0; mf < 2; mf++)
            #pragma unroll
            for (int half_ = 0; half_ < 2; half_++) {
                int lr = wm * 32 + mf * 16 + g + half_ * 8;
                atomicAdd(&s_as[lr], pa[mf][half_]);
                atomicAdd(&s_ad[lr], pd[mf][half_]);
            }
    }
    __syncthreads();
    if (tid < 128) {
        int row = row0 + tid;
        if (row < M) {
            int head = (heads == 1) ? 0 : (col0 >> 6);
            as_out[row * heads + head] = s_as[tid];
            ad_out[row * heads + head] = s_ad[tid];
        }
    }
}

// ---------------- fused softmax + aggregation (fp16 h), H=4 C=64 ----------------
__global__ __launch_bounds__(256)
void agg_fused4(const int* __restrict__ rowptr, const int* __restrict__ srcs,
                const float* __restrict__ as_, const float* __restrict__ ad_,
                float* __restrict__ alpha,
                const __half* __restrict__ hbuf, const float* __restrict__ bias,
                const float* __restrict__ bng, const float* __restrict__ bnb,
                const float* __restrict__ bnm, const float* __restrict__ bnv,
                float* __restrict__ out) {
    __shared__ float s_al[8][32][4];
    __shared__ int   s_sr[8][32];
    int w = (blockIdx.x * blockDim.x + threadIdx.x) >> 5;
    int lane = threadIdx.x & 31;
    int wi = (threadIdx.x >> 5);
    if (w >= NN) return;
    int d = w;
    float4 add = *(const float4*)&ad_[d * 4];
    int beg = rowptr[d], end = rowptr[d + 1];

    float d0 = 0.f, d1 = 0.f, d2 = 0.f, d3 = 0.f;
    for (int j = beg + lane; j < end; j += 32) {
        int s = srcs[j];
        float4 av = *(const float4*)&as_[s * 4];
        float e0 = av.x + add.x; e0 = (e0 > 0.f) ? e0 : NEG_SLOPE * e0;
        float e1 = av.y + add.y; e1 = (e1 > 0.f) ? e1 : NEG_SLOPE * e1;
        float e2 = av.z + add.z; e2 = (e2 > 0.f) ? e2 : NEG_SLOPE * e2;
        float e3 = av.w + add.w; e3 = (e3 > 0.f) ? e3 : NEG_SLOPE * e3;
        float p0 = __expf(e0), p1 = __expf(e1);
        float p2 = __expf(e2), p3 = __expf(e3);
        *(float4*)&alpha[(size_t)j * 4] = make_float4(p0, p1, p2, p3);
        d0 += p0; d1 += p1; d2 += p2; d3 += p3;
    }
    #pragma unroll
    for (int o = 16; o > 0; o >>= 1) {
        d0 += __shfl_xor_sync(0xFFFFFFFFu, d0, o);
        d1 += __shfl_xor_sync(0xFFFFFFFFu, d1, o);
        d2 += __shfl_xor_sync(0xFFFFFFFFu, d2, o);
        d3 += __shfl_xor_sync(0xFFFFFFFFu, d3, o);
    }
    float4 inv = make_float4(1.f / (d0 + 1e-16f), 1.f / (d1 + 1e-16f),
                             1.f / (d2 + 1e-16f), 1.f / (d3 + 1e-16f));

    int h0 = lane >> 4;
    int h1 = 2 + (lane >> 4);

    float4 acc0 = make_float4(0.f, 0.f, 0.f, 0.f);
    float4 acc1 = make_float4(0.f, 0.f, 0.f, 0.f);

    for (int jb = beg; jb < end; jb += 32) {
        int j = jb + lane;
        int s = 0;
        float4 p = make_float4(0.f, 0.f, 0.f, 0.f);
        if (j < end) {
            s = srcs[j];
            p = *(const float4*)&alpha[(size_t)j * 4];
        }
        p.x *= inv.x; p.y *= inv.y; p.z *= inv.z; p.w *= inv.w;
        __syncwarp();
        s_sr[wi][lane] = s;
        *(float4*)&s_al[wi][lane][0] = p;
        __syncwarp();
        int n = min(32, end - jb);
        #pragma unroll 4
        for (int t = 0; t < n; t++) {
            int ss = s_sr[wi][t];
            float a0 = s_al[wi][t][h0];
            float a1 = s_al[wi][t][h1];
            const uint2* hp = (const uint2*)(hbuf + (size_t)ss * FD);
            uint2 u0 = hp[lane];        // features lane*4 .. +3
            uint2 u1 = hp[32 + lane];   // features 128+lane*4 .. +3
            float2 f00 = __half22float2(*(__half2*)&u0.x);
            float2 f01 = __half22float2(*(__half2*)&u0.y);
            float2 f10 = __half22float2(*(__half2*)&u1.x);
            float2 f11 = __half22float2(*(__half2*)&u1.y);
            acc0.x += f00.x * a0; acc0.y += f00.y * a0;
            acc0.z += f01.x * a0; acc0.w += f01.y * a0;
            acc1.x += f10.x * a1; acc1.y += f10.y * a1;
            acc1.z += f11.x * a1; acc1.w += f11.y * a1;
        }
    }

    int f0 = lane * 4, f1 = 128 + lane * 4;
    #pragma unroll
    for (int c = 0; c < 2; c++) {
        int f = c ? f1 : f0;
        float4 acc = c ? acc1 : acc0;
        float4 bv = *(const float4*)&bias[f];
        float4 gv = *(const float4*)&bng[f];
        float4 betav = *(const float4*)&bnb[f];
        float4 mv = *(const float4*)&bnm[f];
        float4 vv = *(const float4*)&bnv[f];
        float4 r;
        r.x = gv.x * (acc.x + bv.x - mv.x) * rsqrtf(vv.x + BN_EPS) + betav.x;
        r.y = gv.y * (acc.y + bv.y - mv.y) * rsqrtf(vv.y + BN_EPS) + betav.y;
        r.z = gv.z * (acc.z + bv.z - mv.z) * rsqrtf(vv.z + BN_EPS) + betav.z;
        r.w = gv.w * (acc.w + bv.w - mv.w) * rsqrtf(vv.w + BN_EPS) + betav.w;
        r.x = (r.x > 0.f) ? r.x : (expf(r.x) - 1.f);
        r.y = (r.y > 0.f) ? r.y : (expf(r.y) - 1.f);
        r.z = (r.z > 0.f) ? r.z : (expf(r.z) - 1.f);
        r.w = (r.w > 0.f) ? r.w : (expf(r.w) - 1.f);
        *(float4*)&out[(size_t)d * FD + f] = r;
    }
}

// ---------------- fused softmax + aggregation (fp16 h), H=1 C=40 ----------------
__global__ __launch_bounds__(256)
void agg_fused1(const int* __restrict__ rowptr, const int* __restrict__ srcs,
                const float* __restrict__ as_, const float* __restrict__ ad_,
                float* __restrict__ alpha,
                const __half* __restrict__ hbuf, const float* __restrict__ bias,
                float* __restrict__ out) {
    __shared__ float s_al[8][32];
    __shared__ int   s_sr[8][32];
    int w = (blockIdx.x * blockDim.x + threadIdx.x) >> 5;
    int lane = threadIdx.x & 31;
    int wi = (threadIdx.x >> 5);
    if (w >= NN) return;
    int d = w;
    float adl = ad_[d];
    int beg = rowptr[d], end = rowptr[d + 1];

    float den = 0.f;
    for (int j = beg + lane; j < end; j += 32) {
        float e = as_[srcs[j]] + adl;
        e = (e > 0.f) ? e : NEG_SLOPE * e;
        float p = __expf(e);
        alpha[j] = p;
        den += p;
    }
    #pragma unroll
    for (int o = 16; o > 0; o >>= 1)
        den += __shfl_xor_sync(0xFFFFFFFFu, den, o);
    float invden = 1.0f / (den + 1e-16f);

    // lane covers feature pair 2*lane, 2*lane+1 (40 features -> lanes 0..19)
    float accx = 0.f, accy = 0.f;
    for (int jb = beg; jb < end; jb += 32) {
        int j = jb + lane;
        int s = 0; float p = 0.f;
        if (j < end) { s = srcs[j]; p = alpha[j]; }
        __syncwarp();
        s_sr[wi][lane] = s;
        s_al[wi][lane] = p * invden;
        __syncwarp();
        int n = min(32, end - jb);
        if (lane < OUTD / 2) {
            #pragma unroll 4
            for (int t = 0; t < n; t++) {
                int ss = s_sr[wi][t];
                float a = s_al[wi][t];
                __half2 hv = *(const __half2*)&hbuf[(size_t)ss * OUTD + 2 * lane];
                float2 f = __half22float2(hv);
                accx += f.x * a;
                accy += f.y * a;
            }
        }
    }
    if (lane < OUTD / 2) {
        out[(size_t)d * OUTD + 2 * lane]     = accx + bias[2 * lane];
        out[(size_t)d * OUTD + 2 * lane + 1] = accy + bias[2 * lane + 1];
    }
}

// ================= launch =================
extern "C" void kernel_launch(void* const* d_in, const int* in_sizes, int n_in,
                              void* d_out, int out_size) {
    const float* x       = (const float*)d_in[0];
    const int*   eidx    = (const int*)d_in[1];
    const float* W0      = (const float*)d_in[2];
    const float* a_src0  = (const float*)d_in[3];
    const float* a_dst0  = (const float*)d_in[4];
    const float* b0      = (const float*)d_in[5];
    const float* bn0_g   = (const float*)d_in[6];
    const float* bn0_b   = (const float*)d_in[7];
    const float* bn0_m   = (const float*)d_in[8];
    const float* bn0_v   = (const float*)d_in[9];
    const float* W1      = (const float*)d_in[10];
    const float* a_src1  = (const float*)d_in[11];
    const float* a_dst1  = (const float*)d_in[12];
    const float* b1      = (const float*)d_in[13];
    const float* bn1_g   = (const float*)d_in[14];
    const float* bn1_b   = (const float*)d_in[15];
    const float* bn1_m   = (const float*)d_in[16];
    const float* bn1_v   = (const float*)d_in[17];
    const float* W2      = (const float*)d_in[18];
    const float* a_src2  = (const float*)d_in[19];
    const float* a_dst2  = (const float*)d_in[20];
    const float* b2      = (const float*)d_in[21];
    float* out = (float*)d_out;

    int E = in_sizes[1] / 2;
    const int* src = eidx;
    const int* dst = eidx + E;

    float *x1_buf, *as_buf, *ad_buf, *al_buf;
    __half* h16;
    int *deg, *cur, *rowptr, *srcs;
    cudaGetSymbolAddress((void**)&h16, g_h16);
    cudaGetSymbolAddress((void**)&x1_buf, g_x1);
    cudaGetSymbolAddress((void**)&as_buf, g_as);
    cudaGetSymbolAddress((void**)&ad_buf, g_ad);
    cudaGetSymbolAddress((void**)&al_buf, g_alpha);
    cudaGetSymbolAddress((void**)&deg, g_deg);
    cudaGetSymbolAddress((void**)&cur, g_cur);
    cudaGetSymbolAddress((void**)&rowptr, g_rowptr);
    cudaGetSymbolAddress((void**)&srcs, g_srcs);

    static cudaStream_t s2 = nullptr;
    static cudaEvent_t ev_fork = nullptr, ev_join = nullptr;
    if (s2 == nullptr) {
        cudaStreamCreateWithFlags(&s2, cudaStreamNonBlocking);
        cudaEventCreateWithFlags(&ev_fork, cudaEventDisableTiming);
        cudaEventCreateWithFlags(&ev_join, cudaEventDisableTiming);
    }

    // ---- fork: CSR build on s2, concurrent with layer-0 GEMM ----
    cudaEventRecord(ev_fork, 0);
    cudaStreamWaitEvent(s2, ev_fork, 0);
    zero_counts<<<cdiv(NN, 256), 256, 0, s2>>>(deg, cur, NN);
    csr_count<<<cdiv(E, 256), 256, 0, s2>>>(dst, E, deg);
    csr_scan<<<1, 1024, 0, s2>>>(deg, rowptr, NN, E);
    csr_fill<<<cdiv(E, 256), 256, 0, s2>>>(src, dst, E, rowptr, cur, srcs);
    cudaEventRecord(ev_join, s2);

    // ---- layer 0 ----
    gemm_bf16s<<<dim3(cdiv(FD, 64), cdiv(NN, 128)), 256>>>(
        x, W0, h16, NN, FD, 256, a_src0, a_dst0, as_buf, ad_buf, HEADS);
    cudaStreamWaitEvent(0, ev_join, 0);
    agg_fused4<<<cdiv(NN * 32, 256), 256>>>(rowptr, srcs, as_buf, ad_buf, al_buf, h16,
                                            b0, bn0_g, bn0_b, bn0_m, bn0_v, x1_buf);

    // ---- layer 1 ----
    gemm_bf16s<<<dim3(cdiv(FD, 64), cdiv(NN, 128)), 256>>>(
        x1_buf, W1, h16, NN, FD, FD, a_src1, a_dst1, as_buf, ad_buf, HEADS);
    agg_fused4<<<cdiv(NN * 32, 256), 256>>>(rowptr, srcs, as_buf, ad_buf, al_buf, h16,
                                            b1, bn1_g, bn1_b, bn1_m, bn1_v, x1_buf);

    // ---- layer 2 (heads=1, ch=40) ----
    gemm_bf16s<<<dim3(cdiv(OUTD, 64), cdiv(NN, 128)), 256>>>(
        x1_buf, W2, h16, NN, OUTD, FD, a_src2, a_dst2, as_buf, ad_buf, 1);
    agg_fused1<<<cdiv(NN * 32, 256), 256>>>(rowptr, srcs, as_buf, ad_buf, al_buf,
                                            h16, b2, out);
}